// round 1
// baseline (speedup 1.0000x reference)
#include <cuda_runtime.h>
#include <math.h>

#define BATCH 4
#define SEQ   2048
#define DIM   1024
#define NHEAD 16
#define HD    64
#define ROWS  (BATCH*SEQ)   // 8192

// ---------------- scratch (device globals; no allocation allowed) ----------
__device__ float g_Qbuf[(size_t)ROWS * DIM];        // x @ q_w (pre-LN)
__device__ float g_KVbuf[(size_t)ROWS * 2 * DIM];   // context @ kv_w
__device__ float g_Q[(size_t)ROWS * DIM];           // [B,H,S,Hd] post LN+RoPE
__device__ float g_K[(size_t)ROWS * DIM];           // [B,H,Sc,Hd] post LN
__device__ float g_V[(size_t)ROWS * DIM];           // [B,H,Sc,Hd]
__device__ float g_O[(size_t)ROWS * DIM];           // attn out, [B,S,H*Hd]

// ---------------- tiled SGEMM: C[M,N] = A[M,K] @ B[K,N] (+bias) ------------
// 128x128 block tile, K-tile 8, 256 threads, 8x8 per thread.
__global__ void sgemm128(const float* __restrict__ A, const float* __restrict__ B,
                         const float* __restrict__ bias, float* __restrict__ C,
                         int M, int N, int K) {
    __shared__ float As[8][128];   // transposed A tile: As[k][m]
    __shared__ float Bs[8][128];   // Bs[k][n]

    const int tid = threadIdx.x;
    const int br  = blockIdx.y, bc = blockIdx.x;
    const int ty  = tid >> 4, tx = tid & 15;     // 16x16 thread grid

    const int arow = tid >> 1;              // 0..127
    const int acol = (tid & 1) * 4;         // 0 or 4
    const int brow = tid >> 5;              // 0..7
    const int bcol = (tid & 31) * 4;        // 0..124

    const float* Ag = A + (size_t)(br * 128 + arow) * K + acol;
    const float* Bg = B + (size_t)brow * N + bc * 128 + bcol;

    float acc[8][8];
#pragma unroll
    for (int i = 0; i < 8; i++)
#pragma unroll
        for (int j = 0; j < 8; j++) acc[i][j] = 0.f;

    for (int k0 = 0; k0 < K; k0 += 8) {
        float4 a4 = *(const float4*)(Ag + k0);
        As[acol + 0][arow] = a4.x;
        As[acol + 1][arow] = a4.y;
        As[acol + 2][arow] = a4.z;
        As[acol + 3][arow] = a4.w;
        float4 b4 = *(const float4*)(Bg + (size_t)k0 * N);
        *(float4*)&Bs[brow][bcol] = b4;
        __syncthreads();

#pragma unroll
        for (int k = 0; k < 8; k++) {
            float a[8], b[8];
            *(float4*)(a)     = *(float4*)&As[k][ty * 8];
            *(float4*)(a + 4) = *(float4*)&As[k][ty * 8 + 4];
            *(float4*)(b)     = *(float4*)&Bs[k][tx * 8];
            *(float4*)(b + 4) = *(float4*)&Bs[k][tx * 8 + 4];
#pragma unroll
            for (int i = 0; i < 8; i++)
#pragma unroll
                for (int j = 0; j < 8; j++) acc[i][j] = fmaf(a[i], b[j], acc[i][j]);
        }
        __syncthreads();
    }

    const int cn = bc * 128 + tx * 8;
    float bv[8];
    if (bias) {
#pragma unroll
        for (int j = 0; j < 8; j++) bv[j] = bias[cn + j];
    } else {
#pragma unroll
        for (int j = 0; j < 8; j++) bv[j] = 0.f;
    }
#pragma unroll
    for (int i = 0; i < 8; i++) {
        int row = br * 128 + ty * 8 + i;
        float* Crow = C + (size_t)row * N + cn;
        float4 o0 = make_float4(acc[i][0] + bv[0], acc[i][1] + bv[1],
                                acc[i][2] + bv[2], acc[i][3] + bv[3]);
        float4 o1 = make_float4(acc[i][4] + bv[4], acc[i][5] + bv[5],
                                acc[i][6] + bv[6], acc[i][7] + bv[7]);
        *(float4*)(Crow)     = o0;
        *(float4*)(Crow + 4) = o1;
    }
}

// --------- per-head LayerNorm + RoPE on q; one warp per (row, head) --------
__global__ void ln_rope_q_kernel(const float* __restrict__ Qbuf,
                                 const float* __restrict__ gamma,
                                 const float* __restrict__ beta,
                                 float* __restrict__ Q) {
    const int gw   = blockIdx.x * 8 + (threadIdx.x >> 5);  // global warp id
    const int lane = threadIdx.x & 31;
    const int h = gw & (NHEAD - 1);
    const int m = gw >> 4;              // 0..ROWS-1
    const int b = m >> 11;              // /SEQ
    const int s = m & (SEQ - 1);

    const float* in = Qbuf + (size_t)m * DIM + h * HD;
    float v0 = in[lane], v1 = in[lane + 32];

    float sum = v0 + v1;
#pragma unroll
    for (int o = 16; o; o >>= 1) sum += __shfl_xor_sync(0xffffffffu, sum, o);
    float mu = sum * (1.f / 64.f);
    float d0 = v0 - mu, d1 = v1 - mu;
    float vs = d0 * d0 + d1 * d1;
#pragma unroll
    for (int o = 16; o; o >>= 1) vs += __shfl_xor_sync(0xffffffffu, vs, o);
    float rstd = rsqrtf(vs * (1.f / 64.f) + 1e-5f);

    float y0 = d0 * rstd * gamma[lane]      + beta[lane];
    float y1 = d1 * rstd * gamma[lane + 32] + beta[lane + 32];

    // RoPE: lane holds (q1[lane], q2[lane]); ang = s * 10000^(-lane/32)
    float invf = powf(10000.f, -(float)lane * (1.f / 32.f));
    float ang  = (float)s * invf;
    float sn, cs;
    sincosf(ang, &sn, &cs);
    float o0 = y0 * cs - y1 * sn;
    float o1 = y0 * sn + y1 * cs;

    float* outp = Q + ((size_t)(b * NHEAD + h) * SEQ + s) * HD;
    outp[lane]      = o0;
    outp[lane + 32] = o1;
}

// --------- per-head LayerNorm on k + transpose copy of v -------------------
__global__ void ln_kv_kernel(const float* __restrict__ KVbuf,
                             const float* __restrict__ gamma,
                             const float* __restrict__ beta,
                             float* __restrict__ K, float* __restrict__ V) {
    const int gw   = blockIdx.x * 8 + (threadIdx.x >> 5);
    const int lane = threadIdx.x & 31;
    const int h = gw & (NHEAD - 1);
    const int m = gw >> 4;
    const int b = m >> 11;
    const int sc = m & (SEQ - 1);

    const float* kin = KVbuf + (size_t)m * (2 * DIM) + h * HD;
    const float* vin = kin + DIM;

    float v0 = kin[lane], v1 = kin[lane + 32];
    float sum = v0 + v1;
#pragma unroll
    for (int o = 16; o; o >>= 1) sum += __shfl_xor_sync(0xffffffffu, sum, o);
    float mu = sum * (1.f / 64.f);
    float d0 = v0 - mu, d1 = v1 - mu;
    float vs = d0 * d0 + d1 * d1;
#pragma unroll
    for (int o = 16; o; o >>= 1) vs += __shfl_xor_sync(0xffffffffu, vs, o);
    float rstd = rsqrtf(vs * (1.f / 64.f) + 1e-5f);

    size_t ob = ((size_t)(b * NHEAD + h) * SEQ + sc) * HD;
    K[ob + lane]      = d0 * rstd * gamma[lane]      + beta[lane];
    K[ob + lane + 32] = d1 * rstd * gamma[lane + 32] + beta[lane + 32];
    V[ob + lane]      = vin[lane];
    V[ob + lane + 32] = vin[lane + 32];
}

// --------- flash attention: 64q x 64k tiles, online softmax ----------------
// 256 threads, 4x4 thread tiles. smem = Qs(64x64) + Ks(64x64, swizzled, reused
// as P after S-compute) + Vs(64x64) = 48 KB exactly.
__global__ void flash_kernel(const float* __restrict__ Q, const float* __restrict__ K,
                             const float* __restrict__ V, float* __restrict__ O) {
    const int qt = blockIdx.x, h = blockIdx.y, b = blockIdx.z;
    __shared__ float sh[3 * 64 * 64];
    float* Qs = sh;                 // [64][64], broadcast reads
    float* Ks = sh + 64 * 64;       // [64][64] XOR-swizzled on d; reused as P
    float* Vs = sh + 2 * 64 * 64;   // [64][64]

    const int tid = threadIdx.x;
    const int ty = tid >> 4, tx = tid & 15;       // rows ty*4.., cols tx*4..
    const int kxor = (tx & 7) << 2;               // per-thread K swizzle

    const float* Qg = Q + ((size_t)(b * NHEAD + h) * SEQ + qt * 64) * HD;
    const float* Kg = K + (size_t)(b * NHEAD + h) * SEQ * HD;
    const float* Vg = V + (size_t)(b * NHEAD + h) * SEQ * HD;

    // load Q tile
    for (int i = tid; i < 64 * 16; i += 256) {
        int r = i >> 4, c4 = (i & 15) << 2;
        *(float4*)(Qs + r * 64 + c4) = *(const float4*)(Qg + r * 64 + c4);
    }

    float m[4], l[4], acc[4][4];
#pragma unroll
    for (int i = 0; i < 4; i++) {
        m[i] = -1e30f; l[i] = 0.f;
#pragma unroll
        for (int j = 0; j < 4; j++) acc[i][j] = 0.f;
    }
    __syncthreads();

    for (int kt = 0; kt < SEQ / 64; kt++) {
        // load K (swizzled) and V tiles
        for (int i = tid; i < 64 * 16; i += 256) {
            int r = i >> 4, c4 = (i & 15) << 2;
            float4 kk = *(const float4*)(Kg + ((size_t)(kt * 64 + r)) * 64 + c4);
            int sw = c4 ^ (((r >> 2) & 7) << 2);
            *(float4*)(Ks + r * 64 + sw) = kk;
            float4 vv = *(const float4*)(Vg + ((size_t)(kt * 64 + r)) * 64 + c4);
            *(float4*)(Vs + r * 64 + c4) = vv;
        }
        __syncthreads();

        // S = Q K^T (4x4 per thread)
        float s[4][4];
#pragma unroll
        for (int i = 0; i < 4; i++)
#pragma unroll
            for (int j = 0; j < 4; j++) s[i][j] = 0.f;
#pragma unroll 16
        for (int k = 0; k < 64; k++) {
            float a[4], bb[4];
#pragma unroll
            for (int i = 0; i < 4; i++) a[i] = Qs[(ty * 4 + i) * 64 + k];
#pragma unroll
            for (int j = 0; j < 4; j++) bb[j] = Ks[(tx * 4 + j) * 64 + (k ^ kxor)];
#pragma unroll
            for (int i = 0; i < 4; i++)
#pragma unroll
                for (int j = 0; j < 4; j++) s[i][j] = fmaf(a[i], bb[j], s[i][j]);
        }

        // online softmax (rows shared by 16 lanes: xor offsets 1..8)
        float mnew[4], pl[4], alpha[4];
#pragma unroll
        for (int i = 0; i < 4; i++) {
            float rm = -1e30f;
#pragma unroll
            for (int j = 0; j < 4; j++) {
                s[i][j] *= 0.125f;   // 1/sqrt(64)
                rm = fmaxf(rm, s[i][j]);
            }
#pragma unroll
            for (int o = 1; o < 16; o <<= 1) rm = fmaxf(rm, __shfl_xor_sync(0xffffffffu, rm, o));
            mnew[i] = fmaxf(m[i], rm);
            float ps = 0.f;
#pragma unroll
            for (int j = 0; j < 4; j++) { s[i][j] = __expf(s[i][j] - mnew[i]); ps += s[i][j]; }
#pragma unroll
            for (int o = 1; o < 16; o <<= 1) ps += __shfl_xor_sync(0xffffffffu, ps, o);
            alpha[i] = __expf(m[i] - mnew[i]);
            l[i] = l[i] * alpha[i] + ps;
            m[i] = mnew[i];
#pragma unroll
            for (int j = 0; j < 4; j++) acc[i][j] *= alpha[i];
        }

        __syncthreads();            // everyone done reading Ks
        // store P into Ks buffer (plain [64][64])
#pragma unroll
        for (int i = 0; i < 4; i++)
#pragma unroll
            for (int j = 0; j < 4; j++) Ks[(ty * 4 + i) * 64 + tx * 4 + j] = s[i][j];
        __syncthreads();

        // O += P @ V
#pragma unroll 16
        for (int jj = 0; jj < 64; jj++) {
            float p[4], vv[4];
#pragma unroll
            for (int i = 0; i < 4; i++) p[i] = Ks[(ty * 4 + i) * 64 + jj];
#pragma unroll
            for (int j = 0; j < 4; j++) vv[j] = Vs[jj * 64 + tx * 4 + j];
#pragma unroll
            for (int i = 0; i < 4; i++)
#pragma unroll
                for (int j = 0; j < 4; j++) acc[i][j] = fmaf(p[i], vv[j], acc[i][j]);
        }
        __syncthreads();            // before next tile overwrites Ks/Vs
    }

    // epilogue -> O laid out [B, S, H*Hd] (ready for proj GEMM)
#pragma unroll
    for (int i = 0; i < 4; i++) {
        float inv = 1.f / l[i];
        int row = qt * 64 + ty * 4 + i;
        float* op = O + ((size_t)b * SEQ + row) * DIM + h * HD + tx * 4;
        *(float4*)op = make_float4(acc[i][0] * inv, acc[i][1] * inv,
                                   acc[i][2] * inv, acc[i][3] * inv);
    }
}

// ---------------------------------------------------------------------------
extern "C" void kernel_launch(void* const* d_in, const int* in_sizes, int n_in,
                              void* d_out, int out_size) {
    const float* x        = (const float*)d_in[0];
    const float* context  = (const float*)d_in[1];
    const float* q_w      = (const float*)d_in[2];
    const float* kv_w     = (const float*)d_in[3];
    const float* qn_scale = (const float*)d_in[4];
    const float* qn_bias  = (const float*)d_in[5];
    const float* kn_scale = (const float*)d_in[6];
    const float* kn_bias  = (const float*)d_in[7];
    const float* proj_w   = (const float*)d_in[8];
    const float* proj_b   = (const float*)d_in[9];
    float* out = (float*)d_out;

    float *Qbuf, *KVbuf, *Q, *K, *V, *O;
    cudaGetSymbolAddress((void**)&Qbuf,  g_Qbuf);
    cudaGetSymbolAddress((void**)&KVbuf, g_KVbuf);
    cudaGetSymbolAddress((void**)&Q,     g_Q);
    cudaGetSymbolAddress((void**)&K,     g_K);
    cudaGetSymbolAddress((void**)&V,     g_V);
    cudaGetSymbolAddress((void**)&O,     g_O);

    // 1) q = x @ q_w               [8192,1024] = [8192,1024]@[1024,1024]
    sgemm128<<<dim3(DIM / 128, ROWS / 128), 256>>>(x, q_w, nullptr, Qbuf, ROWS, DIM, DIM);
    // 2) kv = context @ kv_w       [8192,2048]
    sgemm128<<<dim3(2 * DIM / 128, ROWS / 128), 256>>>(context, kv_w, nullptr, KVbuf, ROWS, 2 * DIM, DIM);
    // 3) per-head LN + RoPE on q -> [B,H,S,Hd]
    ln_rope_q_kernel<<<(ROWS * NHEAD) / 8, 256>>>(Qbuf, qn_scale, qn_bias, Q);
    // 4) per-head LN on k, copy v -> [B,H,Sc,Hd]
    ln_kv_kernel<<<(ROWS * NHEAD) / 8, 256>>>(KVbuf, kn_scale, kn_bias, K, V);
    // 5) attention -> [B,S,H*Hd]
    flash_kernel<<<dim3(SEQ / 64, NHEAD, BATCH), 256>>>(Q, K, V, O);
    // 6) out = O @ proj_w + proj_b
    sgemm128<<<dim3(DIM / 128, ROWS / 128), 256>>>(O, proj_w, proj_b, out, ROWS, DIM, DIM);
}

// round 2
// speedup vs baseline: 2.2500x; 2.2500x over previous
#include <cuda_runtime.h>
#include <math.h>

#define BATCH 4
#define SEQ   2048
#define DIM   1024
#define NHEAD 16
#define HD    64
#define ROWS  (BATCH*SEQ)   // 8192

// ---------------- scratch (device globals; no allocation allowed) ----------
__device__ float g_Qbuf[(size_t)ROWS * DIM];        // x @ q_w (pre-LN)
__device__ float g_KVbuf[(size_t)ROWS * 2 * DIM];   // context @ kv_w
__device__ float g_Q[(size_t)ROWS * DIM];           // [B,H,S,Hd] post LN+RoPE
__device__ float g_K[(size_t)ROWS * DIM];           // [B,H,Sc,Hd] post LN
__device__ float g_V[(size_t)ROWS * DIM];           // [B,H,Sc,Hd]
__device__ float g_O[(size_t)ROWS * DIM];           // attn out, [B,S,H*Hd]

// ---------------- tf32 helpers ---------------------------------------------
__device__ __forceinline__ unsigned tf32(float x) {
    unsigned u;
    asm("cvt.rna.tf32.f32 %0, %1;" : "=r"(u) : "f"(x));
    return u;
}

__device__ __forceinline__ void mma8(float* d, const unsigned* a, const unsigned* b) {
    asm volatile(
        "mma.sync.aligned.m16n8k8.row.col.f32.tf32.tf32.f32 "
        "{%0,%1,%2,%3}, {%4,%5,%6,%7}, {%8,%9}, {%0,%1,%2,%3};"
        : "+f"(d[0]), "+f"(d[1]), "+f"(d[2]), "+f"(d[3])
        : "r"(a[0]), "r"(a[1]), "r"(a[2]), "r"(a[3]), "r"(b[0]), "r"(b[1]));
}

// ---------------- TF32 tensor-core GEMM: C = A @ B (+bias) -----------------
// 128x128 block tile, K-tile 16, 256 threads = 8 warps (2m x 4n), warp 64x32.
__global__ __launch_bounds__(256) void gemm_tf32(
        const float* __restrict__ A, const float* __restrict__ B,
        const float* __restrict__ bias, float* __restrict__ C,
        int M, int N, int K) {
    __shared__ float As[128 * 20];   // [m][k], pad 20: frag banks (g*20+c)%32 distinct
    __shared__ float Bs[16 * 136];   // [k][n], pad 136: frag banks (c*8+g)%32 distinct

    const int tid  = threadIdx.x;
    const int warp = tid >> 5, lane = tid & 31;
    const int g = lane >> 2, c = lane & 3;
    const int wm = (warp >> 2) * 64, wn = (warp & 3) * 32;
    const int bm = blockIdx.y * 128, bn = blockIdx.x * 128;

    const int ar  = tid >> 2;             // 0..63 (A rows, also +64)
    const int ac4 = (tid & 3) << 2;       // k offset 0/4/8/12
    const int bk  = tid >> 5;             // 0..7 (B k rows, also +8)
    const int bc4 = (tid & 31) << 2;      // n offset

    const float* Ap = A + (size_t)(bm + ar) * K + ac4;
    const float* Bp = B + (size_t)bk * N + bn + bc4;

    float acc[4][4][4];
#pragma unroll
    for (int mi = 0; mi < 4; mi++)
#pragma unroll
        for (int ni = 0; ni < 4; ni++)
#pragma unroll
            for (int t = 0; t < 4; t++) acc[mi][ni][t] = 0.f;

    for (int k0 = 0; k0 < K; k0 += 16) {
        float4 a0 = *(const float4*)(Ap + k0);
        float4 a1 = *(const float4*)(Ap + (size_t)64 * K + k0);
        float4 b0 = *(const float4*)(Bp + (size_t)k0 * N);
        float4 b1 = *(const float4*)(Bp + (size_t)(k0 + 8) * N);
        __syncthreads();      // previous tile's compute done
        *(float4*)&As[ar * 20 + ac4]        = a0;
        *(float4*)&As[(ar + 64) * 20 + ac4] = a1;
        *(float4*)&Bs[bk * 136 + bc4]       = b0;
        *(float4*)&Bs[(bk + 8) * 136 + bc4] = b1;
        __syncthreads();

#pragma unroll
        for (int ks = 0; ks < 2; ks++) {
            unsigned af[4][4], bf[4][2];
            const int kk = ks * 8 + c;
#pragma unroll
            for (int mi = 0; mi < 4; mi++) {
                int row = wm + mi * 16 + g;
                af[mi][0] = tf32(As[row * 20 + kk]);
                af[mi][1] = tf32(As[(row + 8) * 20 + kk]);
                af[mi][2] = tf32(As[row * 20 + kk + 4]);
                af[mi][3] = tf32(As[(row + 8) * 20 + kk + 4]);
            }
#pragma unroll
            for (int ni = 0; ni < 4; ni++) {
                int col = wn + ni * 8 + g;
                bf[ni][0] = tf32(Bs[kk * 136 + col]);
                bf[ni][1] = tf32(Bs[(kk + 4) * 136 + col]);
            }
#pragma unroll
            for (int mi = 0; mi < 4; mi++)
#pragma unroll
                for (int ni = 0; ni < 4; ni++)
                    mma8(acc[mi][ni], af[mi], bf[ni]);
        }
    }

#pragma unroll
    for (int mi = 0; mi < 4; mi++) {
        int row = bm + wm + mi * 16 + g;
#pragma unroll
        for (int ni = 0; ni < 4; ni++) {
            int col = bn + wn + ni * 8 + 2 * c;
            float bv0 = bias ? bias[col] : 0.f;
            float bv1 = bias ? bias[col + 1] : 0.f;
            float* p0 = C + (size_t)row * N + col;
            float* p1 = C + (size_t)(row + 8) * N + col;
            p0[0] = acc[mi][ni][0] + bv0; p0[1] = acc[mi][ni][1] + bv1;
            p1[0] = acc[mi][ni][2] + bv0; p1[1] = acc[mi][ni][3] + bv1;
        }
    }
}

// --------- per-head LayerNorm + RoPE on q; one warp per (row, head) --------
__global__ void ln_rope_q_kernel(const float* __restrict__ Qbuf,
                                 const float* __restrict__ gamma,
                                 const float* __restrict__ beta,
                                 float* __restrict__ Q) {
    const int gw   = blockIdx.x * 8 + (threadIdx.x >> 5);
    const int lane = threadIdx.x & 31;
    const int h = gw & (NHEAD - 1);
    const int m = gw >> 4;
    const int b = m >> 11;
    const int s = m & (SEQ - 1);

    const float* in = Qbuf + (size_t)m * DIM + h * HD;
    float v0 = in[lane], v1 = in[lane + 32];

    float sum = v0 + v1;
#pragma unroll
    for (int o = 16; o; o >>= 1) sum += __shfl_xor_sync(0xffffffffu, sum, o);
    float mu = sum * (1.f / 64.f);
    float d0 = v0 - mu, d1 = v1 - mu;
    float vs = d0 * d0 + d1 * d1;
#pragma unroll
    for (int o = 16; o; o >>= 1) vs += __shfl_xor_sync(0xffffffffu, vs, o);
    float rstd = rsqrtf(vs * (1.f / 64.f) + 1e-5f);

    float y0 = d0 * rstd * gamma[lane]      + beta[lane];
    float y1 = d1 * rstd * gamma[lane + 32] + beta[lane + 32];

    float invf = powf(10000.f, -(float)lane * (1.f / 32.f));
    float ang  = (float)s * invf;
    float sn, cs;
    sincosf(ang, &sn, &cs);
    float o0 = y0 * cs - y1 * sn;
    float o1 = y0 * sn + y1 * cs;

    float* outp = Q + ((size_t)(b * NHEAD + h) * SEQ + s) * HD;
    outp[lane]      = o0;
    outp[lane + 32] = o1;
}

// --------- per-head LayerNorm on k + transpose copy of v -------------------
__global__ void ln_kv_kernel(const float* __restrict__ KVbuf,
                             const float* __restrict__ gamma,
                             const float* __restrict__ beta,
                             float* __restrict__ K, float* __restrict__ V) {
    const int gw   = blockIdx.x * 8 + (threadIdx.x >> 5);
    const int lane = threadIdx.x & 31;
    const int h = gw & (NHEAD - 1);
    const int m = gw >> 4;
    const int b = m >> 11;
    const int sc = m & (SEQ - 1);

    const float* kin = KVbuf + (size_t)m * (2 * DIM) + h * HD;
    const float* vin = kin + DIM;

    float v0 = kin[lane], v1 = kin[lane + 32];
    float sum = v0 + v1;
#pragma unroll
    for (int o = 16; o; o >>= 1) sum += __shfl_xor_sync(0xffffffffu, sum, o);
    float mu = sum * (1.f / 64.f);
    float d0 = v0 - mu, d1 = v1 - mu;
    float vs = d0 * d0 + d1 * d1;
#pragma unroll
    for (int o = 16; o; o >>= 1) vs += __shfl_xor_sync(0xffffffffu, vs, o);
    float rstd = rsqrtf(vs * (1.f / 64.f) + 1e-5f);

    size_t ob = ((size_t)(b * NHEAD + h) * SEQ + sc) * HD;
    K[ob + lane]      = d0 * rstd * gamma[lane]      + beta[lane];
    K[ob + lane + 32] = d1 * rstd * gamma[lane + 32] + beta[lane + 32];
    V[ob + lane]      = vin[lane];
    V[ob + lane + 32] = vin[lane + 32];
}

// --------- flash attention with tf32 mma: 64q x 64k tiles ------------------
// 256 threads = 8 warps (4m x 2n). Q frags preloaded to regs; Qs buffer is
// reused for softmax stats and the P matrix. Swizzled smem, 48KB static.
#define QIDX(r, col) ((r) * 64 + ((col) ^ (((r) & 7) << 2)))
#define VIDX(r, col) ((r) * 64 + ((col) ^ (((r) & 3) << 3)))

__global__ __launch_bounds__(256) void flash_tf32(
        const float* __restrict__ Q, const float* __restrict__ K,
        const float* __restrict__ V, float* __restrict__ O) {
    __shared__ float Qs[64 * 64];   // Q tile -> stats (0..255) + P tile
    __shared__ float Ks[64 * 64];
    __shared__ float Vs[64 * 64];

    const int qt = blockIdx.x, h = blockIdx.y, b = blockIdx.z;
    const int tid  = threadIdx.x;
    const int warp = tid >> 5, lane = tid & 31;
    const int g = lane >> 2, c = lane & 3;
    const int wm = (warp >> 1) * 16;     // warp's 16 query rows
    const int wn = (warp & 1) * 32;      // warp's key/d half

    const float* Qg = Q + ((size_t)(b * NHEAD + h) * SEQ + qt * 64) * HD;
    const float* Kg = K + (size_t)(b * NHEAD + h) * SEQ * HD;
    const float* Vg = V + (size_t)(b * NHEAD + h) * SEQ * HD;

    // stage Q, then extract per-warp A-fragments into registers
#pragma unroll
    for (int j = 0; j < 4; j++) {
        int i = tid + j * 256;
        int r = i >> 4, c4 = (i & 15) << 2;
        *(float4*)&Qs[QIDX(r, c4)] = *(const float4*)(Qg + r * 64 + c4);
    }
    __syncthreads();

    unsigned qf[8][4];
#pragma unroll
    for (int ks = 0; ks < 8; ks++) {
        int kk = ks * 8 + c;
        qf[ks][0] = tf32(Qs[QIDX(wm + g, kk)]);
        qf[ks][1] = tf32(Qs[QIDX(wm + 8 + g, kk)]);
        qf[ks][2] = tf32(Qs[QIDX(wm + g, kk + 4)]);
        qf[ks][3] = tf32(Qs[QIDX(wm + 8 + g, kk + 4)]);
    }

    float m0 = -1e30f, m1 = -1e30f, l0 = 0.f, l1 = 0.f;
    float o[4][4];
#pragma unroll
    for (int ni = 0; ni < 4; ni++)
#pragma unroll
        for (int t = 0; t < 4; t++) o[ni][t] = 0.f;

    for (int kt = 0; kt < SEQ / 64; kt++) {
        // load K, V tiles (swizzled)
#pragma unroll
        for (int j = 0; j < 4; j++) {
            int i = tid + j * 256;
            int r = i >> 4, c4 = (i & 15) << 2;
            *(float4*)&Ks[QIDX(r, c4)] = *(const float4*)(Kg + (size_t)(kt * 64 + r) * 64 + c4);
            *(float4*)&Vs[VIDX(r, c4)] = *(const float4*)(Vg + (size_t)(kt * 64 + r) * 64 + c4);
        }
        __syncthreads();   // (a)

        // S = Q K^T for this warp: rows wm..wm+15, keys wn..wn+31
        float s[4][4];
#pragma unroll
        for (int ni = 0; ni < 4; ni++)
#pragma unroll
            for (int t = 0; t < 4; t++) s[ni][t] = 0.f;
#pragma unroll
        for (int ks = 0; ks < 8; ks++) {
            int kk = ks * 8 + c;
            unsigned kb[4][2];
#pragma unroll
            for (int ni = 0; ni < 4; ni++) {
                int kc = wn + ni * 8 + g;
                kb[ni][0] = tf32(Ks[QIDX(kc, kk)]);
                kb[ni][1] = tf32(Ks[QIDX(kc, kk + 4)]);
            }
#pragma unroll
            for (int ni = 0; ni < 4; ni++) mma8(s[ni], qf[ks], kb[ni]);
        }

        // scale + per-warp row max
        float rm0 = -1e30f, rm1 = -1e30f;
#pragma unroll
        for (int ni = 0; ni < 4; ni++) {
            s[ni][0] *= 0.125f; s[ni][1] *= 0.125f;
            s[ni][2] *= 0.125f; s[ni][3] *= 0.125f;
            rm0 = fmaxf(rm0, fmaxf(s[ni][0], s[ni][1]));
            rm1 = fmaxf(rm1, fmaxf(s[ni][2], s[ni][3]));
        }
        rm0 = fmaxf(rm0, __shfl_xor_sync(0xffffffffu, rm0, 1));
        rm0 = fmaxf(rm0, __shfl_xor_sync(0xffffffffu, rm0, 2));
        rm1 = fmaxf(rm1, __shfl_xor_sync(0xffffffffu, rm1, 1));
        rm1 = fmaxf(rm1, __shfl_xor_sync(0xffffffffu, rm1, 2));
        if (c == 0) {                       // stats carve in freed Qs
            Qs[(warp & 1) * 64 + wm + g]     = rm0;
            Qs[(warp & 1) * 64 + wm + 8 + g] = rm1;
        }
        __syncthreads();   // (s1)
        float mc0 = fmaxf(Qs[wm + g],     Qs[64 + wm + g]);
        float mc1 = fmaxf(Qs[wm + 8 + g], Qs[64 + wm + 8 + g]);
        float mn0 = fmaxf(m0, mc0), mn1 = fmaxf(m1, mc1);

        float ps0 = 0.f, ps1 = 0.f;
#pragma unroll
        for (int ni = 0; ni < 4; ni++) {
            s[ni][0] = __expf(s[ni][0] - mn0); s[ni][1] = __expf(s[ni][1] - mn0);
            s[ni][2] = __expf(s[ni][2] - mn1); s[ni][3] = __expf(s[ni][3] - mn1);
            ps0 += s[ni][0] + s[ni][1];
            ps1 += s[ni][2] + s[ni][3];
        }
        ps0 += __shfl_xor_sync(0xffffffffu, ps0, 1);
        ps0 += __shfl_xor_sync(0xffffffffu, ps0, 2);
        ps1 += __shfl_xor_sync(0xffffffffu, ps1, 1);
        ps1 += __shfl_xor_sync(0xffffffffu, ps1, 2);
        if (c == 0) {
            Qs[128 + (warp & 1) * 64 + wm + g]     = ps0;
            Qs[128 + (warp & 1) * 64 + wm + 8 + g] = ps1;
        }
        __syncthreads();   // (s2)
        float ls0 = Qs[128 + wm + g]     + Qs[128 + 64 + wm + g];
        float ls1 = Qs[128 + wm + 8 + g] + Qs[128 + 64 + wm + 8 + g];

        float al0 = __expf(m0 - mn0), al1 = __expf(m1 - mn1);
        m0 = mn0; m1 = mn1;
        l0 = l0 * al0 + ls0;
        l1 = l1 * al1 + ls1;
#pragma unroll
        for (int ni = 0; ni < 4; ni++) {
            o[ni][0] *= al0; o[ni][1] *= al0;
            o[ni][2] *= al1; o[ni][3] *= al1;
        }
        __syncthreads();   // (s3) stats consumed, safe to overwrite with P

        // store P into Qs (swizzled like Q/K)
#pragma unroll
        for (int ni = 0; ni < 4; ni++) {
            int pc = wn + ni * 8 + 2 * c;
            Qs[QIDX(wm + g, pc)]         = s[ni][0];
            Qs[QIDX(wm + g, pc + 1)]     = s[ni][1];
            Qs[QIDX(wm + 8 + g, pc)]     = s[ni][2];
            Qs[QIDX(wm + 8 + g, pc + 1)] = s[ni][3];
        }
        __syncthreads();   // (b)

        // O += P @ V : rows wm..wm+15, d-cols wn..wn+31
#pragma unroll
        for (int ks = 0; ks < 8; ks++) {
            int kk = ks * 8 + c;
            unsigned pa[4], vb[4][2];
            pa[0] = tf32(Qs[QIDX(wm + g, kk)]);
            pa[1] = tf32(Qs[QIDX(wm + 8 + g, kk)]);
            pa[2] = tf32(Qs[QIDX(wm + g, kk + 4)]);
            pa[3] = tf32(Qs[QIDX(wm + 8 + g, kk + 4)]);
#pragma unroll
            for (int ni = 0; ni < 4; ni++) {
                int dc = wn + ni * 8 + g;
                vb[ni][0] = tf32(Vs[VIDX(kk, dc)]);
                vb[ni][1] = tf32(Vs[VIDX(kk + 4, dc)]);
            }
#pragma unroll
            for (int ni = 0; ni < 4; ni++) mma8(o[ni], pa, vb[ni]);
        }
        __syncthreads();   // (c) PV done; next iter may overwrite Ks/Vs
    }

    // epilogue -> O [B, S, H*Hd]
    float inv0 = 1.f / l0, inv1 = 1.f / l1;
    int row0 = qt * 64 + wm + g;
#pragma unroll
    for (int ni = 0; ni < 4; ni++) {
        int col = h * HD + wn + ni * 8 + 2 * c;
        float* p0 = O + ((size_t)b * SEQ + row0) * DIM + col;
        float* p1 = O + ((size_t)b * SEQ + row0 + 8) * DIM + col;
        p0[0] = o[ni][0] * inv0; p0[1] = o[ni][1] * inv0;
        p1[0] = o[ni][2] * inv1; p1[1] = o[ni][3] * inv1;
    }
}

// ---------------------------------------------------------------------------
extern "C" void kernel_launch(void* const* d_in, const int* in_sizes, int n_in,
                              void* d_out, int out_size) {
    const float* x        = (const float*)d_in[0];
    const float* context  = (const float*)d_in[1];
    const float* q_w      = (const float*)d_in[2];
    const float* kv_w     = (const float*)d_in[3];
    const float* qn_scale = (const float*)d_in[4];
    const float* qn_bias  = (const float*)d_in[5];
    const float* kn_scale = (const float*)d_in[6];
    const float* kn_bias  = (const float*)d_in[7];
    const float* proj_w   = (const float*)d_in[8];
    const float* proj_b   = (const float*)d_in[9];
    float* out = (float*)d_out;

    float *Qbuf, *KVbuf, *Q, *K, *V, *O;
    cudaGetSymbolAddress((void**)&Qbuf,  g_Qbuf);
    cudaGetSymbolAddress((void**)&KVbuf, g_KVbuf);
    cudaGetSymbolAddress((void**)&Q,     g_Q);
    cudaGetSymbolAddress((void**)&K,     g_K);
    cudaGetSymbolAddress((void**)&V,     g_V);
    cudaGetSymbolAddress((void**)&O,     g_O);

    // 1) q = x @ q_w
    gemm_tf32<<<dim3(DIM / 128, ROWS / 128), 256>>>(x, q_w, nullptr, Qbuf, ROWS, DIM, DIM);
    // 2) kv = context @ kv_w
    gemm_tf32<<<dim3(2 * DIM / 128, ROWS / 128), 256>>>(context, kv_w, nullptr, KVbuf, ROWS, 2 * DIM, DIM);
    // 3) per-head LN + RoPE on q -> [B,H,S,Hd]
    ln_rope_q_kernel<<<(ROWS * NHEAD) / 8, 256>>>(Qbuf, qn_scale, qn_bias, Q);
    // 4) per-head LN on k, copy v -> [B,H,Sc,Hd]
    ln_kv_kernel<<<(ROWS * NHEAD) / 8, 256>>>(KVbuf, kn_scale, kn_bias, K, V);
    // 5) attention -> [B,S,H*Hd]
    flash_tf32<<<dim3(SEQ / 64, NHEAD, BATCH), 256>>>(Q, K, V, O);
    // 6) out = O @ proj_w + proj_b
    gemm_tf32<<<dim3(DIM / 128, ROWS / 128), 256>>>(O, proj_w, proj_b, out, ROWS, DIM, DIM);
}

// round 3
// speedup vs baseline: 2.9831x; 1.3258x over previous
#include <cuda_runtime.h>
#include <math.h>
#include <stdint.h>

#define BATCH 4
#define SEQ   2048
#define DIM   1024
#define NHEAD 16
#define HD    64
#define ROWS  (BATCH*SEQ)   // 8192

// ---------------- scratch (device globals; no allocation allowed) ----------
__device__ float g_Qbuf[(size_t)ROWS * DIM];
__device__ float g_KVbuf[(size_t)ROWS * 2 * DIM];
__device__ float g_Q[(size_t)ROWS * DIM];           // [B,H,S,Hd]
__device__ float g_K[(size_t)ROWS * DIM];           // [B,H,Sc,Hd]
__device__ float g_V[(size_t)ROWS * DIM];
__device__ float g_O[(size_t)ROWS * DIM];           // [B,S,H*Hd]

// ---------------- helpers ---------------------------------------------------
__device__ __forceinline__ unsigned tf32(float x) {
    unsigned u;
    asm("cvt.rna.tf32.f32 %0, %1;" : "=r"(u) : "f"(x));
    return u;
}

__device__ __forceinline__ void mma8(float* d, const unsigned* a, const unsigned* b) {
    asm volatile(
        "mma.sync.aligned.m16n8k8.row.col.f32.tf32.tf32.f32 "
        "{%0,%1,%2,%3}, {%4,%5,%6,%7}, {%8,%9}, {%0,%1,%2,%3};"
        : "+f"(d[0]), "+f"(d[1]), "+f"(d[2]), "+f"(d[3])
        : "r"(a[0]), "r"(a[1]), "r"(a[2]), "r"(a[3]), "r"(b[0]), "r"(b[1]));
}

__device__ __forceinline__ void cpa16(uint32_t s, const void* g) {
    asm volatile("cp.async.cg.shared.global [%0], [%1], 16;" :: "r"(s), "l"(g));
}
__device__ __forceinline__ void cpa_commit() {
    asm volatile("cp.async.commit_group;");
}

// ---------------- TF32 GEMM, cp.async double-buffered ----------------------
// 128x128 tile, K-tile 16, 256 threads = 8 warps (2m x 4n), warp 64x32.
#define ASTR 20
#define BSTR 136
__global__ __launch_bounds__(256) void gemm_tf32(
        const float* __restrict__ A, const float* __restrict__ B,
        const float* __restrict__ bias, float* __restrict__ C,
        int M, int N, int K) {
    __shared__ float As[2][128 * ASTR];
    __shared__ float Bs[2][16 * BSTR];

    const int tid  = threadIdx.x;
    const int warp = tid >> 5, lane = tid & 31;
    const int g = lane >> 2, c = lane & 3;
    const int wm = (warp >> 2) * 64, wn = (warp & 3) * 32;
    const int bm = blockIdx.y * 128, bn = blockIdx.x * 128;

    const int ar  = tid >> 2;
    const int ac4 = (tid & 3) << 2;
    const int bk  = tid >> 5;
    const int bc4 = (tid & 31) << 2;

    const float* Ap = A + (size_t)(bm + ar) * K + ac4;
    const float* Bp = B + (size_t)bk * N + bn + bc4;

    uint32_t sA0 = (uint32_t)__cvta_generic_to_shared(&As[0][ar * ASTR + ac4]);
    uint32_t sA1 = (uint32_t)__cvta_generic_to_shared(&As[0][(ar + 64) * ASTR + ac4]);
    uint32_t sB0 = (uint32_t)__cvta_generic_to_shared(&Bs[0][bk * BSTR + bc4]);
    uint32_t sB1 = (uint32_t)__cvta_generic_to_shared(&Bs[0][(bk + 8) * BSTR + bc4]);
    const uint32_t apitch = 128 * ASTR * 4, bpitch = 16 * BSTR * 4;

    float acc[4][4][4];
#pragma unroll
    for (int mi = 0; mi < 4; mi++)
#pragma unroll
        for (int ni = 0; ni < 4; ni++)
#pragma unroll
            for (int t = 0; t < 4; t++) acc[mi][ni][t] = 0.f;

    const int nT = K >> 4;
    // prologue: tile 0 -> buf 0
    {
        cpa16(sA0, Ap);
        cpa16(sA1, Ap + (size_t)64 * K);
        cpa16(sB0, Bp);
        cpa16(sB1, Bp + (size_t)8 * N);
        cpa_commit();
    }

    for (int t = 0; t < nT; t++) {
        const int cur = t & 1;
        if (t + 1 < nT) {
            const int nxt = cur ^ 1;
            const int k0 = (t + 1) << 4;
            cpa16(sA0 + nxt * apitch, Ap + k0);
            cpa16(sA1 + nxt * apitch, Ap + (size_t)64 * K + k0);
            cpa16(sB0 + nxt * bpitch, Bp + (size_t)k0 * N);
            cpa16(sB1 + nxt * bpitch, Bp + (size_t)(k0 + 8) * N);
            cpa_commit();
            asm volatile("cp.async.wait_group 1;");
        } else {
            asm volatile("cp.async.wait_group 0;");
        }
        __syncthreads();

        const float* Ab = As[cur];
        const float* Bb = Bs[cur];
#pragma unroll
        for (int ks = 0; ks < 2; ks++) {
            unsigned af[4][4], bf[4][2];
            const int kk = ks * 8 + c;
#pragma unroll
            for (int mi = 0; mi < 4; mi++) {
                int row = wm + mi * 16 + g;
                af[mi][0] = tf32(Ab[row * ASTR + kk]);
                af[mi][1] = tf32(Ab[(row + 8) * ASTR + kk]);
                af[mi][2] = tf32(Ab[row * ASTR + kk + 4]);
                af[mi][3] = tf32(Ab[(row + 8) * ASTR + kk + 4]);
            }
#pragma unroll
            for (int ni = 0; ni < 4; ni++) {
                int col = wn + ni * 8 + g;
                bf[ni][0] = tf32(Bb[kk * BSTR + col]);
                bf[ni][1] = tf32(Bb[(kk + 4) * BSTR + col]);
            }
#pragma unroll
            for (int mi = 0; mi < 4; mi++)
#pragma unroll
                for (int ni = 0; ni < 4; ni++)
                    mma8(acc[mi][ni], af[mi], bf[ni]);
        }
        __syncthreads();
    }

#pragma unroll
    for (int mi = 0; mi < 4; mi++) {
        int row = bm + wm + mi * 16 + g;
#pragma unroll
        for (int ni = 0; ni < 4; ni++) {
            int col = bn + wn + ni * 8 + 2 * c;
            float bv0 = bias ? bias[col] : 0.f;
            float bv1 = bias ? bias[col + 1] : 0.f;
            float* p0 = C + (size_t)row * N + col;
            float* p1 = C + (size_t)(row + 8) * N + col;
            p0[0] = acc[mi][ni][0] + bv0; p0[1] = acc[mi][ni][1] + bv1;
            p1[0] = acc[mi][ni][2] + bv0; p1[1] = acc[mi][ni][3] + bv1;
        }
    }
}

// --------- per-head LayerNorm + RoPE on q ----------------------------------
__global__ void ln_rope_q_kernel(const float* __restrict__ Qbuf,
                                 const float* __restrict__ gamma,
                                 const float* __restrict__ beta,
                                 float* __restrict__ Q) {
    const int gw   = blockIdx.x * 8 + (threadIdx.x >> 5);
    const int lane = threadIdx.x & 31;
    const int h = gw & (NHEAD - 1);
    const int m = gw >> 4;
    const int b = m >> 11;
    const int s = m & (SEQ - 1);

    const float* in = Qbuf + (size_t)m * DIM + h * HD;
    float v0 = in[lane], v1 = in[lane + 32];

    float sum = v0 + v1;
#pragma unroll
    for (int o = 16; o; o >>= 1) sum += __shfl_xor_sync(0xffffffffu, sum, o);
    float mu = sum * (1.f / 64.f);
    float d0 = v0 - mu, d1 = v1 - mu;
    float vs = d0 * d0 + d1 * d1;
#pragma unroll
    for (int o = 16; o; o >>= 1) vs += __shfl_xor_sync(0xffffffffu, vs, o);
    float rstd = rsqrtf(vs * (1.f / 64.f) + 1e-5f);

    float y0 = d0 * rstd * gamma[lane]      + beta[lane];
    float y1 = d1 * rstd * gamma[lane + 32] + beta[lane + 32];

    float invf = powf(10000.f, -(float)lane * (1.f / 32.f));
    float ang  = (float)s * invf;
    float sn, cs;
    sincosf(ang, &sn, &cs);

    float* outp = Q + ((size_t)(b * NHEAD + h) * SEQ + s) * HD;
    outp[lane]      = y0 * cs - y1 * sn;
    outp[lane + 32] = y0 * sn + y1 * cs;
}

// --------- per-head LayerNorm on k + transpose copy of v -------------------
__global__ void ln_kv_kernel(const float* __restrict__ KVbuf,
                             const float* __restrict__ gamma,
                             const float* __restrict__ beta,
                             float* __restrict__ K, float* __restrict__ V) {
    const int gw   = blockIdx.x * 8 + (threadIdx.x >> 5);
    const int lane = threadIdx.x & 31;
    const int h = gw & (NHEAD - 1);
    const int m = gw >> 4;
    const int b = m >> 11;
    const int sc = m & (SEQ - 1);

    const float* kin = KVbuf + (size_t)m * (2 * DIM) + h * HD;
    const float* vin = kin + DIM;

    float v0 = kin[lane], v1 = kin[lane + 32];
    float sum = v0 + v1;
#pragma unroll
    for (int o = 16; o; o >>= 1) sum += __shfl_xor_sync(0xffffffffu, sum, o);
    float mu = sum * (1.f / 64.f);
    float d0 = v0 - mu, d1 = v1 - mu;
    float vs = d0 * d0 + d1 * d1;
#pragma unroll
    for (int o = 16; o; o >>= 1) vs += __shfl_xor_sync(0xffffffffu, vs, o);
    float rstd = rsqrtf(vs * (1.f / 64.f) + 1e-5f);

    size_t ob = ((size_t)(b * NHEAD + h) * SEQ + sc) * HD;
    K[ob + lane]      = d0 * rstd * gamma[lane]      + beta[lane];
    K[ob + lane + 32] = d1 * rstd * gamma[lane + 32] + beta[lane + 32];
    V[ob + lane]      = vin[lane];
    V[ob + lane + 32] = vin[lane + 32];
}

// --------- flash attention v2: 128q x 64k, warp-private rows ---------------
// 8 warps, warp w owns rows w*16..w*16+15 over ALL 64 keys. P stays in
// registers (quad-shuffle accum->A-frag permute). smem = Ks+Vs = 32 KB.
#define QIDX(r, col) ((r) * 64 + ((col) ^ (((r) & 7) << 2)))
#define VIDX(r, col) ((r) * 64 + ((col) ^ (((r) & 3) << 3)))

__global__ __launch_bounds__(256) void flash_tf32(
        const float* __restrict__ Q, const float* __restrict__ K,
        const float* __restrict__ V, float* __restrict__ O) {
    __shared__ float Ks[64 * 64];
    __shared__ float Vs[64 * 64];

    const int qt = blockIdx.x, h = blockIdx.y, b = blockIdx.z;
    const int tid  = threadIdx.x;
    const int warp = tid >> 5, lane = tid & 31;
    const int g = lane >> 2, c = lane & 3;
    const int wm = warp * 16;            // warp's rows in 128-row tile
    const int qbase = lane & ~3;         // quad leader
    const int srcA = qbase + (c >> 1);
    const int srcB = srcA + 2;
    const bool hi = (c & 1);

    const float* Qg = Q + ((size_t)(b * NHEAD + h) * SEQ + qt * 128) * HD;
    const float* Kg = K + (size_t)(b * NHEAD + h) * SEQ * HD;
    const float* Vg = V + (size_t)(b * NHEAD + h) * SEQ * HD;

    // ---- stage Q (128x64) through Ks (rows 0-63) and Vs (rows 64-127) ----
#pragma unroll
    for (int j = 0; j < 8; j++) {
        int i = tid + j * 256;
        int r = i >> 4, c4 = (i & 15) << 2;
        float4 v = *(const float4*)(Qg + (size_t)r * 64 + c4);
        if (r < 64) *(float4*)&Ks[QIDX(r, c4)] = v;
        else        *(float4*)&Vs[QIDX(r - 64, c4)] = v;
    }
    __syncthreads();

    unsigned qf[8][4];
    {
        const float* buf = (wm < 64) ? Ks : Vs;
        const int rb = wm & 63;
#pragma unroll
        for (int ks = 0; ks < 8; ks++) {
            int kk = ks * 8 + c;
            qf[ks][0] = tf32(buf[QIDX(rb + g, kk)]);
            qf[ks][1] = tf32(buf[QIDX(rb + 8 + g, kk)]);
            qf[ks][2] = tf32(buf[QIDX(rb + g, kk + 4)]);
            qf[ks][3] = tf32(buf[QIDX(rb + 8 + g, kk + 4)]);
        }
    }
    __syncthreads();

    float m0 = -1e30f, m1 = -1e30f, l0 = 0.f, l1 = 0.f;
    float o[8][4];
#pragma unroll
    for (int ni = 0; ni < 8; ni++)
#pragma unroll
        for (int t = 0; t < 4; t++) o[ni][t] = 0.f;

    for (int kt = 0; kt < SEQ / 64; kt++) {
        // ---- load K, V tiles (swizzled) ----
#pragma unroll
        for (int j = 0; j < 4; j++) {
            int i = tid + j * 256;
            int r = i >> 4, c4 = (i & 15) << 2;
            *(float4*)&Ks[QIDX(r, c4)] = *(const float4*)(Kg + (size_t)(kt * 64 + r) * 64 + c4);
            *(float4*)&Vs[VIDX(r, c4)] = *(const float4*)(Vg + (size_t)(kt * 64 + r) * 64 + c4);
        }
        __syncthreads();

        // ---- S = Q K^T : 16 rows x 64 keys per warp ----
        float s[8][4];
#pragma unroll
        for (int ni = 0; ni < 8; ni++)
#pragma unroll
            for (int t = 0; t < 4; t++) s[ni][t] = 0.f;
#pragma unroll
        for (int ks = 0; ks < 8; ks++) {
            int kk = ks * 8 + c;
            unsigned kb[8][2];
#pragma unroll
            for (int ni = 0; ni < 8; ni++) {
                int kc = ni * 8 + g;
                kb[ni][0] = tf32(Ks[QIDX(kc, kk)]);
                kb[ni][1] = tf32(Ks[QIDX(kc, kk + 4)]);
            }
#pragma unroll
            for (int ni = 0; ni < 8; ni++) mma8(s[ni], qf[ks], kb[ni]);
        }

        // ---- online softmax (rows fully owned; reduce over quad c-lanes) --
        float rm0 = -1e30f, rm1 = -1e30f;
#pragma unroll
        for (int ni = 0; ni < 8; ni++) {
            s[ni][0] *= 0.125f; s[ni][1] *= 0.125f;
            s[ni][2] *= 0.125f; s[ni][3] *= 0.125f;
            rm0 = fmaxf(rm0, fmaxf(s[ni][0], s[ni][1]));
            rm1 = fmaxf(rm1, fmaxf(s[ni][2], s[ni][3]));
        }
        rm0 = fmaxf(rm0, __shfl_xor_sync(0xffffffffu, rm0, 1));
        rm0 = fmaxf(rm0, __shfl_xor_sync(0xffffffffu, rm0, 2));
        rm1 = fmaxf(rm1, __shfl_xor_sync(0xffffffffu, rm1, 1));
        rm1 = fmaxf(rm1, __shfl_xor_sync(0xffffffffu, rm1, 2));
        float mn0 = fmaxf(m0, rm0), mn1 = fmaxf(m1, rm1);

        float ps0 = 0.f, ps1 = 0.f;
#pragma unroll
        for (int ni = 0; ni < 8; ni++) {
            s[ni][0] = __expf(s[ni][0] - mn0); s[ni][1] = __expf(s[ni][1] - mn0);
            s[ni][2] = __expf(s[ni][2] - mn1); s[ni][3] = __expf(s[ni][3] - mn1);
            ps0 += s[ni][0] + s[ni][1];
            ps1 += s[ni][2] + s[ni][3];
        }
        ps0 += __shfl_xor_sync(0xffffffffu, ps0, 1);
        ps0 += __shfl_xor_sync(0xffffffffu, ps0, 2);
        ps1 += __shfl_xor_sync(0xffffffffu, ps1, 1);
        ps1 += __shfl_xor_sync(0xffffffffu, ps1, 2);

        float al0 = __expf(m0 - mn0), al1 = __expf(m1 - mn1);
        m0 = mn0; m1 = mn1;
        l0 = l0 * al0 + ps0;
        l1 = l1 * al1 + ps1;
#pragma unroll
        for (int ni = 0; ni < 8; ni++) {
            o[ni][0] *= al0; o[ni][1] *= al0;
            o[ni][2] *= al1; o[ni][3] *= al1;
        }

        // ---- O += P @ V : P permuted accum->A-frag via quad shuffles ------
#pragma unroll
        for (int ks = 0; ks < 8; ks++) {
            float e0 = __shfl_sync(0xffffffffu, s[ks][0], srcA);
            float e1 = __shfl_sync(0xffffffffu, s[ks][1], srcA);
            float f0 = __shfl_sync(0xffffffffu, s[ks][0], srcB);
            float f1 = __shfl_sync(0xffffffffu, s[ks][1], srcB);
            float g0 = __shfl_sync(0xffffffffu, s[ks][2], srcA);
            float g1 = __shfl_sync(0xffffffffu, s[ks][3], srcA);
            float h0 = __shfl_sync(0xffffffffu, s[ks][2], srcB);
            float h1 = __shfl_sync(0xffffffffu, s[ks][3], srcB);
            unsigned pa[4];
            pa[0] = tf32(hi ? e1 : e0);
            pa[1] = tf32(hi ? g1 : g0);
            pa[2] = tf32(hi ? f1 : f0);
            pa[3] = tf32(hi ? h1 : h0);

            int kk = ks * 8 + c;
            unsigned vb[8][2];
#pragma unroll
            for (int ni = 0; ni < 8; ni++) {
                int dc = ni * 8 + g;
                vb[ni][0] = tf32(Vs[VIDX(kk, dc)]);
                vb[ni][1] = tf32(Vs[VIDX(kk + 4, dc)]);
            }
#pragma unroll
            for (int ni = 0; ni < 8; ni++) mma8(o[ni], pa, vb[ni]);
        }
        __syncthreads();   // all warps done with Ks/Vs before next tile load
    }

    // ---- epilogue -> O [B, S, H*Hd] ----
    float inv0 = 1.f / l0, inv1 = 1.f / l1;
    int row0 = qt * 128 + wm + g;
#pragma unroll
    for (int ni = 0; ni < 8; ni++) {
        int col = h * HD + ni * 8 + 2 * c;
        float* p0 = O + ((size_t)b * SEQ + row0) * DIM + col;
        float* p1 = O + ((size_t)b * SEQ + row0 + 8) * DIM + col;
        p0[0] = o[ni][0] * inv0; p0[1] = o[ni][1] * inv0;
        p1[0] = o[ni][2] * inv1; p1[1] = o[ni][3] * inv1;
    }
}

// ---------------------------------------------------------------------------
extern "C" void kernel_launch(void* const* d_in, const int* in_sizes, int n_in,
                              void* d_out, int out_size) {
    const float* x        = (const float*)d_in[0];
    const float* context  = (const float*)d_in[1];
    const float* q_w      = (const float*)d_in[2];
    const float* kv_w     = (const float*)d_in[3];
    const float* qn_scale = (const float*)d_in[4];
    const float* qn_bias  = (const float*)d_in[5];
    const float* kn_scale = (const float*)d_in[6];
    const float* kn_bias  = (const float*)d_in[7];
    const float* proj_w   = (const float*)d_in[8];
    const float* proj_b   = (const float*)d_in[9];
    float* out = (float*)d_out;

    float *Qbuf, *KVbuf, *Q, *K, *V, *O;
    cudaGetSymbolAddress((void**)&Qbuf,  g_Qbuf);
    cudaGetSymbolAddress((void**)&KVbuf, g_KVbuf);
    cudaGetSymbolAddress((void**)&Q,     g_Q);
    cudaGetSymbolAddress((void**)&K,     g_K);
    cudaGetSymbolAddress((void**)&V,     g_V);
    cudaGetSymbolAddress((void**)&O,     g_O);

    gemm_tf32<<<dim3(DIM / 128, ROWS / 128), 256>>>(x, q_w, nullptr, Qbuf, ROWS, DIM, DIM);
    gemm_tf32<<<dim3(2 * DIM / 128, ROWS / 128), 256>>>(context, kv_w, nullptr, KVbuf, ROWS, 2 * DIM, DIM);
    ln_rope_q_kernel<<<(ROWS * NHEAD) / 8, 256>>>(Qbuf, qn_scale, qn_bias, Q);
    ln_kv_kernel<<<(ROWS * NHEAD) / 8, 256>>>(KVbuf, kn_scale, kn_bias, K, V);
    flash_tf32<<<dim3(SEQ / 128, NHEAD, BATCH), 256>>>(Q, K, V, O);
    gemm_tf32<<<dim3(DIM / 128, ROWS / 128), 256>>>(O, proj_w, proj_b, out, ROWS, DIM, DIM);
}

// round 4
// speedup vs baseline: 3.1729x; 1.0636x over previous
#include <cuda_runtime.h>
#include <math.h>
#include <stdint.h>

#define BATCH 4
#define SEQ   2048
#define DIM   1024
#define NHEAD 16
#define HD    64
#define ROWS  (BATCH*SEQ)   // 8192

// ---------------- scratch (device globals; no allocation allowed) ----------
__device__ float g_Qbuf[(size_t)ROWS * DIM];
__device__ float g_KVbuf[(size_t)ROWS * 2 * DIM];
__device__ float g_Q[(size_t)ROWS * DIM];           // [B,H,S,Hd]
__device__ float g_K[(size_t)ROWS * DIM];           // [B,H,Sc,Hd]
__device__ float g_V[(size_t)ROWS * DIM];
__device__ float g_O[(size_t)ROWS * DIM];           // [B,S,H*Hd]

// ---------------- helpers ---------------------------------------------------
__device__ __forceinline__ unsigned tf32(float x) {
    unsigned u;
    asm("cvt.rna.tf32.f32 %0, %1;" : "=r"(u) : "f"(x));
    return u;
}

__device__ __forceinline__ void mma8(float* d, const unsigned* a, const unsigned* b) {
    asm volatile(
        "mma.sync.aligned.m16n8k8.row.col.f32.tf32.tf32.f32 "
        "{%0,%1,%2,%3}, {%4,%5,%6,%7}, {%8,%9}, {%0,%1,%2,%3};"
        : "+f"(d[0]), "+f"(d[1]), "+f"(d[2]), "+f"(d[3])
        : "r"(a[0]), "r"(a[1]), "r"(a[2]), "r"(a[3]), "r"(b[0]), "r"(b[1]));
}

__device__ __forceinline__ void cpa16(uint32_t s, const void* g) {
    asm volatile("cp.async.cg.shared.global [%0], [%1], 16;" :: "r"(s), "l"(g));
}
__device__ __forceinline__ void cpa_commit() {
    asm volatile("cp.async.commit_group;");
}
__device__ __forceinline__ uint32_t sptr(const void* p) {
    return (uint32_t)__cvta_generic_to_shared(p);
}

// ---------------- TF32 GEMM, 3-stage cp.async pipeline ---------------------
// 128x128 tile, K-tile 16, 256 threads = 8 warps (2m x 4n), warp 64x32.
#define ASTR 20
#define BSTR 136
#define GA_SZ (128*ASTR)
#define GB_SZ (16*BSTR)
#define GEMM_SMEM (3*(GA_SZ+GB_SZ)*4)

__global__ __launch_bounds__(256) void gemm_tf32(
        const float* __restrict__ A, const float* __restrict__ B,
        const float* __restrict__ bias, float* __restrict__ C,
        int M, int N, int K) {
    extern __shared__ float sm[];
    float* Abuf = sm;               // 3 stages of GA_SZ
    float* Bbuf = sm + 3 * GA_SZ;   // 3 stages of GB_SZ

    const int tid  = threadIdx.x;
    const int warp = tid >> 5, lane = tid & 31;
    const int g = lane >> 2, c = lane & 3;
    const int wm = (warp >> 2) * 64, wn = (warp & 3) * 32;
    const int bm = blockIdx.y * 128, bn = blockIdx.x * 128;

    const int ar  = tid >> 2;
    const int ac4 = (tid & 3) << 2;
    const int bk  = tid >> 5;
    const int bc4 = (tid & 31) << 2;

    const float* Ap = A + (size_t)(bm + ar) * K + ac4;
    const float* Bp = B + (size_t)bk * N + bn + bc4;

    const uint32_t aB0 = sptr(&Abuf[ar * ASTR + ac4]);
    const uint32_t aB1 = sptr(&Abuf[(ar + 64) * ASTR + ac4]);
    const uint32_t bB0 = sptr(&Bbuf[bk * BSTR + bc4]);
    const uint32_t bB1 = sptr(&Bbuf[(bk + 8) * BSTR + bc4]);

    float acc[4][4][4];
#pragma unroll
    for (int mi = 0; mi < 4; mi++)
#pragma unroll
        for (int ni = 0; ni < 4; ni++)
#pragma unroll
            for (int t = 0; t < 4; t++) acc[mi][ni][t] = 0.f;

    const int nT = K >> 4;

    auto issue = [&](int t) {
        const int st = t % 3;
        const int k0 = t << 4;
        cpa16(aB0 + st * GA_SZ * 4, Ap + k0);
        cpa16(aB1 + st * GA_SZ * 4, Ap + (size_t)64 * K + k0);
        cpa16(bB0 + st * GB_SZ * 4, Bp + (size_t)k0 * N);
        cpa16(bB1 + st * GB_SZ * 4, Bp + (size_t)(k0 + 8) * N);
    };

    issue(0); cpa_commit();
    issue(1); cpa_commit();

    for (int t = 0; t < nT; t++) {
        asm volatile("cp.async.wait_group 1;");
        __syncthreads();
        if (t + 2 < nT) issue(t + 2);
        cpa_commit();

        const float* Ab = Abuf + (t % 3) * GA_SZ;
        const float* Bb = Bbuf + (t % 3) * GB_SZ;
#pragma unroll
        for (int ks = 0; ks < 2; ks++) {
            unsigned af[4][4], bf[4][2];
            const int kk = ks * 8 + c;
#pragma unroll
            for (int mi = 0; mi < 4; mi++) {
                int row = wm + mi * 16 + g;
                af[mi][0] = tf32(Ab[row * ASTR + kk]);
                af[mi][1] = tf32(Ab[(row + 8) * ASTR + kk]);
                af[mi][2] = tf32(Ab[row * ASTR + kk + 4]);
                af[mi][3] = tf32(Ab[(row + 8) * ASTR + kk + 4]);
            }
#pragma unroll
            for (int ni = 0; ni < 4; ni++) {
                int col = wn + ni * 8 + g;
                bf[ni][0] = tf32(Bb[kk * BSTR + col]);
                bf[ni][1] = tf32(Bb[(kk + 4) * BSTR + col]);
            }
#pragma unroll
            for (int mi = 0; mi < 4; mi++)
#pragma unroll
                for (int ni = 0; ni < 4; ni++)
                    mma8(acc[mi][ni], af[mi], bf[ni]);
        }
    }

#pragma unroll
    for (int mi = 0; mi < 4; mi++) {
        int row = bm + wm + mi * 16 + g;
#pragma unroll
        for (int ni = 0; ni < 4; ni++) {
            int col = bn + wn + ni * 8 + 2 * c;
            float bv0 = bias ? bias[col] : 0.f;
            float bv1 = bias ? bias[col + 1] : 0.f;
            float* p0 = C + (size_t)row * N + col;
            float* p1 = C + (size_t)(row + 8) * N + col;
            p0[0] = acc[mi][ni][0] + bv0; p0[1] = acc[mi][ni][1] + bv1;
            p1[0] = acc[mi][ni][2] + bv0; p1[1] = acc[mi][ni][3] + bv1;
        }
    }
}

// --------- per-head LayerNorm + RoPE on q ----------------------------------
__global__ void ln_rope_q_kernel(const float* __restrict__ Qbuf,
                                 const float* __restrict__ gamma,
                                 const float* __restrict__ beta,
                                 float* __restrict__ Q) {
    const int gw   = blockIdx.x * 8 + (threadIdx.x >> 5);
    const int lane = threadIdx.x & 31;
    const int h = gw & (NHEAD - 1);
    const int m = gw >> 4;
    const int b = m >> 11;
    const int s = m & (SEQ - 1);

    const float* in = Qbuf + (size_t)m * DIM + h * HD;
    float v0 = in[lane], v1 = in[lane + 32];

    float sum = v0 + v1;
#pragma unroll
    for (int o = 16; o; o >>= 1) sum += __shfl_xor_sync(0xffffffffu, sum, o);
    float mu = sum * (1.f / 64.f);
    float d0 = v0 - mu, d1 = v1 - mu;
    float vs = d0 * d0 + d1 * d1;
#pragma unroll
    for (int o = 16; o; o >>= 1) vs += __shfl_xor_sync(0xffffffffu, vs, o);
    float rstd = rsqrtf(vs * (1.f / 64.f) + 1e-5f);

    float y0 = d0 * rstd * gamma[lane]      + beta[lane];
    float y1 = d1 * rstd * gamma[lane + 32] + beta[lane + 32];

    float invf = powf(10000.f, -(float)lane * (1.f / 32.f));
    float ang  = (float)s * invf;
    float sn, cs;
    sincosf(ang, &sn, &cs);

    float* outp = Q + ((size_t)(b * NHEAD + h) * SEQ + s) * HD;
    outp[lane]      = y0 * cs - y1 * sn;
    outp[lane + 32] = y0 * sn + y1 * cs;
}

// --------- per-head LayerNorm on k + transpose copy of v -------------------
__global__ void ln_kv_kernel(const float* __restrict__ KVbuf,
                             const float* __restrict__ gamma,
                             const float* __restrict__ beta,
                             float* __restrict__ K, float* __restrict__ V) {
    const int gw   = blockIdx.x * 8 + (threadIdx.x >> 5);
    const int lane = threadIdx.x & 31;
    const int h = gw & (NHEAD - 1);
    const int m = gw >> 4;
    const int b = m >> 11;
    const int sc = m & (SEQ - 1);

    const float* kin = KVbuf + (size_t)m * (2 * DIM) + h * HD;
    const float* vin = kin + DIM;

    float v0 = kin[lane], v1 = kin[lane + 32];
    float sum = v0 + v1;
#pragma unroll
    for (int o = 16; o; o >>= 1) sum += __shfl_xor_sync(0xffffffffu, sum, o);
    float mu = sum * (1.f / 64.f);
    float d0 = v0 - mu, d1 = v1 - mu;
    float vs = d0 * d0 + d1 * d1;
#pragma unroll
    for (int o = 16; o; o >>= 1) vs += __shfl_xor_sync(0xffffffffu, vs, o);
    float rstd = rsqrtf(vs * (1.f / 64.f) + 1e-5f);

    size_t ob = ((size_t)(b * NHEAD + h) * SEQ + sc) * HD;
    K[ob + lane]      = d0 * rstd * gamma[lane]      + beta[lane];
    K[ob + lane + 32] = d1 * rstd * gamma[lane + 32] + beta[lane + 32];
    V[ob + lane]      = vin[lane];
    V[ob + lane + 32] = vin[lane + 32];
}

// --------- flash attention: 128q x 64k, 3-stage cp.async K/V pipeline ------
// 8 warps, warp w owns rows w*16..w*16+15 over all 64 keys. P stays in regs.
// smem: 3 stages x (K 16KB + V 16KB) = 96KB dynamic.
#define QIDX(r, col) ((r) * 64 + ((col) ^ (((r) & 7) << 2)))
#define VIDX(r, col) ((r) * 64 + ((col) ^ (((r) & 3) << 3)))
#define FSTG 8192
#define FLASH_SMEM (3*FSTG*4)

__global__ __launch_bounds__(256) void flash_tf32(
        const float* __restrict__ Q, const float* __restrict__ K,
        const float* __restrict__ V, float* __restrict__ O) {
    extern __shared__ float stage[];   // 3 * FSTG floats

    const int qt = blockIdx.x, h = blockIdx.y, b = blockIdx.z;
    const int tid  = threadIdx.x;
    const int warp = tid >> 5, lane = tid & 31;
    const int g = lane >> 2, c = lane & 3;
    const int wm = warp * 16;
    const int qbase = lane & ~3;
    const int srcA = qbase + (c >> 1);
    const int srcB = srcA + 2;
    const bool hi = (c & 1);

    const float* Qg = Q + ((size_t)(b * NHEAD + h) * SEQ + qt * 128) * HD;
    const float* Kg = K + (size_t)(b * NHEAD + h) * SEQ * HD;
    const float* Vg = V + (size_t)(b * NHEAD + h) * SEQ * HD;

    // ---- stage Q (128x64) through stage0 via cp.async ----
#pragma unroll
    for (int j = 0; j < 8; j++) {
        int i = tid + j * 256;
        int r = i >> 4, c4 = (i & 15) << 2;
        float* dst = (r < 64) ? &stage[QIDX(r, c4)] : &stage[4096 + QIDX(r - 64, c4)];
        cpa16(sptr(dst), Qg + (size_t)r * 64 + c4);
    }
    cpa_commit();
    asm volatile("cp.async.wait_group 0;");
    __syncthreads();

    unsigned qf[8][4];
    {
        const float* buf = (wm < 64) ? stage : stage + 4096;
        const int rb = wm & 63;
#pragma unroll
        for (int ks = 0; ks < 8; ks++) {
            int kk = ks * 8 + c;
            qf[ks][0] = tf32(buf[QIDX(rb + g, kk)]);
            qf[ks][1] = tf32(buf[QIDX(rb + 8 + g, kk)]);
            qf[ks][2] = tf32(buf[QIDX(rb + g, kk + 4)]);
            qf[ks][3] = tf32(buf[QIDX(rb + 8 + g, kk + 4)]);
        }
    }
    __syncthreads();   // qf extracted everywhere before tile0 overwrites stage0

    auto issueKV = [&](int t) {
        float* Kb = stage + (t % 3) * FSTG;
        float* Vb = Kb + 4096;
#pragma unroll
        for (int j = 0; j < 4; j++) {
            int i = tid + j * 256;
            int r = i >> 4, c4 = (i & 15) << 2;
            cpa16(sptr(&Kb[QIDX(r, c4)]), Kg + (size_t)(t * 64 + r) * 64 + c4);
            cpa16(sptr(&Vb[VIDX(r, c4)]), Vg + (size_t)(t * 64 + r) * 64 + c4);
        }
    };

    issueKV(0); cpa_commit();
    issueKV(1); cpa_commit();

    float m0 = -1e30f, m1 = -1e30f, l0 = 0.f, l1 = 0.f;
    float o[8][4];
#pragma unroll
    for (int ni = 0; ni < 8; ni++)
#pragma unroll
        for (int t = 0; t < 4; t++) o[ni][t] = 0.f;

    const int nT = SEQ / 64;
    for (int kt = 0; kt < nT; kt++) {
        asm volatile("cp.async.wait_group 1;");
        __syncthreads();
        if (kt + 2 < nT) issueKV(kt + 2);
        cpa_commit();

        const float* Ks = stage + (kt % 3) * FSTG;
        const float* Vs = Ks + 4096;

        // ---- S = Q K^T : 16 rows x 64 keys per warp ----
        float s[8][4];
#pragma unroll
        for (int ni = 0; ni < 8; ni++)
#pragma unroll
            for (int t = 0; t < 4; t++) s[ni][t] = 0.f;
#pragma unroll
        for (int ks = 0; ks < 8; ks++) {
            int kk = ks * 8 + c;
            unsigned kb[8][2];
#pragma unroll
            for (int ni = 0; ni < 8; ni++) {
                int kc = ni * 8 + g;
                kb[ni][0] = tf32(Ks[QIDX(kc, kk)]);
                kb[ni][1] = tf32(Ks[QIDX(kc, kk + 4)]);
            }
#pragma unroll
            for (int ni = 0; ni < 8; ni++) mma8(s[ni], qf[ks], kb[ni]);
        }

        // ---- online softmax ----
        float rm0 = -1e30f, rm1 = -1e30f;
#pragma unroll
        for (int ni = 0; ni < 8; ni++) {
            s[ni][0] *= 0.125f; s[ni][1] *= 0.125f;
            s[ni][2] *= 0.125f; s[ni][3] *= 0.125f;
            rm0 = fmaxf(rm0, fmaxf(s[ni][0], s[ni][1]));
            rm1 = fmaxf(rm1, fmaxf(s[ni][2], s[ni][3]));
        }
        rm0 = fmaxf(rm0, __shfl_xor_sync(0xffffffffu, rm0, 1));
        rm0 = fmaxf(rm0, __shfl_xor_sync(0xffffffffu, rm0, 2));
        rm1 = fmaxf(rm1, __shfl_xor_sync(0xffffffffu, rm1, 1));
        rm1 = fmaxf(rm1, __shfl_xor_sync(0xffffffffu, rm1, 2));
        float mn0 = fmaxf(m0, rm0), mn1 = fmaxf(m1, rm1);

        float ps0 = 0.f, ps1 = 0.f;
#pragma unroll
        for (int ni = 0; ni < 8; ni++) {
            s[ni][0] = __expf(s[ni][0] - mn0); s[ni][1] = __expf(s[ni][1] - mn0);
            s[ni][2] = __expf(s[ni][2] - mn1); s[ni][3] = __expf(s[ni][3] - mn1);
            ps0 += s[ni][0] + s[ni][1];
            ps1 += s[ni][2] + s[ni][3];
        }
        ps0 += __shfl_xor_sync(0xffffffffu, ps0, 1);
        ps0 += __shfl_xor_sync(0xffffffffu, ps0, 2);
        ps1 += __shfl_xor_sync(0xffffffffu, ps1, 1);
        ps1 += __shfl_xor_sync(0xffffffffu, ps1, 2);

        float al0 = __expf(m0 - mn0), al1 = __expf(m1 - mn1);
        m0 = mn0; m1 = mn1;
        l0 = l0 * al0 + ps0;
        l1 = l1 * al1 + ps1;
#pragma unroll
        for (int ni = 0; ni < 8; ni++) {
            o[ni][0] *= al0; o[ni][1] *= al0;
            o[ni][2] *= al1; o[ni][3] *= al1;
        }

        // ---- O += P @ V : accum->A-frag permute via quad shuffles ----
#pragma unroll
        for (int ks = 0; ks < 8; ks++) {
            float e0 = __shfl_sync(0xffffffffu, s[ks][0], srcA);
            float e1 = __shfl_sync(0xffffffffu, s[ks][1], srcA);
            float f0 = __shfl_sync(0xffffffffu, s[ks][0], srcB);
            float f1 = __shfl_sync(0xffffffffu, s[ks][1], srcB);
            float g0 = __shfl_sync(0xffffffffu, s[ks][2], srcA);
            float g1 = __shfl_sync(0xffffffffu, s[ks][3], srcA);
            float h0 = __shfl_sync(0xffffffffu, s[ks][2], srcB);
            float h1 = __shfl_sync(0xffffffffu, s[ks][3], srcB);
            unsigned pa[4];
            pa[0] = tf32(hi ? e1 : e0);
            pa[1] = tf32(hi ? g1 : g0);
            pa[2] = tf32(hi ? f1 : f0);
            pa[3] = tf32(hi ? h1 : h0);

            int kk = ks * 8 + c;
            unsigned vb[8][2];
#pragma unroll
            for (int ni = 0; ni < 8; ni++) {
                int dc = ni * 8 + g;
                vb[ni][0] = tf32(Vs[VIDX(kk, dc)]);
                vb[ni][1] = tf32(Vs[VIDX(kk + 4, dc)]);
            }
#pragma unroll
            for (int ni = 0; ni < 8; ni++) mma8(o[ni], pa, vb[ni]);
        }
    }

    // ---- epilogue -> O [B, S, H*Hd] ----
    float inv0 = 1.f / l0, inv1 = 1.f / l1;
    int row0 = qt * 128 + wm + g;
#pragma unroll
    for (int ni = 0; ni < 8; ni++) {
        int col = h * HD + ni * 8 + 2 * c;
        float* p0 = O + ((size_t)b * SEQ + row0) * DIM + col;
        float* p1 = O + ((size_t)b * SEQ + row0 + 8) * DIM + col;
        p0[0] = o[ni][0] * inv0; p0[1] = o[ni][1] * inv0;
        p1[0] = o[ni][2] * inv1; p1[1] = o[ni][3] * inv1;
    }
}

// ---------------------------------------------------------------------------
extern "C" void kernel_launch(void* const* d_in, const int* in_sizes, int n_in,
                              void* d_out, int out_size) {
    const float* x        = (const float*)d_in[0];
    const float* context  = (const float*)d_in[1];
    const float* q_w      = (const float*)d_in[2];
    const float* kv_w     = (const float*)d_in[3];
    const float* qn_scale = (const float*)d_in[4];
    const float* qn_bias  = (const float*)d_in[5];
    const float* kn_scale = (const float*)d_in[6];
    const float* kn_bias  = (const float*)d_in[7];
    const float* proj_w   = (const float*)d_in[8];
    const float* proj_b   = (const float*)d_in[9];
    float* out = (float*)d_out;

    float *Qbuf, *KVbuf, *Q, *K, *V, *O;
    cudaGetSymbolAddress((void**)&Qbuf,  g_Qbuf);
    cudaGetSymbolAddress((void**)&KVbuf, g_KVbuf);
    cudaGetSymbolAddress((void**)&Q,     g_Q);
    cudaGetSymbolAddress((void**)&K,     g_K);
    cudaGetSymbolAddress((void**)&V,     g_V);
    cudaGetSymbolAddress((void**)&O,     g_O);

    cudaFuncSetAttribute(gemm_tf32,
        cudaFuncAttributeMaxDynamicSharedMemorySize, GEMM_SMEM);
    cudaFuncSetAttribute(flash_tf32,
        cudaFuncAttributeMaxDynamicSharedMemorySize, FLASH_SMEM);

    gemm_tf32<<<dim3(DIM / 128, ROWS / 128), 256, GEMM_SMEM>>>(
        x, q_w, nullptr, Qbuf, ROWS, DIM, DIM);
    gemm_tf32<<<dim3(2 * DIM / 128, ROWS / 128), 256, GEMM_SMEM>>>(
        context, kv_w, nullptr, KVbuf, ROWS, 2 * DIM, DIM);
    ln_rope_q_kernel<<<(ROWS * NHEAD) / 8, 256>>>(Qbuf, qn_scale, qn_bias, Q);
    ln_kv_kernel<<<(ROWS * NHEAD) / 8, 256>>>(KVbuf, kn_scale, kn_bias, K, V);
    flash_tf32<<<dim3(SEQ / 128, NHEAD, BATCH), 256, FLASH_SMEM>>>(Q, K, V, O);
    gemm_tf32<<<dim3(DIM / 128, ROWS / 128), 256, GEMM_SMEM>>>(
        O, proj_w, proj_b, out, ROWS, DIM, DIM);
}

// round 5
// speedup vs baseline: 3.4304x; 1.0812x over previous
#include <cuda_runtime.h>
#include <math.h>
#include <stdint.h>

#define BATCH 4
#define SEQ   2048
#define DIM   1024
#define NHEAD 16
#define HD    64
#define ROWS  (BATCH*SEQ)   // 8192

// ---------------- scratch (device globals; no allocation allowed) ----------
__device__ float g_Qbuf[(size_t)ROWS * DIM];
__device__ float g_KVbuf[(size_t)ROWS * 2 * DIM];
__device__ float g_Q[(size_t)ROWS * DIM];           // [B,H,S,Hd] tf32-rounded
__device__ float g_K[(size_t)ROWS * DIM];           // tf32-rounded
__device__ float g_V[(size_t)ROWS * DIM];           // tf32-rounded
__device__ float g_O[(size_t)ROWS * DIM];           // tf32-rounded
// tf32-rounded copies of external inputs
__device__ float g_xc[(size_t)ROWS * DIM];
__device__ float g_cc[(size_t)ROWS * DIM];
__device__ float g_qwc[(size_t)DIM * DIM];
__device__ float g_kvwc[(size_t)DIM * 2 * DIM];
__device__ float g_pwc[(size_t)DIM * DIM];

// ---------------- helpers ---------------------------------------------------
__device__ __forceinline__ unsigned tf32(float x) {
    unsigned u;
    asm("cvt.rna.tf32.f32 %0, %1;" : "=r"(u) : "f"(x));
    return u;
}

__device__ __forceinline__ void mma8(float* d, const unsigned* a, const unsigned* b) {
    asm volatile(
        "mma.sync.aligned.m16n8k8.row.col.f32.tf32.tf32.f32 "
        "{%0,%1,%2,%3}, {%4,%5,%6,%7}, {%8,%9}, {%0,%1,%2,%3};"
        : "+f"(d[0]), "+f"(d[1]), "+f"(d[2]), "+f"(d[3])
        : "r"(a[0]), "r"(a[1]), "r"(a[2]), "r"(a[3]), "r"(b[0]), "r"(b[1]));
}

__device__ __forceinline__ void ldsm4(unsigned* r, uint32_t addr) {
    asm volatile("ldmatrix.sync.aligned.m8n8.x4.shared.b16 {%0,%1,%2,%3}, [%4];"
        : "=r"(r[0]), "=r"(r[1]), "=r"(r[2]), "=r"(r[3]) : "r"(addr));
}

__device__ __forceinline__ void cpa16(uint32_t s, const void* g) {
    asm volatile("cp.async.cg.shared.global [%0], [%1], 16;" :: "r"(s), "l"(g));
}
__device__ __forceinline__ void cpa_commit() {
    asm volatile("cp.async.commit_group;");
}
__device__ __forceinline__ uint32_t sptr(const void* p) {
    return (uint32_t)__cvta_generic_to_shared(p);
}

// ---------------- tf32 rounding pass ----------------------------------------
__global__ void round_tf32_kernel(const float4* __restrict__ in,
                                  float4* __restrict__ out, int n4) {
    int i = blockIdx.x * blockDim.x + threadIdx.x;
    if (i < n4) {
        float4 v = in[i];
        v.x = __uint_as_float(tf32(v.x));
        v.y = __uint_as_float(tf32(v.y));
        v.z = __uint_as_float(tf32(v.z));
        v.w = __uint_as_float(tf32(v.w));
        out[i] = v;
    }
}

// ---------------- TF32 GEMM, 3-stage cp.async + ldmatrix -------------------
// Inputs pre-rounded to tf32. 128x128 tile, K-tile 16, 8 warps (2m x 4n).
#define ASTR 20
#define BSTR 136
#define GA_SZ (128*ASTR)
#define GB_SZ (16*BSTR)
#define GEMM_SMEM (3*(GA_SZ+GB_SZ)*4)

__global__ __launch_bounds__(256) void gemm_tf32(
        const float* __restrict__ A, const float* __restrict__ B,
        const float* __restrict__ bias, float* __restrict__ C,
        int M, int N, int K) {
    extern __shared__ float sm[];
    float* Abuf = sm;
    float* Bbuf = sm + 3 * GA_SZ;

    const int tid  = threadIdx.x;
    const int warp = tid >> 5, lane = tid & 31;
    const int g = lane >> 2, c = lane & 3;
    const int wm = (warp >> 2) * 64, wn = (warp & 3) * 32;
    const int bm = blockIdx.y * 128, bn = blockIdx.x * 128;

    const int ar  = tid >> 2;
    const int ac4 = (tid & 3) << 2;
    const int bk  = tid >> 5;
    const int bc4 = (tid & 31) << 2;

    const float* Ap = A + (size_t)(bm + ar) * K + ac4;
    const float* Bp = B + (size_t)bk * N + bn + bc4;

    const uint32_t aB0 = sptr(&Abuf[ar * ASTR + ac4]);
    const uint32_t aB1 = sptr(&Abuf[(ar + 64) * ASTR + ac4]);
    const uint32_t bB0 = sptr(&Bbuf[bk * BSTR + bc4]);
    const uint32_t bB1 = sptr(&Bbuf[(bk + 8) * BSTR + bc4]);

    // ldmatrix A-fragment addressing: lane -> (matrix m = lane>>3, row rw = lane&7)
    const int mloc = lane >> 3, rw = lane & 7;
    const uint32_t a_off =
        (uint32_t)((wm + ((mloc & 1) << 3) + rw) * ASTR + ((mloc >> 1) << 2)) * 4;
    const uint32_t abase0 = sptr(Abuf) + a_off;

    float acc[4][4][4];
#pragma unroll
    for (int mi = 0; mi < 4; mi++)
#pragma unroll
        for (int ni = 0; ni < 4; ni++)
#pragma unroll
            for (int t = 0; t < 4; t++) acc[mi][ni][t] = 0.f;

    const int nT = K >> 4;

    auto issue = [&](int t) {
        const int st = t % 3;
        const int k0 = t << 4;
        cpa16(aB0 + st * GA_SZ * 4, Ap + k0);
        cpa16(aB1 + st * GA_SZ * 4, Ap + (size_t)64 * K + k0);
        cpa16(bB0 + st * GB_SZ * 4, Bp + (size_t)k0 * N);
        cpa16(bB1 + st * GB_SZ * 4, Bp + (size_t)(k0 + 8) * N);
    };

    issue(0); cpa_commit();
    issue(1); cpa_commit();

    for (int t = 0; t < nT; t++) {
        asm volatile("cp.async.wait_group 1;");
        __syncthreads();
        if (t + 2 < nT) issue(t + 2);
        cpa_commit();

        const int st = t % 3;
        const uint32_t ab = abase0 + st * GA_SZ * 4;
        const float* Bb = Bbuf + st * GB_SZ;
#pragma unroll
        for (int ks = 0; ks < 2; ks++) {
            unsigned af[4][4], bf[4][2];
            const int kk = ks * 8 + c;
#pragma unroll
            for (int mi = 0; mi < 4; mi++)
                ldsm4(af[mi], ab + mi * (16 * ASTR * 4) + ks * 32);
#pragma unroll
            for (int ni = 0; ni < 4; ni++) {
                int col = wn + ni * 8 + g;
                bf[ni][0] = __float_as_uint(Bb[kk * BSTR + col]);
                bf[ni][1] = __float_as_uint(Bb[(kk + 4) * BSTR + col]);
            }
#pragma unroll
            for (int mi = 0; mi < 4; mi++)
#pragma unroll
                for (int ni = 0; ni < 4; ni++)
                    mma8(acc[mi][ni], af[mi], bf[ni]);
        }
    }

#pragma unroll
    for (int mi = 0; mi < 4; mi++) {
        int row = bm + wm + mi * 16 + g;
#pragma unroll
        for (int ni = 0; ni < 4; ni++) {
            int col = bn + wn + ni * 8 + 2 * c;
            float bv0 = bias ? bias[col] : 0.f;
            float bv1 = bias ? bias[col + 1] : 0.f;
            float* p0 = C + (size_t)row * N + col;
            float* p1 = C + (size_t)(row + 8) * N + col;
            p0[0] = acc[mi][ni][0] + bv0; p0[1] = acc[mi][ni][1] + bv1;
            p1[0] = acc[mi][ni][2] + bv0; p1[1] = acc[mi][ni][3] + bv1;
        }
    }
}

// --------- per-head LayerNorm + RoPE on q (tf32-rounded output) ------------
__global__ void ln_rope_q_kernel(const float* __restrict__ Qbuf,
                                 const float* __restrict__ gamma,
                                 const float* __restrict__ beta,
                                 float* __restrict__ Q) {
    const int gw   = blockIdx.x * 8 + (threadIdx.x >> 5);
    const int lane = threadIdx.x & 31;
    const int h = gw & (NHEAD - 1);
    const int m = gw >> 4;
    const int b = m >> 11;
    const int s = m & (SEQ - 1);

    const float* in = Qbuf + (size_t)m * DIM + h * HD;
    float v0 = in[lane], v1 = in[lane + 32];

    float sum = v0 + v1;
#pragma unroll
    for (int o = 16; o; o >>= 1) sum += __shfl_xor_sync(0xffffffffu, sum, o);
    float mu = sum * (1.f / 64.f);
    float d0 = v0 - mu, d1 = v1 - mu;
    float vs = d0 * d0 + d1 * d1;
#pragma unroll
    for (int o = 16; o; o >>= 1) vs += __shfl_xor_sync(0xffffffffu, vs, o);
    float rstd = rsqrtf(vs * (1.f / 64.f) + 1e-5f);

    float y0 = d0 * rstd * gamma[lane]      + beta[lane];
    float y1 = d1 * rstd * gamma[lane + 32] + beta[lane + 32];

    float invf = powf(10000.f, -(float)lane * (1.f / 32.f));
    float ang  = (float)s * invf;
    float sn, cs;
    sincosf(ang, &sn, &cs);

    float* outp = Q + ((size_t)(b * NHEAD + h) * SEQ + s) * HD;
    outp[lane]      = __uint_as_float(tf32(y0 * cs - y1 * sn));
    outp[lane + 32] = __uint_as_float(tf32(y0 * sn + y1 * cs));
}

// --------- per-head LayerNorm on k + copy v (tf32-rounded outputs) ---------
__global__ void ln_kv_kernel(const float* __restrict__ KVbuf,
                             const float* __restrict__ gamma,
                             const float* __restrict__ beta,
                             float* __restrict__ K, float* __restrict__ V) {
    const int gw   = blockIdx.x * 8 + (threadIdx.x >> 5);
    const int lane = threadIdx.x & 31;
    const int h = gw & (NHEAD - 1);
    const int m = gw >> 4;
    const int b = m >> 11;
    const int sc = m & (SEQ - 1);

    const float* kin = KVbuf + (size_t)m * (2 * DIM) + h * HD;
    const float* vin = kin + DIM;

    float v0 = kin[lane], v1 = kin[lane + 32];
    float sum = v0 + v1;
#pragma unroll
    for (int o = 16; o; o >>= 1) sum += __shfl_xor_sync(0xffffffffu, sum, o);
    float mu = sum * (1.f / 64.f);
    float d0 = v0 - mu, d1 = v1 - mu;
    float vs = d0 * d0 + d1 * d1;
#pragma unroll
    for (int o = 16; o; o >>= 1) vs += __shfl_xor_sync(0xffffffffu, vs, o);
    float rstd = rsqrtf(vs * (1.f / 64.f) + 1e-5f);

    size_t ob = ((size_t)(b * NHEAD + h) * SEQ + sc) * HD;
    K[ob + lane]      = __uint_as_float(tf32(d0 * rstd * gamma[lane]      + beta[lane]));
    K[ob + lane + 32] = __uint_as_float(tf32(d1 * rstd * gamma[lane + 32] + beta[lane + 32]));
    V[ob + lane]      = __uint_as_float(tf32(vin[lane]));
    V[ob + lane + 32] = __uint_as_float(tf32(vin[lane + 32]));
}

// --------- flash attention: 128q x 64k, ldmatrix K, no cvt in mainloop -----
#define QIDX(r, col) ((r) * 64 + ((col) ^ (((r) & 7) << 2)))
#define VIDX(r, col) ((r) * 64 + ((col) ^ (((r) & 3) << 3)))
#define FSTG 8192
#define FLASH_SMEM (3*FSTG*4)

__global__ __launch_bounds__(256) void flash_tf32(
        const float* __restrict__ Q, const float* __restrict__ K,
        const float* __restrict__ V, float* __restrict__ O) {
    extern __shared__ float stage[];

    const int qt = blockIdx.x, h = blockIdx.y, b = blockIdx.z;
    const int tid  = threadIdx.x;
    const int warp = tid >> 5, lane = tid & 31;
    const int g = lane >> 2, c = lane & 3;
    const int wm = warp * 16;
    const int qbase = lane & ~3;
    const int srcA = qbase + (c >> 1);
    const int srcB = srcA + 2;
    const bool hi = (c & 1);

    // ldmatrix K-fragment addressing (4 groups of 2 ni each)
    const int mloc = lane >> 3, rw = lane & 7;
    uint32_t kb_base[4];
#pragma unroll
    for (int gi = 0; gi < 4; gi++) {
        int row = (gi * 2 + (mloc >> 1)) * 8 + rw;
        kb_base[gi] = (uint32_t)(row * 256) + ((((mloc & 1) << 4) ^ (rw << 4)));
    }

    const float* Qg = Q + ((size_t)(b * NHEAD + h) * SEQ + qt * 128) * HD;
    const float* Kg = K + (size_t)(b * NHEAD + h) * SEQ * HD;
    const float* Vg = V + (size_t)(b * NHEAD + h) * SEQ * HD;

    // ---- stage Q (128x64) through stage0 via cp.async ----
#pragma unroll
    for (int j = 0; j < 8; j++) {
        int i = tid + j * 256;
        int r = i >> 4, c4 = (i & 15) << 2;
        float* dst = (r < 64) ? &stage[QIDX(r, c4)] : &stage[4096 + QIDX(r - 64, c4)];
        cpa16(sptr(dst), Qg + (size_t)r * 64 + c4);
    }
    cpa_commit();
    asm volatile("cp.async.wait_group 0;");
    __syncthreads();

    // Q fragments pre-scaled by 1/sqrt(64) (exact exponent shift, stays tf32)
    unsigned qf[8][4];
    {
        const float* buf = (wm < 64) ? stage : stage + 4096;
        const int rb = wm & 63;
#pragma unroll
        for (int ks = 0; ks < 8; ks++) {
            int kk = ks * 8 + c;
            qf[ks][0] = __float_as_uint(0.125f * buf[QIDX(rb + g, kk)]);
            qf[ks][1] = __float_as_uint(0.125f * buf[QIDX(rb + 8 + g, kk)]);
            qf[ks][2] = __float_as_uint(0.125f * buf[QIDX(rb + g, kk + 4)]);
            qf[ks][3] = __float_as_uint(0.125f * buf[QIDX(rb + 8 + g, kk + 4)]);
        }
    }
    __syncthreads();

    auto issueKV = [&](int t) {
        float* Kb = stage + (t % 3) * FSTG;
        float* Vb = Kb + 4096;
#pragma unroll
        for (int j = 0; j < 4; j++) {
            int i = tid + j * 256;
            int r = i >> 4, c4 = (i & 15) << 2;
            cpa16(sptr(&Kb[QIDX(r, c4)]), Kg + (size_t)(t * 64 + r) * 64 + c4);
            cpa16(sptr(&Vb[VIDX(r, c4)]), Vg + (size_t)(t * 64 + r) * 64 + c4);
        }
    };

    issueKV(0); cpa_commit();
    issueKV(1); cpa_commit();

    float m0 = -1e30f, m1 = -1e30f, l0 = 0.f, l1 = 0.f;
    float o[8][4];
#pragma unroll
    for (int ni = 0; ni < 8; ni++)
#pragma unroll
        for (int t = 0; t < 4; t++) o[ni][t] = 0.f;

    const int nT = SEQ / 64;
    for (int kt = 0; kt < nT; kt++) {
        asm volatile("cp.async.wait_group 1;");
        __syncthreads();
        if (kt + 2 < nT) issueKV(kt + 2);
        cpa_commit();

        const uint32_t ksb = sptr(stage + (kt % 3) * FSTG);
        const float* Vs = stage + (kt % 3) * FSTG + 4096;

        // ---- S = Q K^T ----
        float s[8][4];
#pragma unroll
        for (int ni = 0; ni < 8; ni++)
#pragma unroll
            for (int t = 0; t < 4; t++) s[ni][t] = 0.f;
#pragma unroll
        for (int ks = 0; ks < 8; ks++) {
            unsigned kb[16];
#pragma unroll
            for (int gi = 0; gi < 4; gi++)
                ldsm4(&kb[gi * 4], ksb + (kb_base[gi] ^ (uint32_t)(ks << 5)));
#pragma unroll
            for (int ni = 0; ni < 8; ni++) mma8(s[ni], qf[ks], &kb[ni * 2]);
        }

        // ---- online softmax (Q pre-scaled; s already scaled) ----
        float rm0 = -1e30f, rm1 = -1e30f;
#pragma unroll
        for (int ni = 0; ni < 8; ni++) {
            rm0 = fmaxf(rm0, fmaxf(s[ni][0], s[ni][1]));
            rm1 = fmaxf(rm1, fmaxf(s[ni][2], s[ni][3]));
        }
        rm0 = fmaxf(rm0, __shfl_xor_sync(0xffffffffu, rm0, 1));
        rm0 = fmaxf(rm0, __shfl_xor_sync(0xffffffffu, rm0, 2));
        rm1 = fmaxf(rm1, __shfl_xor_sync(0xffffffffu, rm1, 1));
        rm1 = fmaxf(rm1, __shfl_xor_sync(0xffffffffu, rm1, 2));
        float mn0 = fmaxf(m0, rm0), mn1 = fmaxf(m1, rm1);

        float ps0 = 0.f, ps1 = 0.f;
#pragma unroll
        for (int ni = 0; ni < 8; ni++) {
            s[ni][0] = __expf(s[ni][0] - mn0); s[ni][1] = __expf(s[ni][1] - mn0);
            s[ni][2] = __expf(s[ni][2] - mn1); s[ni][3] = __expf(s[ni][3] - mn1);
            ps0 += s[ni][0] + s[ni][1];
            ps1 += s[ni][2] + s[ni][3];
        }
        ps0 += __shfl_xor_sync(0xffffffffu, ps0, 1);
        ps0 += __shfl_xor_sync(0xffffffffu, ps0, 2);
        ps1 += __shfl_xor_sync(0xffffffffu, ps1, 1);
        ps1 += __shfl_xor_sync(0xffffffffu, ps1, 2);

        float al0 = __expf(m0 - mn0), al1 = __expf(m1 - mn1);
        m0 = mn0; m1 = mn1;
        l0 = l0 * al0 + ps0;
        l1 = l1 * al1 + ps1;
#pragma unroll
        for (int ni = 0; ni < 8; ni++) {
            o[ni][0] *= al0; o[ni][1] *= al0;
            o[ni][2] *= al1; o[ni][3] *= al1;
        }

        // ---- O += P @ V ----
#pragma unroll
        for (int ks = 0; ks < 8; ks++) {
            float e0 = __shfl_sync(0xffffffffu, s[ks][0], srcA);
            float e1 = __shfl_sync(0xffffffffu, s[ks][1], srcA);
            float f0 = __shfl_sync(0xffffffffu, s[ks][0], srcB);
            float f1 = __shfl_sync(0xffffffffu, s[ks][1], srcB);
            float g0 = __shfl_sync(0xffffffffu, s[ks][2], srcA);
            float g1 = __shfl_sync(0xffffffffu, s[ks][3], srcA);
            float h0 = __shfl_sync(0xffffffffu, s[ks][2], srcB);
            float h1 = __shfl_sync(0xffffffffu, s[ks][3], srcB);
            unsigned pa[4];
            pa[0] = tf32(hi ? e1 : e0);
            pa[1] = tf32(hi ? g1 : g0);
            pa[2] = tf32(hi ? f1 : f0);
            pa[3] = tf32(hi ? h1 : h0);

            int kk = ks * 8 + c;
            unsigned vb[8][2];
#pragma unroll
            for (int ni = 0; ni < 8; ni++) {
                int dc = ni * 8 + g;
                vb[ni][0] = __float_as_uint(Vs[VIDX(kk, dc)]);
                vb[ni][1] = __float_as_uint(Vs[VIDX(kk + 4, dc)]);
            }
#pragma unroll
            for (int ni = 0; ni < 8; ni++) mma8(o[ni], pa, vb[ni]);
        }
    }

    // ---- epilogue -> O [B, S, H*Hd], tf32-rounded for proj GEMM ----
    float inv0 = 1.f / l0, inv1 = 1.f / l1;
    int row0 = qt * 128 + wm + g;
#pragma unroll
    for (int ni = 0; ni < 8; ni++) {
        int col = h * HD + ni * 8 + 2 * c;
        float* p0 = O + ((size_t)b * SEQ + row0) * DIM + col;
        float* p1 = O + ((size_t)b * SEQ + row0 + 8) * DIM + col;
        p0[0] = __uint_as_float(tf32(o[ni][0] * inv0));
        p0[1] = __uint_as_float(tf32(o[ni][1] * inv0));
        p1[0] = __uint_as_float(tf32(o[ni][2] * inv1));
        p1[1] = __uint_as_float(tf32(o[ni][3] * inv1));
    }
}

// ---------------------------------------------------------------------------
extern "C" void kernel_launch(void* const* d_in, const int* in_sizes, int n_in,
                              void* d_out, int out_size) {
    const float* x        = (const float*)d_in[0];
    const float* context  = (const float*)d_in[1];
    const float* q_w      = (const float*)d_in[2];
    const float* kv_w     = (const float*)d_in[3];
    const float* qn_scale = (const float*)d_in[4];
    const float* qn_bias  = (const float*)d_in[5];
    const float* kn_scale = (const float*)d_in[6];
    const float* kn_bias  = (const float*)d_in[7];
    const float* proj_w   = (const float*)d_in[8];
    const float* proj_b   = (const float*)d_in[9];
    float* out = (float*)d_out;

    float *Qbuf, *KVbuf, *Q, *K, *V, *O, *xc, *cc, *qwc, *kvwc, *pwc;
    cudaGetSymbolAddress((void**)&Qbuf,  g_Qbuf);
    cudaGetSymbolAddress((void**)&KVbuf, g_KVbuf);
    cudaGetSymbolAddress((void**)&Q,     g_Q);
    cudaGetSymbolAddress((void**)&K,     g_K);
    cudaGetSymbolAddress((void**)&V,     g_V);
    cudaGetSymbolAddress((void**)&O,     g_O);
    cudaGetSymbolAddress((void**)&xc,    g_xc);
    cudaGetSymbolAddress((void**)&cc,    g_cc);
    cudaGetSymbolAddress((void**)&qwc,   g_qwc);
    cudaGetSymbolAddress((void**)&kvwc,  g_kvwc);
    cudaGetSymbolAddress((void**)&pwc,   g_pwc);

    cudaFuncSetAttribute(gemm_tf32,
        cudaFuncAttributeMaxDynamicSharedMemorySize, GEMM_SMEM);
    cudaFuncSetAttribute(flash_tf32,
        cudaFuncAttributeMaxDynamicSharedMemorySize, FLASH_SMEM);

    // tf32-round all external GEMM operands once
    {
        const int T = 256;
        int n;
        n = ROWS * DIM / 4;
        round_tf32_kernel<<<(n + T - 1) / T, T>>>((const float4*)x, (float4*)xc, n);
        round_tf32_kernel<<<(n + T - 1) / T, T>>>((const float4*)context, (float4*)cc, n);
        n = DIM * DIM / 4;
        round_tf32_kernel<<<(n + T - 1) / T, T>>>((const float4*)q_w, (float4*)qwc, n);
        round_tf32_kernel<<<(n + T - 1) / T, T>>>((const float4*)proj_w, (float4*)pwc, n);
        n = DIM * 2 * DIM / 4;
        round_tf32_kernel<<<(n + T - 1) / T, T>>>((const float4*)kv_w, (float4*)kvwc, n);
    }

    gemm_tf32<<<dim3(DIM / 128, ROWS / 128), 256, GEMM_SMEM>>>(
        xc, qwc, nullptr, Qbuf, ROWS, DIM, DIM);
    gemm_tf32<<<dim3(2 * DIM / 128, ROWS / 128), 256, GEMM_SMEM>>>(
        cc, kvwc, nullptr, KVbuf, ROWS, 2 * DIM, DIM);
    ln_rope_q_kernel<<<(ROWS * NHEAD) / 8, 256>>>(Qbuf, qn_scale, qn_bias, Q);
    ln_kv_kernel<<<(ROWS * NHEAD) / 8, 256>>>(KVbuf, kn_scale, kn_bias, K, V);
    flash_tf32<<<dim3(SEQ / 128, NHEAD, BATCH), 256, FLASH_SMEM>>>(Q, K, V, O);
    gemm_tf32<<<dim3(DIM / 128, ROWS / 128), 256, GEMM_SMEM>>>(
        O, pwc, proj_b, out, ROWS, DIM, DIM);
}

// round 6
// speedup vs baseline: 3.5383x; 1.0314x over previous
#include <cuda_runtime.h>
#include <math.h>
#include <stdint.h>

#define BATCH 4
#define SEQ   2048
#define DIM   1024
#define NHEAD 16
#define HD    64
#define ROWS  (BATCH*SEQ)   // 8192

// ---------------- scratch (device globals; no allocation allowed) ----------
__device__ float g_Qbuf[(size_t)ROWS * DIM];
__device__ float g_KVbuf[(size_t)ROWS * 2 * DIM];
__device__ float g_Q[(size_t)ROWS * DIM];           // [B,H,S,Hd] tf32-rounded
__device__ float g_K[(size_t)ROWS * DIM];           // [B,H,Sc,Hd] tf32-rounded
__device__ float g_V[(size_t)ROWS * DIM];           // [B,H,Hd,Sc] TRANSPOSED, tf32
__device__ float g_O[(size_t)ROWS * DIM];           // [B,S,H*Hd] tf32-rounded
__device__ float g_xc[(size_t)ROWS * DIM];
__device__ float g_cc[(size_t)ROWS * DIM];
__device__ float g_qwc[(size_t)DIM * DIM];
__device__ float g_kvwc[(size_t)DIM * 2 * DIM];
__device__ float g_pwc[(size_t)DIM * DIM];

// ---------------- helpers ---------------------------------------------------
__device__ __forceinline__ unsigned tf32(float x) {
    unsigned u;
    asm("cvt.rna.tf32.f32 %0, %1;" : "=r"(u) : "f"(x));
    return u;
}

__device__ __forceinline__ void mma8(float* d, const unsigned* a, const unsigned* b) {
    asm volatile(
        "mma.sync.aligned.m16n8k8.row.col.f32.tf32.tf32.f32 "
        "{%0,%1,%2,%3}, {%4,%5,%6,%7}, {%8,%9}, {%0,%1,%2,%3};"
        : "+f"(d[0]), "+f"(d[1]), "+f"(d[2]), "+f"(d[3])
        : "r"(a[0]), "r"(a[1]), "r"(a[2]), "r"(a[3]), "r"(b[0]), "r"(b[1]));
}

__device__ __forceinline__ void mma8b(float* d, const unsigned* a,
                                      unsigned b0, unsigned b1) {
    asm volatile(
        "mma.sync.aligned.m16n8k8.row.col.f32.tf32.tf32.f32 "
        "{%0,%1,%2,%3}, {%4,%5,%6,%7}, {%8,%9}, {%0,%1,%2,%3};"
        : "+f"(d[0]), "+f"(d[1]), "+f"(d[2]), "+f"(d[3])
        : "r"(a[0]), "r"(a[1]), "r"(a[2]), "r"(a[3]), "r"(b0), "r"(b1));
}

__device__ __forceinline__ void ldsm4(unsigned* r, uint32_t addr) {
    asm volatile("ldmatrix.sync.aligned.m8n8.x4.shared.b16 {%0,%1,%2,%3}, [%4];"
        : "=r"(r[0]), "=r"(r[1]), "=r"(r[2]), "=r"(r[3]) : "r"(addr));
}

__device__ __forceinline__ void cpa16(uint32_t s, const void* g) {
    asm volatile("cp.async.cg.shared.global [%0], [%1], 16;" :: "r"(s), "l"(g));
}
__device__ __forceinline__ void cpa_commit() {
    asm volatile("cp.async.commit_group;");
}
__device__ __forceinline__ uint32_t sptr(const void* p) {
    return (uint32_t)__cvta_generic_to_shared(p);
}

// ---------------- fused tf32 rounding pass (all operands in one kernel) -----
#define RN1 2097152            // x            (8192*1024/4)
#define RN2 4194304            // + context
#define RN3 4456448            // + q_w        (262144)
#define RN4 4718592            // + proj_w
#define RN5 5242880            // + kv_w       (524288)
__global__ void round_all_kernel(
        const float4* __restrict__ x,  const float4* __restrict__ cc,
        const float4* __restrict__ qw, const float4* __restrict__ pw,
        const float4* __restrict__ kvw,
        float4* __restrict__ xo,  float4* __restrict__ cco,
        float4* __restrict__ qwo, float4* __restrict__ pwo,
        float4* __restrict__ kvwo) {
    int i = blockIdx.x * blockDim.x + threadIdx.x;
    const float4* src; float4* dst; int off;
    if (i < RN1)      { src = x;   dst = xo;   off = i; }
    else if (i < RN2) { src = cc;  dst = cco;  off = i - RN1; }
    else if (i < RN3) { src = qw;  dst = qwo;  off = i - RN2; }
    else if (i < RN4) { src = pw;  dst = pwo;  off = i - RN3; }
    else              { src = kvw; dst = kvwo; off = i - RN4; }
    float4 v = src[off];
    v.x = __uint_as_float(tf32(v.x));
    v.y = __uint_as_float(tf32(v.y));
    v.z = __uint_as_float(tf32(v.z));
    v.w = __uint_as_float(tf32(v.w));
    dst[off] = v;
}

// ---------------- TF32 GEMM, 3-stage cp.async + ldmatrix -------------------
#define ASTR 20
#define BSTR 136
#define GA_SZ (128*ASTR)
#define GB_SZ (16*BSTR)
#define GEMM_SMEM (3*(GA_SZ+GB_SZ)*4)

__global__ __launch_bounds__(256) void gemm_tf32(
        const float* __restrict__ A, const float* __restrict__ B,
        const float* __restrict__ bias, float* __restrict__ C,
        int M, int N, int K) {
    extern __shared__ float sm[];
    float* Abuf = sm;
    float* Bbuf = sm + 3 * GA_SZ;

    const int tid  = threadIdx.x;
    const int warp = tid >> 5, lane = tid & 31;
    const int g = lane >> 2, c = lane & 3;
    const int wm = (warp >> 2) * 64, wn = (warp & 3) * 32;
    const int bm = blockIdx.y * 128, bn = blockIdx.x * 128;

    const int ar  = tid >> 2;
    const int ac4 = (tid & 3) << 2;
    const int bk  = tid >> 5;
    const int bc4 = (tid & 31) << 2;

    const float* Ap = A + (size_t)(bm + ar) * K + ac4;
    const float* Bp = B + (size_t)bk * N + bn + bc4;

    const uint32_t aB0 = sptr(&Abuf[ar * ASTR + ac4]);
    const uint32_t aB1 = sptr(&Abuf[(ar + 64) * ASTR + ac4]);
    const uint32_t bB0 = sptr(&Bbuf[bk * BSTR + bc4]);
    const uint32_t bB1 = sptr(&Bbuf[(bk + 8) * BSTR + bc4]);

    const int mloc = lane >> 3, rw = lane & 7;
    const uint32_t a_off =
        (uint32_t)((wm + ((mloc & 1) << 3) + rw) * ASTR + ((mloc >> 1) << 2)) * 4;
    const uint32_t abase0 = sptr(Abuf) + a_off;

    float acc[4][4][4];
#pragma unroll
    for (int mi = 0; mi < 4; mi++)
#pragma unroll
        for (int ni = 0; ni < 4; ni++)
#pragma unroll
            for (int t = 0; t < 4; t++) acc[mi][ni][t] = 0.f;

    const int nT = K >> 4;

    auto issue = [&](int t) {
        const int st = t % 3;
        const int k0 = t << 4;
        cpa16(aB0 + st * GA_SZ * 4, Ap + k0);
        cpa16(aB1 + st * GA_SZ * 4, Ap + (size_t)64 * K + k0);
        cpa16(bB0 + st * GB_SZ * 4, Bp + (size_t)k0 * N);
        cpa16(bB1 + st * GB_SZ * 4, Bp + (size_t)(k0 + 8) * N);
    };

    issue(0); cpa_commit();
    issue(1); cpa_commit();

    for (int t = 0; t < nT; t++) {
        asm volatile("cp.async.wait_group 1;");
        __syncthreads();
        if (t + 2 < nT) issue(t + 2);
        cpa_commit();

        const int st = t % 3;
        const uint32_t ab = abase0 + st * GA_SZ * 4;
        const float* Bb = Bbuf + st * GB_SZ;
#pragma unroll
        for (int ks = 0; ks < 2; ks++) {
            unsigned af[4][4], bf[4][2];
            const int kk = ks * 8 + c;
#pragma unroll
            for (int mi = 0; mi < 4; mi++)
                ldsm4(af[mi], ab + mi * (16 * ASTR * 4) + ks * 32);
#pragma unroll
            for (int ni = 0; ni < 4; ni++) {
                int col = wn + ni * 8 + g;
                bf[ni][0] = __float_as_uint(Bb[kk * BSTR + col]);
                bf[ni][1] = __float_as_uint(Bb[(kk + 4) * BSTR + col]);
            }
#pragma unroll
            for (int mi = 0; mi < 4; mi++)
#pragma unroll
                for (int ni = 0; ni < 4; ni++)
                    mma8(acc[mi][ni], af[mi], bf[ni]);
        }
    }

#pragma unroll
    for (int mi = 0; mi < 4; mi++) {
        int row = bm + wm + mi * 16 + g;
#pragma unroll
        for (int ni = 0; ni < 4; ni++) {
            int col = bn + wn + ni * 8 + 2 * c;
            float bv0 = bias ? bias[col] : 0.f;
            float bv1 = bias ? bias[col + 1] : 0.f;
            float* p0 = C + (size_t)row * N + col;
            float* p1 = C + (size_t)(row + 8) * N + col;
            p0[0] = acc[mi][ni][0] + bv0; p0[1] = acc[mi][ni][1] + bv1;
            p1[0] = acc[mi][ni][2] + bv0; p1[1] = acc[mi][ni][3] + bv1;
        }
    }
}

// --------- per-head LayerNorm + RoPE on q (tf32-rounded output) ------------
__global__ void ln_rope_q_kernel(const float* __restrict__ Qbuf,
                                 const float* __restrict__ gamma,
                                 const float* __restrict__ beta,
                                 float* __restrict__ Q) {
    const int gw   = blockIdx.x * 8 + (threadIdx.x >> 5);
    const int lane = threadIdx.x & 31;
    const int h = gw & (NHEAD - 1);
    const int m = gw >> 4;
    const int b = m >> 11;
    const int s = m & (SEQ - 1);

    const float* in = Qbuf + (size_t)m * DIM + h * HD;
    float v0 = in[lane], v1 = in[lane + 32];

    float sum = v0 + v1;
#pragma unroll
    for (int o = 16; o; o >>= 1) sum += __shfl_xor_sync(0xffffffffu, sum, o);
    float mu = sum * (1.f / 64.f);
    float d0 = v0 - mu, d1 = v1 - mu;
    float vs = d0 * d0 + d1 * d1;
#pragma unroll
    for (int o = 16; o; o >>= 1) vs += __shfl_xor_sync(0xffffffffu, vs, o);
    float rstd = rsqrtf(vs * (1.f / 64.f) + 1e-5f);

    float y0 = d0 * rstd * gamma[lane]      + beta[lane];
    float y1 = d1 * rstd * gamma[lane + 32] + beta[lane + 32];

    float invf = powf(10000.f, -(float)lane * (1.f / 32.f));
    float ang  = (float)s * invf;
    float sn, cs;
    sincosf(ang, &sn, &cs);

    float* outp = Q + ((size_t)(b * NHEAD + h) * SEQ + s) * HD;
    outp[lane]      = __uint_as_float(tf32(y0 * cs - y1 * sn));
    outp[lane + 32] = __uint_as_float(tf32(y0 * sn + y1 * cs));
}

// --------- LN on k + V global transpose: Vt[b,h,d,key] ---------------------
// One block per (64-key tile, h, b). 8 warps x 8 keys. V transposed via smem.
__global__ __launch_bounds__(256) void ln_kv_kernel(
        const float* __restrict__ KVbuf,
        const float* __restrict__ gamma, const float* __restrict__ beta,
        float* __restrict__ K, float* __restrict__ Vt) {
    __shared__ float Vs[64 * 65];
    const int b = blockIdx.z, h = blockIdx.y, kb = blockIdx.x * 64;
    const int tid = threadIdx.x, warp = tid >> 5, lane = tid & 31;

    const float ga0 = gamma[lane], ga1 = gamma[lane + 32];
    const float be0 = beta[lane],  be1 = beta[lane + 32];

#pragma unroll
    for (int j = 0; j < 8; j++) {
        const int kl  = warp * 8 + j;          // local key 0..63
        const int key = kb + kl;
        const float* kin = KVbuf + ((size_t)b * SEQ + key) * (2 * DIM) + h * HD;
        const float* vin = kin + DIM;

        float v0 = kin[lane], v1 = kin[lane + 32];
        float sum = v0 + v1;
#pragma unroll
        for (int o = 16; o; o >>= 1) sum += __shfl_xor_sync(0xffffffffu, sum, o);
        float mu = sum * (1.f / 64.f);
        float d0 = v0 - mu, d1 = v1 - mu;
        float vs = d0 * d0 + d1 * d1;
#pragma unroll
        for (int o = 16; o; o >>= 1) vs += __shfl_xor_sync(0xffffffffu, vs, o);
        float rstd = rsqrtf(vs * (1.f / 64.f) + 1e-5f);

        size_t ob = ((size_t)(b * NHEAD + h) * SEQ + key) * HD;
        K[ob + lane]      = __uint_as_float(tf32(d0 * rstd * ga0 + be0));
        K[ob + lane + 32] = __uint_as_float(tf32(d1 * rstd * ga1 + be1));
        Vs[lane * 65 + kl]        = __uint_as_float(tf32(vin[lane]));
        Vs[(lane + 32) * 65 + kl] = __uint_as_float(tf32(vin[lane + 32]));
    }
    __syncthreads();

    // write Vt rows (d-major), coalesced 256B per row segment
    const int d = tid >> 2, c0 = (tid & 3) * 16;
    float* dst = Vt + ((size_t)((b * NHEAD + h) * HD + d)) * SEQ + kb + c0;
#pragma unroll
    for (int e = 0; e < 16; e += 4) {
        const float* s = &Vs[d * 65 + c0 + e];
        *(float4*)(dst + e) = make_float4(s[0], s[1], s[2], s[3]);
    }
}

// --------- flash attention: 128q x 64k, ldsm K + ldsm V(transposed) --------
#define QIDX(r, col) ((r) * 64 + ((col) ^ (((r) & 7) << 2)))
// transposed V tile: rows = d, 16B-granule swizzle gran ^= (d&7)
#define VTIDX(d, key) ((d) * 64 + (((((key) >> 2) ^ ((d) & 7)) << 2) | ((key) & 3)))
#define FSTG 8192
#define FLASH_SMEM (3*FSTG*4)

__global__ __launch_bounds__(256) void flash_tf32(
        const float* __restrict__ Q, const float* __restrict__ K,
        const float* __restrict__ Vt, float* __restrict__ O) {
    extern __shared__ float stage[];

    const int qt = blockIdx.x, h = blockIdx.y, b = blockIdx.z;
    const int tid  = threadIdx.x;
    const int warp = tid >> 5, lane = tid & 31;
    const int g = lane >> 2, c = lane & 3;
    const int wm = warp * 16;
    const int qbase = lane & ~3;
    const int srcA = qbase + (c >> 1);
    const int srcB = srcA + 2;
    const bool hi = (c & 1);

    // K ldsm addressing (as in R5, verified)
    const int mloc = lane >> 3, rw = lane & 7;
    uint32_t kb_base[4];
#pragma unroll
    for (int gi = 0; gi < 4; gi++) {
        int row = (gi * 2 + (mloc >> 1)) * 8 + rw;
        kb_base[gi] = (uint32_t)(row * 256) + ((((mloc & 1) << 4) ^ (rw << 4)));
    }
    // V ldsm addressing: addr(gi,ks) = vtb + vrow[gi] + ((ks<<5) ^ vlc)
    const int Lr = lane & 15, h4 = lane >> 4, mmv = lane & 7;
    uint32_t vrow[4];
#pragma unroll
    for (int gi = 0; gi < 4; gi++) vrow[gi] = (uint32_t)((16 * gi + Lr) * 256);
    const uint32_t vlc = ((uint32_t)h4 << 4) ^ ((uint32_t)mmv << 4);

    const float* Qg  = Q  + ((size_t)(b * NHEAD + h) * SEQ + qt * 128) * HD;
    const float* Kg  = K  + (size_t)(b * NHEAD + h) * SEQ * HD;
    const float* Vtg = Vt + (size_t)(b * NHEAD + h) * HD * SEQ;

    // ---- stage Q (128x64) through stage0 via cp.async ----
#pragma unroll
    for (int j = 0; j < 8; j++) {
        int i = tid + j * 256;
        int r = i >> 4, c4 = (i & 15) << 2;
        float* dst = (r < 64) ? &stage[QIDX(r, c4)] : &stage[4096 + QIDX(r - 64, c4)];
        cpa16(sptr(dst), Qg + (size_t)r * 64 + c4);
    }
    cpa_commit();
    asm volatile("cp.async.wait_group 0;");
    __syncthreads();

    unsigned qf[8][4];
    {
        const float* buf = (wm < 64) ? stage : stage + 4096;
        const int rb = wm & 63;
#pragma unroll
        for (int ks = 0; ks < 8; ks++) {
            int kk = ks * 8 + c;
            qf[ks][0] = __float_as_uint(0.125f * buf[QIDX(rb + g, kk)]);
            qf[ks][1] = __float_as_uint(0.125f * buf[QIDX(rb + 8 + g, kk)]);
            qf[ks][2] = __float_as_uint(0.125f * buf[QIDX(rb + g, kk + 4)]);
            qf[ks][3] = __float_as_uint(0.125f * buf[QIDX(rb + 8 + g, kk + 4)]);
        }
    }
    __syncthreads();

    auto issueKV = [&](int t) {
        float* Kb = stage + (t % 3) * FSTG;
        float* Vb = Kb + 4096;
#pragma unroll
        for (int j = 0; j < 4; j++) {
            int i = tid + j * 256;
            int r = i >> 4, c4 = (i & 15) << 2;
            cpa16(sptr(&Kb[QIDX(r, c4)]), Kg + (size_t)(t * 64 + r) * 64 + c4);
            // Vt tile: row r = d, cols = keys t*64+c4..
            cpa16(sptr(&Vb[VTIDX(r, c4)]), Vtg + (size_t)r * SEQ + t * 64 + c4);
        }
    };

    issueKV(0); cpa_commit();
    issueKV(1); cpa_commit();

    float m0 = -1e30f, m1 = -1e30f, l0 = 0.f, l1 = 0.f;
    float o[8][4];
#pragma unroll
    for (int ni = 0; ni < 8; ni++)
#pragma unroll
        for (int t = 0; t < 4; t++) o[ni][t] = 0.f;

    const int nT = SEQ / 64;
    for (int kt = 0; kt < nT; kt++) {
        asm volatile("cp.async.wait_group 1;");
        __syncthreads();
        if (kt + 2 < nT) issueKV(kt + 2);
        cpa_commit();

        const uint32_t ksb = sptr(stage + (kt % 3) * FSTG);
        const uint32_t vtb = ksb + 4096 * 4;

        // ---- S = Q K^T ----
        float s[8][4];
#pragma unroll
        for (int ni = 0; ni < 8; ni++)
#pragma unroll
            for (int t = 0; t < 4; t++) s[ni][t] = 0.f;
#pragma unroll
        for (int ks = 0; ks < 8; ks++) {
            unsigned kbf[16];
#pragma unroll
            for (int gi = 0; gi < 4; gi++)
                ldsm4(&kbf[gi * 4], ksb + (kb_base[gi] ^ (uint32_t)(ks << 5)));
#pragma unroll
            for (int ni = 0; ni < 8; ni++) mma8(s[ni], qf[ks], &kbf[ni * 2]);
        }

        // ---- online softmax ----
        float rm0 = -1e30f, rm1 = -1e30f;
#pragma unroll
        for (int ni = 0; ni < 8; ni++) {
            rm0 = fmaxf(rm0, fmaxf(s[ni][0], s[ni][1]));
            rm1 = fmaxf(rm1, fmaxf(s[ni][2], s[ni][3]));
        }
        rm0 = fmaxf(rm0, __shfl_xor_sync(0xffffffffu, rm0, 1));
        rm0 = fmaxf(rm0, __shfl_xor_sync(0xffffffffu, rm0, 2));
        rm1 = fmaxf(rm1, __shfl_xor_sync(0xffffffffu, rm1, 1));
        rm1 = fmaxf(rm1, __shfl_xor_sync(0xffffffffu, rm1, 2));
        float mn0 = fmaxf(m0, rm0), mn1 = fmaxf(m1, rm1);

        float ps0 = 0.f, ps1 = 0.f;
#pragma unroll
        for (int ni = 0; ni < 8; ni++) {
            s[ni][0] = __expf(s[ni][0] - mn0); s[ni][1] = __expf(s[ni][1] - mn0);
            s[ni][2] = __expf(s[ni][2] - mn1); s[ni][3] = __expf(s[ni][3] - mn1);
            ps0 += s[ni][0] + s[ni][1];
            ps1 += s[ni][2] + s[ni][3];
        }
        ps0 += __shfl_xor_sync(0xffffffffu, ps0, 1);
        ps0 += __shfl_xor_sync(0xffffffffu, ps0, 2);
        ps1 += __shfl_xor_sync(0xffffffffu, ps1, 1);
        ps1 += __shfl_xor_sync(0xffffffffu, ps1, 2);

        float al0 = __expf(m0 - mn0), al1 = __expf(m1 - mn1);
        m0 = mn0; m1 = mn1;
        l0 = l0 * al0 + ps0;
        l1 = l1 * al1 + ps1;
#pragma unroll
        for (int ni = 0; ni < 8; ni++) {
            o[ni][0] *= al0; o[ni][1] *= al0;
            o[ni][2] *= al1; o[ni][3] *= al1;
        }

        // ---- O += P @ V : P via quad shuffles, V via ldsm on transposed tile
#pragma unroll
        for (int ks = 0; ks < 8; ks++) {
            float e0 = __shfl_sync(0xffffffffu, s[ks][0], srcA);
            float e1 = __shfl_sync(0xffffffffu, s[ks][1], srcA);
            float f0 = __shfl_sync(0xffffffffu, s[ks][0], srcB);
            float f1 = __shfl_sync(0xffffffffu, s[ks][1], srcB);
            float g0 = __shfl_sync(0xffffffffu, s[ks][2], srcA);
            float g1 = __shfl_sync(0xffffffffu, s[ks][3], srcA);
            float h0 = __shfl_sync(0xffffffffu, s[ks][2], srcB);
            float h1 = __shfl_sync(0xffffffffu, s[ks][3], srcB);
            unsigned pa[4];
            pa[0] = tf32(hi ? e1 : e0);
            pa[1] = tf32(hi ? g1 : g0);
            pa[2] = tf32(hi ? f1 : f0);
            pa[3] = tf32(hi ? h1 : h0);

            const uint32_t xo = ((uint32_t)ks << 5) ^ vlc;
#pragma unroll
            for (int gi = 0; gi < 4; gi++) {
                unsigned vv[4];
                ldsm4(vv, vtb + vrow[gi] + xo);
                mma8b(o[2 * gi],     pa, vv[0], vv[2]);
                mma8b(o[2 * gi + 1], pa, vv[1], vv[3]);
            }
        }
    }

    // ---- epilogue -> O [B, S, H*Hd], tf32-rounded for proj GEMM ----
    float inv0 = 1.f / l0, inv1 = 1.f / l1;
    int row0 = qt * 128 + wm + g;
#pragma unroll
    for (int ni = 0; ni < 8; ni++) {
        int col = h * HD + ni * 8 + 2 * c;
        float* p0 = O + ((size_t)b * SEQ + row0) * DIM + col;
        float* p1 = O + ((size_t)b * SEQ + row0 + 8) * DIM + col;
        p0[0] = __uint_as_float(tf32(o[ni][0] * inv0));
        p0[1] = __uint_as_float(tf32(o[ni][1] * inv0));
        p1[0] = __uint_as_float(tf32(o[ni][2] * inv1));
        p1[1] = __uint_as_float(tf32(o[ni][3] * inv1));
    }
}

// ---------------------------------------------------------------------------
extern "C" void kernel_launch(void* const* d_in, const int* in_sizes, int n_in,
                              void* d_out, int out_size) {
    const float* x        = (const float*)d_in[0];
    const float* context  = (const float*)d_in[1];
    const float* q_w      = (const float*)d_in[2];
    const float* kv_w     = (const float*)d_in[3];
    const float* qn_scale = (const float*)d_in[4];
    const float* qn_bias  = (const float*)d_in[5];
    const float* kn_scale = (const float*)d_in[6];
    const float* kn_bias  = (const float*)d_in[7];
    const float* proj_w   = (const float*)d_in[8];
    const float* proj_b   = (const float*)d_in[9];
    float* out = (float*)d_out;

    float *Qbuf, *KVbuf, *Q, *K, *V, *O, *xc, *cc, *qwc, *kvwc, *pwc;
    cudaGetSymbolAddress((void**)&Qbuf,  g_Qbuf);
    cudaGetSymbolAddress((void**)&KVbuf, g_KVbuf);
    cudaGetSymbolAddress((void**)&Q,     g_Q);
    cudaGetSymbolAddress((void**)&K,     g_K);
    cudaGetSymbolAddress((void**)&V,     g_V);
    cudaGetSymbolAddress((void**)&O,     g_O);
    cudaGetSymbolAddress((void**)&xc,    g_xc);
    cudaGetSymbolAddress((void**)&cc,    g_cc);
    cudaGetSymbolAddress((void**)&qwc,   g_qwc);
    cudaGetSymbolAddress((void**)&kvwc,  g_kvwc);
    cudaGetSymbolAddress((void**)&pwc,   g_pwc);

    cudaFuncSetAttribute(gemm_tf32,
        cudaFuncAttributeMaxDynamicSharedMemorySize, GEMM_SMEM);
    cudaFuncSetAttribute(flash_tf32,
        cudaFuncAttributeMaxDynamicSharedMemorySize, FLASH_SMEM);

    // L1: one fused rounding pass for all GEMM operands
    round_all_kernel<<<RN5 / 256, 256>>>(
        (const float4*)x, (const float4*)context, (const float4*)q_w,
        (const float4*)proj_w, (const float4*)kv_w,
        (float4*)xc, (float4*)cc, (float4*)qwc, (float4*)pwc, (float4*)kvwc);
    // L2: q = x @ q_w
    gemm_tf32<<<dim3(DIM / 128, ROWS / 128), 256, GEMM_SMEM>>>(
        xc, qwc, nullptr, Qbuf, ROWS, DIM, DIM);
    // L3: LN+RoPE on q
    ln_rope_q_kernel<<<(ROWS * NHEAD) / 8, 256>>>(Qbuf, qn_scale, qn_bias, Q);
    // L4: kv = context @ kv_w   (profiled launch slot)
    gemm_tf32<<<dim3(2 * DIM / 128, ROWS / 128), 256, GEMM_SMEM>>>(
        cc, kvwc, nullptr, KVbuf, ROWS, 2 * DIM, DIM);
    // L5: LN on k + V transpose
    ln_kv_kernel<<<dim3(SEQ / 64, NHEAD, BATCH), 256>>>(KVbuf, kn_scale, kn_bias, K, V);
    // L6: attention
    flash_tf32<<<dim3(SEQ / 128, NHEAD, BATCH), 256, FLASH_SMEM>>>(Q, K, V, O);
    // L7: out = O @ proj_w + proj_b
    gemm_tf32<<<dim3(DIM / 128, ROWS / 128), 256, GEMM_SMEM>>>(
        O, pwc, proj_b, out, ROWS, DIM, DIM);
}

// round 7
// speedup vs baseline: 3.6737x; 1.0383x over previous
#include <cuda_runtime.h>
#include <math.h>
#include <stdint.h>

#define BATCH 4
#define SEQ   2048
#define DIM   1024
#define NHEAD 16
#define HD    64
#define ROWS  (BATCH*SEQ)   // 8192

// ---------------- scratch (device globals; no allocation allowed) ----------
__device__ float g_Qbuf[(size_t)ROWS * DIM];
__device__ float g_KVbuf[(size_t)ROWS * 2 * DIM];
__device__ float g_Q[(size_t)ROWS * DIM];           // [B,H,S,Hd] tf32
__device__ float g_K[(size_t)ROWS * DIM];           // [B,H,Sc,Hd] tf32
__device__ float g_V[(size_t)ROWS * DIM];           // [B,H,Hd,Sc] transposed tf32
__device__ float g_O[(size_t)ROWS * DIM];           // [B,S,H*Hd] tf32
__device__ float g_xc[(size_t)ROWS * DIM];          // tf32 x
__device__ float g_cc[(size_t)ROWS * DIM];          // tf32 context
__device__ float g_qwt[(size_t)DIM * DIM];          // q_w^T   [N][K] tf32
__device__ float g_kvwt[(size_t)2 * DIM * DIM];     // kv_w^T  [2N][K] tf32
__device__ float g_pwt[(size_t)DIM * DIM];          // proj_w^T tf32

// ---------------- helpers ---------------------------------------------------
__device__ __forceinline__ unsigned tf32(float x) {
    unsigned u;
    asm("cvt.rna.tf32.f32 %0, %1;" : "=r"(u) : "f"(x));
    return u;
}
__device__ __forceinline__ float tf32f(float x) { return __uint_as_float(tf32(x)); }

__device__ __forceinline__ void mma8(float* d, const unsigned* a, const unsigned* b) {
    asm volatile(
        "mma.sync.aligned.m16n8k8.row.col.f32.tf32.tf32.f32 "
        "{%0,%1,%2,%3}, {%4,%5,%6,%7}, {%8,%9}, {%0,%1,%2,%3};"
        : "+f"(d[0]), "+f"(d[1]), "+f"(d[2]), "+f"(d[3])
        : "r"(a[0]), "r"(a[1]), "r"(a[2]), "r"(a[3]), "r"(b[0]), "r"(b[1]));
}
__device__ __forceinline__ void mma8b(float* d, const unsigned* a,
                                      unsigned b0, unsigned b1) {
    asm volatile(
        "mma.sync.aligned.m16n8k8.row.col.f32.tf32.tf32.f32 "
        "{%0,%1,%2,%3}, {%4,%5,%6,%7}, {%8,%9}, {%0,%1,%2,%3};"
        : "+f"(d[0]), "+f"(d[1]), "+f"(d[2]), "+f"(d[3])
        : "r"(a[0]), "r"(a[1]), "r"(a[2]), "r"(a[3]), "r"(b0), "r"(b1));
}
__device__ __forceinline__ void ldsm4(unsigned* r, uint32_t addr) {
    asm volatile("ldmatrix.sync.aligned.m8n8.x4.shared.b16 {%0,%1,%2,%3}, [%4];"
        : "=r"(r[0]), "=r"(r[1]), "=r"(r[2]), "=r"(r[3]) : "r"(addr));
}
__device__ __forceinline__ void cpa16(uint32_t s, const void* g) {
    asm volatile("cp.async.cg.shared.global [%0], [%1], 16;" :: "r"(s), "l"(g));
}
__device__ __forceinline__ void cpa_commit() {
    asm volatile("cp.async.commit_group;");
}
__device__ __forceinline__ uint32_t sptr(const void* p) {
    return (uint32_t)__cvta_generic_to_shared(p);
}

// ---------------- prep: round x/context + transpose-round 3 weights --------
__global__ void prep_kernel(
        const float4* __restrict__ x,  const float4* __restrict__ cc,
        const float* __restrict__ qw,  const float* __restrict__ pw,
        const float* __restrict__ kvw,
        float4* __restrict__ xo, float4* __restrict__ cco,
        float* __restrict__ qwt, float* __restrict__ pwt,
        float* __restrict__ kvwt) {
    const int z = blockIdx.z;
    if (z < 2) {
        const float4* src = z ? cc : x;
        float4* dst = z ? cco : xo;
        const int n4 = ROWS * DIM / 4;
        for (int i = blockIdx.x * blockDim.x + threadIdx.x; i < n4;
             i += gridDim.x * blockDim.x) {
            float4 v = src[i];
            v.x = tf32f(v.x); v.y = tf32f(v.y);
            v.z = tf32f(v.z); v.w = tf32f(v.w);
            dst[i] = v;
        }
        return;
    }
    const float* W; float* Wt; int N;
    if (z == 2)      { W = qw;  Wt = qwt;  N = DIM; }
    else if (z == 3) { W = pw;  Wt = pwt;  N = DIM; }
    else             { W = kvw; Wt = kvwt; N = 2 * DIM; }
    const int ntx = N / 32;
    const int tile = blockIdx.x;
    if (tile >= (DIM / 32) * ntx) return;
    const int kx = (tile / ntx) * 32, ny = (tile % ntx) * 32;
    __shared__ float t[32][33];
    const int tx = threadIdx.x & 31, ty = threadIdx.x >> 5;   // 32x8
#pragma unroll
    for (int j = 0; j < 32; j += 8)
        t[ty + j][tx] = tf32f(W[(size_t)(kx + ty + j) * N + ny + tx]);
    __syncthreads();
#pragma unroll
    for (int j = 0; j < 32; j += 8)
        Wt[(size_t)(ny + ty + j) * DIM + kx + tx] = t[tx][ty + j];
}

// ---------------- TF32 GEMM core: C = A @ Bt^T (+bias) ---------------------
// Bt is [N][K] (pre-transposed). 128x128 tile, K-tile 16, both operands via
// ldmatrix. 3-stage cp.async. 8 warps (2m x 4n), warp 64x32.
#define TSTR 20
#define OP_SZ (128*TSTR)               // floats per operand per stage
#define STG_B (2*OP_SZ*4)              // bytes per stage (A+B)
#define GEMM_SMEM (3*STG_B)            // 61440 B

__device__ __forceinline__ void gemm_core(
        const float* __restrict__ A, const float* __restrict__ Bt,
        const float* __restrict__ bias, float* __restrict__ C,
        int N, int K, float* sm, int bx, int by) {
    const int tid  = threadIdx.x;
    const int warp = tid >> 5, lane = tid & 31;
    const int g = lane >> 2, c = lane & 3;
    const int wm = (warp >> 2) * 64, wn = (warp & 3) * 32;
    const int bm = by * 128, bn = bx * 128;

    const int ar  = tid >> 2;            // 0..63
    const int ac4 = (tid & 3) << 2;

    const float* Ap = A  + (size_t)(bm + ar) * K + ac4;
    const float* Bp = Bt + (size_t)(bn + ar) * K + ac4;

    const uint32_t s0 = sptr(sm);
    const uint32_t cpA0 = s0 + (ar * TSTR + ac4) * 4;
    const uint32_t cpA1 = cpA0 + 64 * TSTR * 4;
    const uint32_t cpB0 = cpA0 + OP_SZ * 4;
    const uint32_t cpB1 = cpB0 + 64 * TSTR * 4;

    const int mloc = lane >> 3, rw = lane & 7;
    const uint32_t ard = s0 +
        ((wm + ((mloc & 1) << 3) + rw) * TSTR + ((mloc >> 1) << 2)) * 4;
    const uint32_t brd = s0 + OP_SZ * 4 +
        ((wn + ((lane >> 4) << 3) + rw) * TSTR + (((lane >> 3) & 1) << 2)) * 4;

    float acc[4][4][4];
#pragma unroll
    for (int mi = 0; mi < 4; mi++)
#pragma unroll
        for (int ni = 0; ni < 4; ni++)
#pragma unroll
            for (int t = 0; t < 4; t++) acc[mi][ni][t] = 0.f;

    const int nT = K >> 4;
    auto issue = [&](int t) {
        const uint32_t off = (uint32_t)(t % 3) * STG_B;
        const int k0 = t << 4;
        cpa16(cpA0 + off, Ap + k0);
        cpa16(cpA1 + off, Ap + (size_t)64 * K + k0);
        cpa16(cpB0 + off, Bp + k0);
        cpa16(cpB1 + off, Bp + (size_t)64 * K + k0);
    };

    issue(0); cpa_commit();
    issue(1); cpa_commit();

    for (int t = 0; t < nT; t++) {
        asm volatile("cp.async.wait_group 1;");
        __syncthreads();
        if (t + 2 < nT) issue(t + 2);
        cpa_commit();

        const uint32_t off = (uint32_t)(t % 3) * STG_B;
#pragma unroll
        for (int ks = 0; ks < 2; ks++) {
            unsigned af[4][4], bfr[8];
#pragma unroll
            for (int mi = 0; mi < 4; mi++)
                ldsm4(af[mi], ard + off + mi * (16 * TSTR * 4) + ks * 32);
            ldsm4(bfr,     brd + off + ks * 32);
            ldsm4(bfr + 4, brd + off + 16 * TSTR * 4 + ks * 32);
#pragma unroll
            for (int mi = 0; mi < 4; mi++)
#pragma unroll
                for (int ni = 0; ni < 4; ni++)
                    mma8b(acc[mi][ni], af[mi], bfr[2 * ni], bfr[2 * ni + 1]);
        }
    }

#pragma unroll
    for (int mi = 0; mi < 4; mi++) {
        int row = bm + wm + mi * 16 + g;
#pragma unroll
        for (int ni = 0; ni < 4; ni++) {
            int col = bn + wn + ni * 8 + 2 * c;
            float bv0 = bias ? bias[col] : 0.f;
            float bv1 = bias ? bias[col + 1] : 0.f;
            float* p0 = C + (size_t)row * N + col;
            float* p1 = C + (size_t)(row + 8) * N + col;
            p0[0] = acc[mi][ni][0] + bv0; p0[1] = acc[mi][ni][1] + bv1;
            p1[0] = acc[mi][ni][2] + bv0; p1[1] = acc[mi][ni][3] + bv1;
        }
    }
}

// fused q+kv projections: z=0 -> q (N=1024), z=1 -> kv (N=2048)
__global__ __launch_bounds__(256) void gemm_qkv(
        const float* __restrict__ Ax, const float* __restrict__ Ac,
        const float* __restrict__ Bq, const float* __restrict__ Bkv,
        float* __restrict__ Cq, float* __restrict__ Ckv) {
    extern __shared__ float sm[];
    const int z = blockIdx.z;
    if (z == 0 && blockIdx.x >= 8) return;
    gemm_core(z ? Ac : Ax, z ? Bkv : Bq, nullptr, z ? Ckv : Cq,
              z ? 2 * DIM : DIM, DIM, sm, blockIdx.x, blockIdx.y);
}

__global__ __launch_bounds__(256) void gemm_tf32(
        const float* __restrict__ A, const float* __restrict__ Bt,
        const float* __restrict__ bias, float* __restrict__ C,
        int N, int K) {
    extern __shared__ float sm[];
    gemm_core(A, Bt, bias, C, N, K, sm, blockIdx.x, blockIdx.y);
}

// ---------------- fused LN: q-mode (LN+RoPE) and kv-mode (LN k + V^T) ------
// grid (32, 16, 8): z<4 -> kv batch z; z>=4 -> q batch z-4.
__global__ __launch_bounds__(256) void ln_all_kernel(
        const float* __restrict__ Qbuf, const float* __restrict__ KVbuf,
        const float* __restrict__ qg, const float* __restrict__ qb,
        const float* __restrict__ kg, const float* __restrict__ kb_,
        float* __restrict__ Q, float* __restrict__ K, float* __restrict__ Vt) {
    const int h = blockIdx.y, rb = blockIdx.x * 64;
    const int tid = threadIdx.x, warp = tid >> 5, lane = tid & 31;

    if (blockIdx.z >= 4) {
        // ---- q: LN + RoPE ----
        const int b = blockIdx.z - 4;
        const float ga0 = qg[lane], ga1 = qg[lane + 32];
        const float be0 = qb[lane], be1 = qb[lane + 32];
        const float invf = powf(10000.f, -(float)lane * (1.f / 32.f));
#pragma unroll
        for (int j = 0; j < 8; j++) {
            const int s = rb + warp * 8 + j;
            const float* in = Qbuf + ((size_t)b * SEQ + s) * DIM + h * HD;
            float v0 = in[lane], v1 = in[lane + 32];
            float sum = v0 + v1;
#pragma unroll
            for (int o = 16; o; o >>= 1) sum += __shfl_xor_sync(0xffffffffu, sum, o);
            float mu = sum * (1.f / 64.f);
            float d0 = v0 - mu, d1 = v1 - mu;
            float vs = d0 * d0 + d1 * d1;
#pragma unroll
            for (int o = 16; o; o >>= 1) vs += __shfl_xor_sync(0xffffffffu, vs, o);
            float rstd = rsqrtf(vs * (1.f / 64.f) + 1e-5f);
            float y0 = d0 * rstd * ga0 + be0;
            float y1 = d1 * rstd * ga1 + be1;
            float sn, cs;
            sincosf((float)s * invf, &sn, &cs);
            float* outp = Q + ((size_t)(b * NHEAD + h) * SEQ + s) * HD;
            outp[lane]      = tf32f(y0 * cs - y1 * sn);
            outp[lane + 32] = tf32f(y0 * sn + y1 * cs);
        }
        return;
    }

    // ---- kv: LN on k + transposed V ----
    __shared__ float Vs[64 * 65];
    const int b = blockIdx.z;
    const float ga0 = kg[lane], ga1 = kg[lane + 32];
    const float be0 = kb_[lane], be1 = kb_[lane + 32];
#pragma unroll
    for (int j = 0; j < 8; j++) {
        const int kl  = warp * 8 + j;
        const int key = rb + kl;
        const float* kin = KVbuf + ((size_t)b * SEQ + key) * (2 * DIM) + h * HD;
        const float* vin = kin + DIM;
        float v0 = kin[lane], v1 = kin[lane + 32];
        float sum = v0 + v1;
#pragma unroll
        for (int o = 16; o; o >>= 1) sum += __shfl_xor_sync(0xffffffffu, sum, o);
        float mu = sum * (1.f / 64.f);
        float d0 = v0 - mu, d1 = v1 - mu;
        float vs = d0 * d0 + d1 * d1;
#pragma unroll
        for (int o = 16; o; o >>= 1) vs += __shfl_xor_sync(0xffffffffu, vs, o);
        float rstd = rsqrtf(vs * (1.f / 64.f) + 1e-5f);
        size_t ob = ((size_t)(b * NHEAD + h) * SEQ + key) * HD;
        K[ob + lane]      = tf32f(d0 * rstd * ga0 + be0);
        K[ob + lane + 32] = tf32f(d1 * rstd * ga1 + be1);
        Vs[lane * 65 + kl]        = tf32f(vin[lane]);
        Vs[(lane + 32) * 65 + kl] = tf32f(vin[lane + 32]);
    }
    __syncthreads();
    const int d = tid >> 2, c0 = (tid & 3) * 16;
    float* dst = Vt + ((size_t)((b * NHEAD + h) * HD + d)) * SEQ + rb + c0;
#pragma unroll
    for (int e = 0; e < 16; e += 4) {
        const float* s = &Vs[d * 65 + c0 + e];
        *(float4*)(dst + e) = make_float4(s[0], s[1], s[2], s[3]);
    }
}

// --------- flash attention: 128q x 64k, P via warp-private smem + ldsm ----
#define QIDX(r, col) ((r) * 64 + ((col) ^ (((r) & 7) << 2)))
#define VTIDX(d, key) ((d) * 64 + (((((key) >> 2) ^ ((d) & 7)) << 2) | ((key) & 3)))
#define FKV 8192                      // one KV stage in floats
#define PSTR 68
#define PWARP (16*PSTR)               // 1088 floats per warp
#define FLASH_SMEM ((2*FKV + 8*PWARP)*4)   // 100352 B

__global__ __launch_bounds__(256) void flash_tf32(
        const float* __restrict__ Q, const float* __restrict__ K,
        const float* __restrict__ Vt, float* __restrict__ O) {
    extern __shared__ float stage[];

    const int qt = blockIdx.x, h = blockIdx.y, b = blockIdx.z;
    const int tid  = threadIdx.x;
    const int warp = tid >> 5, lane = tid & 31;
    const int g = lane >> 2, c = lane & 3;
    const int wm = warp * 16;

    // K ldsm bases
    const int mloc = lane >> 3, rw = lane & 7;
    uint32_t kb_base[4];
#pragma unroll
    for (int gi = 0; gi < 4; gi++) {
        int row = (gi * 2 + (mloc >> 1)) * 8 + rw;
        kb_base[gi] = (uint32_t)(row * 256) + ((((mloc & 1) << 4) ^ (rw << 4)));
    }
    // V ldsm bases
    const int Lr = lane & 15, h4 = lane >> 4, mmv = lane & 7;
    uint32_t vrow[4];
#pragma unroll
    for (int gi = 0; gi < 4; gi++) vrow[gi] = (uint32_t)((16 * gi + Lr) * 256);
    const uint32_t vlc = ((uint32_t)h4 << 4) ^ ((uint32_t)mmv << 4);
    // P (warp-private)
    float* Pw = stage + 2 * FKV + warp * PWARP;
    const uint32_t pwb = sptr(Pw);
    const uint32_t p_off =
        (uint32_t)(((((lane >> 3) & 1) * 8 + rw) * PSTR + ((lane >> 4) << 2)) * 4);

    const float* Qg  = Q  + ((size_t)(b * NHEAD + h) * SEQ + qt * 128) * HD;
    const float* Kg  = K  + (size_t)(b * NHEAD + h) * SEQ * HD;
    const float* Vtg = Vt + (size_t)(b * NHEAD + h) * HD * SEQ;

    // ---- stage Q (128x64) through stage0 (K0+V0 areas) ----
#pragma unroll
    for (int j = 0; j < 8; j++) {
        int i = tid + j * 256;
        int r = i >> 4, c4 = (i & 15) << 2;
        float* dst = (r < 64) ? &stage[QIDX(r, c4)] : &stage[4096 + QIDX(r - 64, c4)];
        cpa16(sptr(dst), Qg + (size_t)r * 64 + c4);
    }
    cpa_commit();
    asm volatile("cp.async.wait_group 0;");
    __syncthreads();

    unsigned qf[8][4];
    {
        const float* buf = (wm < 64) ? stage : stage + 4096;
        const int rb = wm & 63;
#pragma unroll
        for (int ks = 0; ks < 8; ks++) {
            int kk = ks * 8 + c;
            qf[ks][0] = __float_as_uint(0.125f * buf[QIDX(rb + g, kk)]);
            qf[ks][1] = __float_as_uint(0.125f * buf[QIDX(rb + 8 + g, kk)]);
            qf[ks][2] = __float_as_uint(0.125f * buf[QIDX(rb + g, kk + 4)]);
            qf[ks][3] = __float_as_uint(0.125f * buf[QIDX(rb + 8 + g, kk + 4)]);
        }
    }
    __syncthreads();

    auto issueKV = [&](int t) {
        float* Kb = stage + (t & 1) * FKV;
        float* Vb = Kb + 4096;
#pragma unroll
        for (int j = 0; j < 4; j++) {
            int i = tid + j * 256;
            int r = i >> 4, c4 = (i & 15) << 2;
            cpa16(sptr(&Kb[QIDX(r, c4)]), Kg + (size_t)(t * 64 + r) * 64 + c4);
            cpa16(sptr(&Vb[VTIDX(r, c4)]), Vtg + (size_t)r * SEQ + t * 64 + c4);
        }
    };

    issueKV(0); cpa_commit();
    issueKV(1); cpa_commit();

    float m0 = -1e30f, m1 = -1e30f, l0 = 0.f, l1 = 0.f;
    float o[8][4];
#pragma unroll
    for (int ni = 0; ni < 8; ni++)
#pragma unroll
        for (int t = 0; t < 4; t++) o[ni][t] = 0.f;

    const int nT = SEQ / 64;
    for (int kt = 0; kt < nT; kt++) {
        asm volatile("cp.async.wait_group 1;");
        __syncthreads();

        const uint32_t ksb = sptr(stage + (kt & 1) * FKV);
        const uint32_t vtb = ksb + 4096 * 4;

        // ---- S = Q K^T ----
        float s[8][4];
#pragma unroll
        for (int ni = 0; ni < 8; ni++)
#pragma unroll
            for (int t = 0; t < 4; t++) s[ni][t] = 0.f;
#pragma unroll
        for (int ks = 0; ks < 8; ks++) {
            unsigned kbf[16];
#pragma unroll
            for (int gi = 0; gi < 4; gi++)
                ldsm4(&kbf[gi * 4], ksb + (kb_base[gi] ^ (uint32_t)(ks << 5)));
#pragma unroll
            for (int ni = 0; ni < 8; ni++) mma8(s[ni], qf[ks], &kbf[ni * 2]);
        }

        // ---- online softmax ----
        float rm0 = -1e30f, rm1 = -1e30f;
#pragma unroll
        for (int ni = 0; ni < 8; ni++) {
            rm0 = fmaxf(rm0, fmaxf(s[ni][0], s[ni][1]));
            rm1 = fmaxf(rm1, fmaxf(s[ni][2], s[ni][3]));
        }
        rm0 = fmaxf(rm0, __shfl_xor_sync(0xffffffffu, rm0, 1));
        rm0 = fmaxf(rm0, __shfl_xor_sync(0xffffffffu, rm0, 2));
        rm1 = fmaxf(rm1, __shfl_xor_sync(0xffffffffu, rm1, 1));
        rm1 = fmaxf(rm1, __shfl_xor_sync(0xffffffffu, rm1, 2));
        float mn0 = fmaxf(m0, rm0), mn1 = fmaxf(m1, rm1);

        float ps0 = 0.f, ps1 = 0.f;
#pragma unroll
        for (int ni = 0; ni < 8; ni++) {
            s[ni][0] = __expf(s[ni][0] - mn0); s[ni][1] = __expf(s[ni][1] - mn0);
            s[ni][2] = __expf(s[ni][2] - mn1); s[ni][3] = __expf(s[ni][3] - mn1);
            ps0 += s[ni][0] + s[ni][1];
            ps1 += s[ni][2] + s[ni][3];
        }
        ps0 += __shfl_xor_sync(0xffffffffu, ps0, 1);
        ps0 += __shfl_xor_sync(0xffffffffu, ps0, 2);
        ps1 += __shfl_xor_sync(0xffffffffu, ps1, 1);
        ps1 += __shfl_xor_sync(0xffffffffu, ps1, 2);

        float al0 = __expf(m0 - mn0), al1 = __expf(m1 - mn1);
        m0 = mn0; m1 = mn1;
        l0 = l0 * al0 + ps0;
        l1 = l1 * al1 + ps1;
#pragma unroll
        for (int ni = 0; ni < 8; ni++) {
            o[ni][0] *= al0; o[ni][1] *= al0;
            o[ni][2] *= al1; o[ni][3] *= al1;
        }

        // ---- store P (tf32-rounded) into warp-private smem ----
#pragma unroll
        for (int ni = 0; ni < 8; ni++) {
            const int colb = ni * 8 + 2 * c;
            *(float2*)&Pw[g * PSTR + colb] =
                make_float2(tf32f(s[ni][0]), tf32f(s[ni][1]));
            *(float2*)&Pw[(g + 8) * PSTR + colb] =
                make_float2(tf32f(s[ni][2]), tf32f(s[ni][3]));
        }
        __syncwarp();

        // ---- O += P @ V : P A-frags + V B-frags via ldsm ----
#pragma unroll
        for (int ks = 0; ks < 8; ks++) {
            unsigned pa[4];
            ldsm4(pa, pwb + p_off + (uint32_t)(ks * 32));
            const uint32_t xo = ((uint32_t)ks << 5) ^ vlc;
#pragma unroll
            for (int gi = 0; gi < 4; gi++) {
                unsigned vv[4];
                ldsm4(vv, vtb + vrow[gi] + xo);
                mma8b(o[2 * gi],     pa, vv[0], vv[2]);
                mma8b(o[2 * gi + 1], pa, vv[1], vv[3]);
            }
        }

        __syncthreads();          // all warps done reading stage kt&1
        if (kt + 2 < nT) issueKV(kt + 2);
        cpa_commit();
    }

    // ---- epilogue -> O [B, S, H*Hd], tf32-rounded ----
    float inv0 = 1.f / l0, inv1 = 1.f / l1;
    int row0 = qt * 128 + wm + g;
#pragma unroll
    for (int ni = 0; ni < 8; ni++) {
        int col = h * HD + ni * 8 + 2 * c;
        float* p0 = O + ((size_t)b * SEQ + row0) * DIM + col;
        float* p1 = O + ((size_t)b * SEQ + row0 + 8) * DIM + col;
        p0[0] = tf32f(o[ni][0] * inv0);
        p0[1] = tf32f(o[ni][1] * inv0);
        p1[0] = tf32f(o[ni][2] * inv1);
        p1[1] = tf32f(o[ni][3] * inv1);
    }
}

// ---------------------------------------------------------------------------
extern "C" void kernel_launch(void* const* d_in, const int* in_sizes, int n_in,
                              void* d_out, int out_size) {
    const float* x        = (const float*)d_in[0];
    const float* context  = (const float*)d_in[1];
    const float* q_w      = (const float*)d_in[2];
    const float* kv_w     = (const float*)d_in[3];
    const float* qn_scale = (const float*)d_in[4];
    const float* qn_bias  = (const float*)d_in[5];
    const float* kn_scale = (const float*)d_in[6];
    const float* kn_bias  = (const float*)d_in[7];
    const float* proj_w   = (const float*)d_in[8];
    const float* proj_b   = (const float*)d_in[9];
    float* out = (float*)d_out;

    float *Qbuf, *KVbuf, *Q, *K, *V, *O, *xc, *cc, *qwt, *kvwt, *pwt;
    cudaGetSymbolAddress((void**)&Qbuf,  g_Qbuf);
    cudaGetSymbolAddress((void**)&KVbuf, g_KVbuf);
    cudaGetSymbolAddress((void**)&Q,     g_Q);
    cudaGetSymbolAddress((void**)&K,     g_K);
    cudaGetSymbolAddress((void**)&V,     g_V);
    cudaGetSymbolAddress((void**)&O,     g_O);
    cudaGetSymbolAddress((void**)&xc,    g_xc);
    cudaGetSymbolAddress((void**)&cc,    g_cc);
    cudaGetSymbolAddress((void**)&qwt,   g_qwt);
    cudaGetSymbolAddress((void**)&kvwt,  g_kvwt);
    cudaGetSymbolAddress((void**)&pwt,   g_pwt);

    cudaFuncSetAttribute(gemm_qkv,
        cudaFuncAttributeMaxDynamicSharedMemorySize, GEMM_SMEM);
    cudaFuncSetAttribute(gemm_tf32,
        cudaFuncAttributeMaxDynamicSharedMemorySize, GEMM_SMEM);
    cudaFuncSetAttribute(flash_tf32,
        cudaFuncAttributeMaxDynamicSharedMemorySize, FLASH_SMEM);

    // L1: prep (round x/context, transpose+round 3 weights)
    prep_kernel<<<dim3(2048, 1, 5), 256>>>(
        (const float4*)x, (const float4*)context, q_w, proj_w, kv_w,
        (float4*)xc, (float4*)cc, qwt, pwt, kvwt);
    // L2: fused q + kv projections
    gemm_qkv<<<dim3(16, 64, 2), 256, GEMM_SMEM>>>(xc, cc, qwt, kvwt, Qbuf, KVbuf);
    // L3: fused LN (q: LN+RoPE, kv: LN k + V^T)
    ln_all_kernel<<<dim3(32, 16, 8), 256>>>(
        Qbuf, KVbuf, qn_scale, qn_bias, kn_scale, kn_bias, Q, K, V);
    // L4: attention  (profiled slot)
    flash_tf32<<<dim3(SEQ / 128, NHEAD, BATCH), 256, FLASH_SMEM>>>(Q, K, V, O);
    // L5: out = O @ proj_w + proj_b
    gemm_tf32<<<dim3(8, 64), 256, GEMM_SMEM>>>(O, pwt, proj_b, out, DIM, DIM);
}

// round 8
// speedup vs baseline: 3.7544x; 1.0220x over previous
#include <cuda_runtime.h>
#include <math.h>
#include <stdint.h>

#define BATCH 4
#define SEQ   2048
#define DIM   1024
#define NHEAD 16
#define HD    64
#define ROWS  (BATCH*SEQ)   // 8192

// ---------------- scratch (device globals; no allocation allowed) ----------
__device__ float g_Qbuf[(size_t)ROWS * DIM];
__device__ float g_KVbuf[(size_t)ROWS * 2 * DIM];
__device__ float g_Q[(size_t)ROWS * DIM];           // [B,H,S,Hd] tf32
__device__ float g_K[(size_t)ROWS * DIM];           // [B,H,Sc,Hd] tf32
__device__ float g_V[(size_t)ROWS * DIM];           // [B,H,Hd,Sc] transposed tf32
__device__ float g_O[(size_t)ROWS * DIM];           // [B,S,H*Hd] tf32
__device__ float g_qwt[(size_t)DIM * DIM];          // q_w^T   [N][K] tf32
__device__ float g_kvwt[(size_t)2 * DIM * DIM];     // kv_w^T  [2N][K] tf32
__device__ float g_pwt[(size_t)DIM * DIM];          // proj_w^T tf32

// ---------------- helpers ---------------------------------------------------
__device__ __forceinline__ unsigned tf32(float x) {
    unsigned u;
    asm("cvt.rna.tf32.f32 %0, %1;" : "=r"(u) : "f"(x));
    return u;
}
__device__ __forceinline__ float tf32f(float x) { return __uint_as_float(tf32(x)); }
__device__ __forceinline__ float ex2(float x) {
    float y;
    asm("ex2.approx.f32 %0, %1;" : "=f"(y) : "f"(x));
    return y;
}

__device__ __forceinline__ void mma8(float* d, const unsigned* a, const unsigned* b) {
    asm volatile(
        "mma.sync.aligned.m16n8k8.row.col.f32.tf32.tf32.f32 "
        "{%0,%1,%2,%3}, {%4,%5,%6,%7}, {%8,%9}, {%0,%1,%2,%3};"
        : "+f"(d[0]), "+f"(d[1]), "+f"(d[2]), "+f"(d[3])
        : "r"(a[0]), "r"(a[1]), "r"(a[2]), "r"(a[3]), "r"(b[0]), "r"(b[1]));
}
__device__ __forceinline__ void mma8b(float* d, const unsigned* a,
                                      unsigned b0, unsigned b1) {
    asm volatile(
        "mma.sync.aligned.m16n8k8.row.col.f32.tf32.tf32.f32 "
        "{%0,%1,%2,%3}, {%4,%5,%6,%7}, {%8,%9}, {%0,%1,%2,%3};"
        : "+f"(d[0]), "+f"(d[1]), "+f"(d[2]), "+f"(d[3])
        : "r"(a[0]), "r"(a[1]), "r"(a[2]), "r"(a[3]), "r"(b0), "r"(b1));
}
__device__ __forceinline__ void ldsm4(unsigned* r, uint32_t addr) {
    asm volatile("ldmatrix.sync.aligned.m8n8.x4.shared.b16 {%0,%1,%2,%3}, [%4];"
        : "=r"(r[0]), "=r"(r[1]), "=r"(r[2]), "=r"(r[3]) : "r"(addr));
}
__device__ __forceinline__ void cpa16(uint32_t s, const void* g) {
    asm volatile("cp.async.cg.shared.global [%0], [%1], 16;" :: "r"(s), "l"(g));
}
__device__ __forceinline__ void cpa_commit() {
    asm volatile("cp.async.commit_group;");
}
__device__ __forceinline__ uint32_t sptr(const void* p) {
    return (uint32_t)__cvta_generic_to_shared(p);
}

// ---------------- prep: transpose + tf32-round the 3 weights ---------------
__global__ void prep_kernel(
        const float* __restrict__ qw,  const float* __restrict__ pw,
        const float* __restrict__ kvw,
        float* __restrict__ qwt, float* __restrict__ pwt,
        float* __restrict__ kvwt) {
    const int z = blockIdx.z;
    const float* W; float* Wt; int N;
    if (z == 0)      { W = qw;  Wt = qwt;  N = DIM; }
    else if (z == 1) { W = pw;  Wt = pwt;  N = DIM; }
    else             { W = kvw; Wt = kvwt; N = 2 * DIM; }
    const int ntx = N / 32;
    const int tile = blockIdx.x;
    if (tile >= (DIM / 32) * ntx) return;
    const int kx = (tile / ntx) * 32, ny = (tile % ntx) * 32;
    __shared__ float t[32][33];
    const int tx = threadIdx.x & 31, ty = threadIdx.x >> 5;   // 32x8
#pragma unroll
    for (int j = 0; j < 32; j += 8)
        t[ty + j][tx] = tf32f(W[(size_t)(kx + ty + j) * N + ny + tx]);
    __syncthreads();
#pragma unroll
    for (int j = 0; j < 32; j += 8)
        Wt[(size_t)(ny + ty + j) * DIM + kx + tx] = t[tx][ty + j];
}

// ---------------- TF32 GEMM core: C = A @ Bt^T (+bias) ---------------------
// A raw fp32 (cvt to tf32 post-ldsm); Bt pre-transposed+rounded [N][K].
// 128x128 tile, K-tile 16, 3-stage cp.async, 8 warps (2m x 4n), warp 64x32.
#define TSTR 20
#define OP_SZ (128*TSTR)
#define STG_B (2*OP_SZ*4)
#define GEMM_SMEM (3*STG_B)            // 61440 B

__device__ __forceinline__ void gemm_core(
        const float* __restrict__ A, const float* __restrict__ Bt,
        const float* __restrict__ bias, float* __restrict__ C,
        int N, int K, float* sm, int bx, int by) {
    const int tid  = threadIdx.x;
    const int warp = tid >> 5, lane = tid & 31;
    const int g = lane >> 2, c = lane & 3;
    const int wm = (warp >> 2) * 64, wn = (warp & 3) * 32;
    const int bm = by * 128, bn = bx * 128;

    const int ar  = tid >> 2;
    const int ac4 = (tid & 3) << 2;

    const float* Ap = A  + (size_t)(bm + ar) * K + ac4;
    const float* Bp = Bt + (size_t)(bn + ar) * K + ac4;

    const uint32_t s0 = sptr(sm);
    const uint32_t cpA0 = s0 + (ar * TSTR + ac4) * 4;
    const uint32_t cpA1 = cpA0 + 64 * TSTR * 4;
    const uint32_t cpB0 = cpA0 + OP_SZ * 4;
    const uint32_t cpB1 = cpB0 + 64 * TSTR * 4;

    const int mloc = lane >> 3, rw = lane & 7;
    const uint32_t ard = s0 +
        ((wm + ((mloc & 1) << 3) + rw) * TSTR + ((mloc >> 1) << 2)) * 4;
    const uint32_t brd = s0 + OP_SZ * 4 +
        ((wn + ((lane >> 4) << 3) + rw) * TSTR + (((lane >> 3) & 1) << 2)) * 4;

    float acc[4][4][4];
#pragma unroll
    for (int mi = 0; mi < 4; mi++)
#pragma unroll
        for (int ni = 0; ni < 4; ni++)
#pragma unroll
            for (int t = 0; t < 4; t++) acc[mi][ni][t] = 0.f;

    const int nT = K >> 4;
    auto issue = [&](int t) {
        const uint32_t off = (uint32_t)(t % 3) * STG_B;
        const int k0 = t << 4;
        cpa16(cpA0 + off, Ap + k0);
        cpa16(cpA1 + off, Ap + (size_t)64 * K + k0);
        cpa16(cpB0 + off, Bp + k0);
        cpa16(cpB1 + off, Bp + (size_t)64 * K + k0);
    };

    issue(0); cpa_commit();
    issue(1); cpa_commit();

    for (int t = 0; t < nT; t++) {
        asm volatile("cp.async.wait_group 1;");
        __syncthreads();
        if (t + 2 < nT) issue(t + 2);
        cpa_commit();

        const uint32_t off = (uint32_t)(t % 3) * STG_B;
#pragma unroll
        for (int ks = 0; ks < 2; ks++) {
            unsigned af[4][4], bfr[8];
#pragma unroll
            for (int mi = 0; mi < 4; mi++)
                ldsm4(af[mi], ard + off + mi * (16 * TSTR * 4) + ks * 32);
            ldsm4(bfr,     brd + off + ks * 32);
            ldsm4(bfr + 4, brd + off + 16 * TSTR * 4 + ks * 32);
            // A is raw fp32: round fragments to tf32 (B pre-rounded)
#pragma unroll
            for (int mi = 0; mi < 4; mi++)
#pragma unroll
                for (int t2 = 0; t2 < 4; t2++)
                    af[mi][t2] = tf32(__uint_as_float(af[mi][t2]));
#pragma unroll
            for (int mi = 0; mi < 4; mi++)
#pragma unroll
                for (int ni = 0; ni < 4; ni++)
                    mma8b(acc[mi][ni], af[mi], bfr[2 * ni], bfr[2 * ni + 1]);
        }
    }

#pragma unroll
    for (int mi = 0; mi < 4; mi++) {
        int row = bm + wm + mi * 16 + g;
#pragma unroll
        for (int ni = 0; ni < 4; ni++) {
            int col = bn + wn + ni * 8 + 2 * c;
            float bv0 = bias ? bias[col] : 0.f;
            float bv1 = bias ? bias[col + 1] : 0.f;
            float* p0 = C + (size_t)row * N + col;
            float* p1 = C + (size_t)(row + 8) * N + col;
            p0[0] = acc[mi][ni][0] + bv0; p0[1] = acc[mi][ni][1] + bv1;
            p1[0] = acc[mi][ni][2] + bv0; p1[1] = acc[mi][ni][3] + bv1;
        }
    }
}

// fused q+kv projections: z=0 -> q (N=1024), z=1 -> kv (N=2048)
__global__ __launch_bounds__(256) void gemm_qkv(
        const float* __restrict__ Ax, const float* __restrict__ Ac,
        const float* __restrict__ Bq, const float* __restrict__ Bkv,
        float* __restrict__ Cq, float* __restrict__ Ckv) {
    extern __shared__ float sm[];
    const int z = blockIdx.z;
    if (z == 0 && blockIdx.x >= 8) return;
    gemm_core(z ? Ac : Ax, z ? Bkv : Bq, nullptr, z ? Ckv : Cq,
              z ? 2 * DIM : DIM, DIM, sm, blockIdx.x, blockIdx.y);
}

__global__ __launch_bounds__(256) void gemm_tf32(
        const float* __restrict__ A, const float* __restrict__ Bt,
        const float* __restrict__ bias, float* __restrict__ C,
        int N, int K) {
    extern __shared__ float sm[];
    gemm_core(A, Bt, bias, C, N, K, sm, blockIdx.x, blockIdx.y);
}

// ---------------- fused LN: q-mode (LN+RoPE) and kv-mode (LN k + V^T) ------
__global__ __launch_bounds__(256) void ln_all_kernel(
        const float* __restrict__ Qbuf, const float* __restrict__ KVbuf,
        const float* __restrict__ qg, const float* __restrict__ qb,
        const float* __restrict__ kg, const float* __restrict__ kb_,
        float* __restrict__ Q, float* __restrict__ K, float* __restrict__ Vt) {
    const int h = blockIdx.y, rb = blockIdx.x * 64;
    const int tid = threadIdx.x, warp = tid >> 5, lane = tid & 31;

    if (blockIdx.z >= 4) {
        const int b = blockIdx.z - 4;
        const float ga0 = qg[lane], ga1 = qg[lane + 32];
        const float be0 = qb[lane], be1 = qb[lane + 32];
        const float invf = powf(10000.f, -(float)lane * (1.f / 32.f));
#pragma unroll
        for (int j = 0; j < 8; j++) {
            const int s = rb + warp * 8 + j;
            const float* in = Qbuf + ((size_t)b * SEQ + s) * DIM + h * HD;
            float v0 = in[lane], v1 = in[lane + 32];
            float sum = v0 + v1;
#pragma unroll
            for (int o = 16; o; o >>= 1) sum += __shfl_xor_sync(0xffffffffu, sum, o);
            float mu = sum * (1.f / 64.f);
            float d0 = v0 - mu, d1 = v1 - mu;
            float vs = d0 * d0 + d1 * d1;
#pragma unroll
            for (int o = 16; o; o >>= 1) vs += __shfl_xor_sync(0xffffffffu, vs, o);
            float rstd = rsqrtf(vs * (1.f / 64.f) + 1e-5f);
            float y0 = d0 * rstd * ga0 + be0;
            float y1 = d1 * rstd * ga1 + be1;
            float sn, cs;
            sincosf((float)s * invf, &sn, &cs);
            float* outp = Q + ((size_t)(b * NHEAD + h) * SEQ + s) * HD;
            outp[lane]      = tf32f(y0 * cs - y1 * sn);
            outp[lane + 32] = tf32f(y0 * sn + y1 * cs);
        }
        return;
    }

    __shared__ float Vs[64 * 65];
    const int b = blockIdx.z;
    const float ga0 = kg[lane], ga1 = kg[lane + 32];
    const float be0 = kb_[lane], be1 = kb_[lane + 32];
#pragma unroll
    for (int j = 0; j < 8; j++) {
        const int kl  = warp * 8 + j;
        const int key = rb + kl;
        const float* kin = KVbuf + ((size_t)b * SEQ + key) * (2 * DIM) + h * HD;
        const float* vin = kin + DIM;
        float v0 = kin[lane], v1 = kin[lane + 32];
        float sum = v0 + v1;
#pragma unroll
        for (int o = 16; o; o >>= 1) sum += __shfl_xor_sync(0xffffffffu, sum, o);
        float mu = sum * (1.f / 64.f);
        float d0 = v0 - mu, d1 = v1 - mu;
        float vs = d0 * d0 + d1 * d1;
#pragma unroll
        for (int o = 16; o; o >>= 1) vs += __shfl_xor_sync(0xffffffffu, vs, o);
        float rstd = rsqrtf(vs * (1.f / 64.f) + 1e-5f);
        size_t ob = ((size_t)(b * NHEAD + h) * SEQ + key) * HD;
        K[ob + lane]      = tf32f(d0 * rstd * ga0 + be0);
        K[ob + lane + 32] = tf32f(d1 * rstd * ga1 + be1);
        Vs[lane * 65 + kl]        = tf32f(vin[lane]);
        Vs[(lane + 32) * 65 + kl] = tf32f(vin[lane + 32]);
    }
    __syncthreads();
    const int d = tid >> 2, c0 = (tid & 3) * 16;
    float* dst = Vt + ((size_t)((b * NHEAD + h) * HD + d)) * SEQ + rb + c0;
#pragma unroll
    for (int e = 0; e < 16; e += 4) {
        const float* s = &Vs[d * 65 + c0 + e];
        *(float4*)(dst + e) = make_float4(s[0], s[1], s[2], s[3]);
    }
}

// --------- flash attention: 128q x 64k, exp2-domain softmax ----------------
#define QIDX(r, col) ((r) * 64 + ((col) ^ (((r) & 7) << 2)))
#define VTIDX(d, key) ((d) * 64 + (((((key) >> 2) ^ ((d) & 7)) << 2) | ((key) & 3)))
#define FKV 8192
#define PWARP 1024                          // 16 rows x 64 cols, swizzled
#define FLASH_SMEM ((2*FKV + 8*PWARP)*4)    // 98304 B

#define QSCALE (0.125f * 1.44269504088896340736f)   // 1/sqrt(64) * log2(e)

__global__ __launch_bounds__(256) void flash_tf32(
        const float* __restrict__ Q, const float* __restrict__ K,
        const float* __restrict__ Vt, float* __restrict__ O) {
    extern __shared__ float stage[];

    const int qt = blockIdx.x, h = blockIdx.y, b = blockIdx.z;
    const int tid  = threadIdx.x;
    const int warp = tid >> 5, lane = tid & 31;
    const int g = lane >> 2, c = lane & 3;
    const int wm = warp * 16;

    // K ldsm bases
    const int mloc = lane >> 3, rw = lane & 7;
    uint32_t kb_base[4];
#pragma unroll
    for (int gi = 0; gi < 4; gi++) {
        int row = (gi * 2 + (mloc >> 1)) * 8 + rw;
        kb_base[gi] = (uint32_t)(row * 256) + ((((mloc & 1) << 4) ^ (rw << 4)));
    }
    // V ldsm bases
    const int Lr = lane & 15, h4 = lane >> 4, mmv = lane & 7;
    uint32_t vrow[4];
#pragma unroll
    for (int gi = 0; gi < 4; gi++) vrow[gi] = (uint32_t)((16 * gi + Lr) * 256);
    const uint32_t vlc = ((uint32_t)h4 << 4) ^ ((uint32_t)mmv << 4);
    // P (warp-private, stride-64 swizzled like QIDX)
    float* Pw = stage + 2 * FKV + warp * PWARP;
    const uint32_t pwb = sptr(Pw);
    const uint32_t p_row = (uint32_t)((((lane >> 3) & 1) * 8 + rw) * 256);
    const uint32_t p_hi  = (uint32_t)((lane >> 4) << 4);
    const uint32_t p_rsw = (uint32_t)(rw << 4);

    const float* Qg  = Q  + ((size_t)(b * NHEAD + h) * SEQ + qt * 128) * HD;
    const float* Kg  = K  + (size_t)(b * NHEAD + h) * SEQ * HD;
    const float* Vtg = Vt + (size_t)(b * NHEAD + h) * HD * SEQ;

    // ---- stage Q (128x64) through stage0 (K0+V0 areas) ----
#pragma unroll
    for (int j = 0; j < 8; j++) {
        int i = tid + j * 256;
        int r = i >> 4, c4 = (i & 15) << 2;
        float* dst = (r < 64) ? &stage[QIDX(r, c4)] : &stage[4096 + QIDX(r - 64, c4)];
        cpa16(sptr(dst), Qg + (size_t)r * 64 + c4);
    }
    cpa_commit();
    asm volatile("cp.async.wait_group 0;");
    __syncthreads();

    // Q fragments pre-scaled into exp2 domain (explicit tf32 rounding)
    unsigned qf[8][4];
    {
        const float* buf = (wm < 64) ? stage : stage + 4096;
        const int rb = wm & 63;
#pragma unroll
        for (int ks = 0; ks < 8; ks++) {
            int kk = ks * 8 + c;
            qf[ks][0] = tf32(QSCALE * buf[QIDX(rb + g, kk)]);
            qf[ks][1] = tf32(QSCALE * buf[QIDX(rb + 8 + g, kk)]);
            qf[ks][2] = tf32(QSCALE * buf[QIDX(rb + g, kk + 4)]);
            qf[ks][3] = tf32(QSCALE * buf[QIDX(rb + 8 + g, kk + 4)]);
        }
    }
    __syncthreads();

    auto issueKV = [&](int t) {
        float* Kb = stage + (t & 1) * FKV;
        float* Vb = Kb + 4096;
#pragma unroll
        for (int j = 0; j < 4; j++) {
            int i = tid + j * 256;
            int r = i >> 4, c4 = (i & 15) << 2;
            cpa16(sptr(&Kb[QIDX(r, c4)]), Kg + (size_t)(t * 64 + r) * 64 + c4);
            cpa16(sptr(&Vb[VTIDX(r, c4)]), Vtg + (size_t)r * SEQ + t * 64 + c4);
        }
    };

    issueKV(0); cpa_commit();
    issueKV(1); cpa_commit();

    float m0 = -1e30f, m1 = -1e30f, l0 = 0.f, l1 = 0.f;
    float o[8][4];
#pragma unroll
    for (int ni = 0; ni < 8; ni++)
#pragma unroll
        for (int t = 0; t < 4; t++) o[ni][t] = 0.f;

    const int nT = SEQ / 64;
    for (int kt = 0; kt < nT; kt++) {
        asm volatile("cp.async.wait_group 1;");
        __syncthreads();

        const uint32_t ksb = sptr(stage + (kt & 1) * FKV);
        const uint32_t vtb = ksb + 4096 * 4;

        // ---- S = Q K^T (exp2 domain) ----
        float s[8][4];
#pragma unroll
        for (int ni = 0; ni < 8; ni++)
#pragma unroll
            for (int t = 0; t < 4; t++) s[ni][t] = 0.f;
#pragma unroll
        for (int ks = 0; ks < 8; ks++) {
            unsigned kbf[16];
#pragma unroll
            for (int gi = 0; gi < 4; gi++)
                ldsm4(&kbf[gi * 4], ksb + (kb_base[gi] ^ (uint32_t)(ks << 5)));
#pragma unroll
            for (int ni = 0; ni < 8; ni++) mma8(s[ni], qf[ks], &kbf[ni * 2]);
        }

        // ---- online softmax in exp2 domain ----
        float rm0 = -1e30f, rm1 = -1e30f;
#pragma unroll
        for (int ni = 0; ni < 8; ni++) {
            rm0 = fmaxf(rm0, fmaxf(s[ni][0], s[ni][1]));
            rm1 = fmaxf(rm1, fmaxf(s[ni][2], s[ni][3]));
        }
        rm0 = fmaxf(rm0, __shfl_xor_sync(0xffffffffu, rm0, 1));
        rm0 = fmaxf(rm0, __shfl_xor_sync(0xffffffffu, rm0, 2));
        rm1 = fmaxf(rm1, __shfl_xor_sync(0xffffffffu, rm1, 1));
        rm1 = fmaxf(rm1, __shfl_xor_sync(0xffffffffu, rm1, 2));
        float mn0 = fmaxf(m0, rm0), mn1 = fmaxf(m1, rm1);

        float ps0 = 0.f, ps1 = 0.f;
#pragma unroll
        for (int ni = 0; ni < 8; ni++) {
            s[ni][0] = ex2(s[ni][0] - mn0); s[ni][1] = ex2(s[ni][1] - mn0);
            s[ni][2] = ex2(s[ni][2] - mn1); s[ni][3] = ex2(s[ni][3] - mn1);
            ps0 += s[ni][0] + s[ni][1];
            ps1 += s[ni][2] + s[ni][3];
        }
        ps0 += __shfl_xor_sync(0xffffffffu, ps0, 1);
        ps0 += __shfl_xor_sync(0xffffffffu, ps0, 2);
        ps1 += __shfl_xor_sync(0xffffffffu, ps1, 1);
        ps1 += __shfl_xor_sync(0xffffffffu, ps1, 2);

        float al0 = ex2(m0 - mn0), al1 = ex2(m1 - mn1);
        m0 = mn0; m1 = mn1;
        l0 = l0 * al0 + ps0;
        l1 = l1 * al1 + ps1;
#pragma unroll
        for (int ni = 0; ni < 8; ni++) {
            o[ni][0] *= al0; o[ni][1] *= al0;
            o[ni][2] *= al1; o[ni][3] *= al1;
        }

        // ---- store P (tf32-rounded) into warp-private swizzled smem ----
        {
            const int sw = g << 2;
#pragma unroll
            for (int ni = 0; ni < 8; ni++) {
                const int colb = ni * 8 + 2 * c;
                *(float2*)&Pw[g * 64 + (colb ^ sw)] =
                    make_float2(tf32f(s[ni][0]), tf32f(s[ni][1]));
                *(float2*)&Pw[(g + 8) * 64 + (colb ^ sw)] =
                    make_float2(tf32f(s[ni][2]), tf32f(s[ni][3]));
            }
        }
        __syncwarp();

        // ---- O += P @ V ----
#pragma unroll
        for (int ks = 0; ks < 8; ks++) {
            unsigned pa[4];
            ldsm4(pa, pwb + p_row + ((((uint32_t)ks << 5) | p_hi) ^ p_rsw));
            const uint32_t xo = ((uint32_t)ks << 5) ^ vlc;
#pragma unroll
            for (int gi = 0; gi < 4; gi++) {
                unsigned vv[4];
                ldsm4(vv, vtb + vrow[gi] + xo);
                mma8b(o[2 * gi],     pa, vv[0], vv[2]);
                mma8b(o[2 * gi + 1], pa, vv[1], vv[3]);
            }
        }

        __syncthreads();
        if (kt + 2 < nT) issueKV(kt + 2);
        cpa_commit();
    }

    // ---- epilogue -> O [B, S, H*Hd], tf32-rounded ----
    float inv0 = 1.f / l0, inv1 = 1.f / l1;
    int row0 = qt * 128 + wm + g;
#pragma unroll
    for (int ni = 0; ni < 8; ni++) {
        int col = h * HD + ni * 8 + 2 * c;
        float* p0 = O + ((size_t)b * SEQ + row0) * DIM + col;
        float* p1 = O + ((size_t)b * SEQ + row0 + 8) * DIM + col;
        p0[0] = tf32f(o[ni][0] * inv0);
        p0[1] = tf32f(o[ni][1] * inv0);
        p1[0] = tf32f(o[ni][2] * inv1);
        p1[1] = tf32f(o[ni][3] * inv1);
    }
}

// ---------------------------------------------------------------------------
extern "C" void kernel_launch(void* const* d_in, const int* in_sizes, int n_in,
                              void* d_out, int out_size) {
    const float* x        = (const float*)d_in[0];
    const float* context  = (const float*)d_in[1];
    const float* q_w      = (const float*)d_in[2];
    const float* kv_w     = (const float*)d_in[3];
    const float* qn_scale = (const float*)d_in[4];
    const float* qn_bias  = (const float*)d_in[5];
    const float* kn_scale = (const float*)d_in[6];
    const float* kn_bias  = (const float*)d_in[7];
    const float* proj_w   = (const float*)d_in[8];
    const float* proj_b   = (const float*)d_in[9];
    float* out = (float*)d_out;

    float *Qbuf, *KVbuf, *Q, *K, *V, *O, *qwt, *kvwt, *pwt;
    cudaGetSymbolAddress((void**)&Qbuf,  g_Qbuf);
    cudaGetSymbolAddress((void**)&KVbuf, g_KVbuf);
    cudaGetSymbolAddress((void**)&Q,     g_Q);
    cudaGetSymbolAddress((void**)&K,     g_K);
    cudaGetSymbolAddress((void**)&V,     g_V);
    cudaGetSymbolAddress((void**)&O,     g_O);
    cudaGetSymbolAddress((void**)&qwt,   g_qwt);
    cudaGetSymbolAddress((void**)&kvwt,  g_kvwt);
    cudaGetSymbolAddress((void**)&pwt,   g_pwt);

    cudaFuncSetAttribute(gemm_qkv,
        cudaFuncAttributeMaxDynamicSharedMemorySize, GEMM_SMEM);
    cudaFuncSetAttribute(gemm_tf32,
        cudaFuncAttributeMaxDynamicSharedMemorySize, GEMM_SMEM);
    cudaFuncSetAttribute(flash_tf32,
        cudaFuncAttributeMaxDynamicSharedMemorySize, FLASH_SMEM);

    // L1: prep (transpose+round weights only)
    prep_kernel<<<dim3(2048, 1, 3), 256>>>(q_w, proj_w, kv_w, qwt, pwt, kvwt);
    // L2: fused q + kv projections (A converted in-kernel)
    gemm_qkv<<<dim3(16, 64, 2), 256, GEMM_SMEM>>>(x, context, qwt, kvwt, Qbuf, KVbuf);
    // L3: fused LN (q: LN+RoPE, kv: LN k + V^T)
    ln_all_kernel<<<dim3(32, 16, 8), 256>>>(
        Qbuf, KVbuf, qn_scale, qn_bias, kn_scale, kn_bias, Q, K, V);
    // L4: attention  (profiled slot)
    flash_tf32<<<dim3(SEQ / 128, NHEAD, BATCH), 256, FLASH_SMEM>>>(Q, K, V, O);
    // L5: out = O @ proj_w + proj_b
    gemm_tf32<<<dim3(8, 64), 256, GEMM_SMEM>>>(O, pwt, proj_b, out, DIM, DIM);
}

// round 10
// speedup vs baseline: 3.9229x; 1.0449x over previous
#include <cuda_runtime.h>
#include <math.h>
#include <stdint.h>

#define BATCH 4
#define SEQ   2048
#define DIM   1024
#define NHEAD 16
#define HD    64
#define ROWS  (BATCH*SEQ)   // 8192

// ---------------- scratch (device globals; no allocation allowed) ----------
__device__ float g_Qbuf[(size_t)ROWS * DIM];
__device__ float g_KVbuf[(size_t)ROWS * 2 * DIM];
__device__ float g_Q[(size_t)ROWS * DIM];           // [B,H,S,Hd] tf32
__device__ float g_K[(size_t)ROWS * DIM];           // [B,H,Sc,Hd] tf32
__device__ float g_V[(size_t)ROWS * DIM];           // [B,H,Hd,Sc] transposed tf32
__device__ float g_O[(size_t)ROWS * DIM];           // [B,S,H*Hd] tf32
__device__ float g_xc[(size_t)ROWS * DIM];          // tf32 x
__device__ float g_cc[(size_t)ROWS * DIM];          // tf32 context
__device__ float g_qwt[(size_t)DIM * DIM];          // q_w^T   [N][K] tf32
__device__ float g_kvwt[(size_t)2 * DIM * DIM];     // kv_w^T  [2N][K] tf32
__device__ float g_pwt[(size_t)DIM * DIM];          // proj_w^T tf32

// ---------------- helpers ---------------------------------------------------
__device__ __forceinline__ unsigned tf32(float x) {
    unsigned u;
    asm("cvt.rna.tf32.f32 %0, %1;" : "=r"(u) : "f"(x));
    return u;
}
__device__ __forceinline__ float tf32f(float x) { return __uint_as_float(tf32(x)); }
__device__ __forceinline__ float ex2(float x) {
    float y;
    asm("ex2.approx.f32 %0, %1;" : "=f"(y) : "f"(x));
    return y;
}

__device__ __forceinline__ void mma8(float* d, const unsigned* a, const unsigned* b) {
    asm volatile(
        "mma.sync.aligned.m16n8k8.row.col.f32.tf32.tf32.f32 "
        "{%0,%1,%2,%3}, {%4,%5,%6,%7}, {%8,%9}, {%0,%1,%2,%3};"
        : "+f"(d[0]), "+f"(d[1]), "+f"(d[2]), "+f"(d[3])
        : "r"(a[0]), "r"(a[1]), "r"(a[2]), "r"(a[3]), "r"(b[0]), "r"(b[1]));
}
__device__ __forceinline__ void mma8b(float* d, const unsigned* a,
                                      unsigned b0, unsigned b1) {
    asm volatile(
        "mma.sync.aligned.m16n8k8.row.col.f32.tf32.tf32.f32 "
        "{%0,%1,%2,%3}, {%4,%5,%6,%7}, {%8,%9}, {%0,%1,%2,%3};"
        : "+f"(d[0]), "+f"(d[1]), "+f"(d[2]), "+f"(d[3])
        : "r"(a[0]), "r"(a[1]), "r"(a[2]), "r"(a[3]), "r"(b0), "r"(b1));
}
__device__ __forceinline__ void ldsm4(unsigned* r, uint32_t addr) {
    asm volatile("ldmatrix.sync.aligned.m8n8.x4.shared.b16 {%0,%1,%2,%3}, [%4];"
        : "=r"(r[0]), "=r"(r[1]), "=r"(r[2]), "=r"(r[3]) : "r"(addr));
}
__device__ __forceinline__ void cpa16(uint32_t s, const void* g) {
    asm volatile("cp.async.cg.shared.global [%0], [%1], 16;" :: "r"(s), "l"(g));
}
__device__ __forceinline__ void cpa_commit() {
    asm volatile("cp.async.commit_group;");
}
__device__ __forceinline__ uint32_t sptr(const void* p) {
    return (uint32_t)__cvta_generic_to_shared(p);
}

// ---------------- prep: round x/context + transpose-round 3 weights --------
__global__ void prep_kernel(
        const float4* __restrict__ x,  const float4* __restrict__ cc,
        const float* __restrict__ qw,  const float* __restrict__ pw,
        const float* __restrict__ kvw,
        float4* __restrict__ xo, float4* __restrict__ cco,
        float* __restrict__ qwt, float* __restrict__ pwt,
        float* __restrict__ kvwt) {
    const int z = blockIdx.z;
    if (z < 2) {
        const float4* src = z ? cc : x;
        float4* dst = z ? cco : xo;
        const int n4 = ROWS * DIM / 4;
        for (int i = blockIdx.x * blockDim.x + threadIdx.x; i < n4;
             i += gridDim.x * blockDim.x) {
            float4 v = src[i];
            v.x = tf32f(v.x); v.y = tf32f(v.y);
            v.z = tf32f(v.z); v.w = tf32f(v.w);
            dst[i] = v;
        }
        return;
    }
    const float* W; float* Wt; int N;
    if (z == 2)      { W = qw;  Wt = qwt;  N = DIM; }
    else if (z == 3) { W = pw;  Wt = pwt;  N = DIM; }
    else             { W = kvw; Wt = kvwt; N = 2 * DIM; }
    const int ntx = N / 32;
    const int tile = blockIdx.x;
    if (tile >= (DIM / 32) * ntx) return;
    const int kx = (tile / ntx) * 32, ny = (tile % ntx) * 32;
    __shared__ float t[32][33];
    const int tx = threadIdx.x & 31, ty = threadIdx.x >> 5;
#pragma unroll
    for (int j = 0; j < 32; j += 8)
        t[ty + j][tx] = tf32f(W[(size_t)(kx + ty + j) * N + ny + tx]);
    __syncthreads();
#pragma unroll
    for (int j = 0; j < 32; j += 8)
        Wt[(size_t)(ny + ty + j) * DIM + kx + tx] = t[tx][ty + j];
}

// ---------------- TF32 GEMM core: C = A @ Bt^T (+bias) ---------------------
// A, Bt both pre-rounded tf32; Bt pre-transposed [N][K]. 128x128 tile,
// K-tile 16, 3-stage cp.async, 8 warps (2m x 4n), warp 64x32.
#define TSTR 20
#define OP_SZ (128*TSTR)
#define STG_B (2*OP_SZ*4)
#define GEMM_SMEM (3*STG_B)            // 61440 B

__device__ __forceinline__ void gemm_core(
        const float* __restrict__ A, const float* __restrict__ Bt,
        const float* __restrict__ bias, float* __restrict__ C,
        int N, int K, float* sm, int bx, int by) {
    const int tid  = threadIdx.x;
    const int warp = tid >> 5, lane = tid & 31;
    const int g = lane >> 2, c = lane & 3;
    const int wm = (warp >> 2) * 64, wn = (warp & 3) * 32;
    const int bm = by * 128, bn = bx * 128;

    const int ar  = tid >> 2;
    const int ac4 = (tid & 3) << 2;

    const float* Ap = A  + (size_t)(bm + ar) * K + ac4;
    const float* Bp = Bt + (size_t)(bn + ar) * K + ac4;

    const uint32_t s0 = sptr(sm);
    const uint32_t cpA0 = s0 + (ar * TSTR + ac4) * 4;
    const uint32_t cpA1 = cpA0 + 64 * TSTR * 4;
    const uint32_t cpB0 = cpA0 + OP_SZ * 4;
    const uint32_t cpB1 = cpB0 + 64 * TSTR * 4;

    const int mloc = lane >> 3, rw = lane & 7;
    const uint32_t ard = s0 +
        ((wm + ((mloc & 1) << 3) + rw) * TSTR + ((mloc >> 1) << 2)) * 4;
    const uint32_t brd = s0 + OP_SZ * 4 +
        ((wn + ((lane >> 4) << 3) + rw) * TSTR + (((lane >> 3) & 1) << 2)) * 4;

    float acc[4][4][4];
#pragma unroll
    for (int mi = 0; mi < 4; mi++)
#pragma unroll
        for (int ni = 0; ni < 4; ni++)
#pragma unroll
            for (int t = 0; t < 4; t++) acc[mi][ni][t] = 0.f;

    const int nT = K >> 4;
    auto issue = [&](int t) {
        const uint32_t off = (uint32_t)(t % 3) * STG_B;
        const int k0 = t << 4;
        cpa16(cpA0 + off, Ap + k0);
        cpa16(cpA1 + off, Ap + (size_t)64 * K + k0);
        cpa16(cpB0 + off, Bp + k0);
        cpa16(cpB1 + off, Bp + (size_t)64 * K + k0);
    };

    issue(0); cpa_commit();
    issue(1); cpa_commit();

    for (int t = 0; t < nT; t++) {
        asm volatile("cp.async.wait_group 1;");
        __syncthreads();

        const uint32_t off = (uint32_t)(t % 3) * STG_B;

        // ---- k-step 0 ----
        {
            unsigned af[4][4], bfr[8];
#pragma unroll
            for (int mi = 0; mi < 4; mi++)
                ldsm4(af[mi], ard + off + mi * (16 * TSTR * 4));
            ldsm4(bfr,     brd + off);
            ldsm4(bfr + 4, brd + off + 16 * TSTR * 4);
#pragma unroll
            for (int mi = 0; mi < 4; mi++)
#pragma unroll
                for (int ni = 0; ni < 4; ni++)
                    mma8b(acc[mi][ni], af[mi], bfr[2 * ni], bfr[2 * ni + 1]);
        }

        // ---- prefetch next-next slab (LDGSTS overlaps k-step 1 math) ----
        if (t + 2 < nT) issue(t + 2);
        cpa_commit();

        // ---- k-step 1 ----
        {
            unsigned af[4][4], bfr[8];
#pragma unroll
            for (int mi = 0; mi < 4; mi++)
                ldsm4(af[mi], ard + off + mi * (16 * TSTR * 4) + 32);
            ldsm4(bfr,     brd + off + 32);
            ldsm4(bfr + 4, brd + off + 16 * TSTR * 4 + 32);
#pragma unroll
            for (int mi = 0; mi < 4; mi++)
#pragma unroll
                for (int ni = 0; ni < 4; ni++)
                    mma8b(acc[mi][ni], af[mi], bfr[2 * ni], bfr[2 * ni + 1]);
        }
    }

#pragma unroll
    for (int mi = 0; mi < 4; mi++) {
        int row = bm + wm + mi * 16 + g;
#pragma unroll
        for (int ni = 0; ni < 4; ni++) {
            int col = bn + wn + ni * 8 + 2 * c;
            float bv0 = bias ? bias[col] : 0.f;
            float bv1 = bias ? bias[col + 1] : 0.f;
            float* p0 = C + (size_t)row * N + col;
            float* p1 = C + (size_t)(row + 8) * N + col;
            p0[0] = acc[mi][ni][0] + bv0; p0[1] = acc[mi][ni][1] + bv1;
            p1[0] = acc[mi][ni][2] + bv0; p1[1] = acc[mi][ni][3] + bv1;
        }
    }
}

// fused q+kv projections: z=0 -> q (N=1024), z=1 -> kv (N=2048)
__global__ __launch_bounds__(256) void gemm_qkv(
        const float* __restrict__ Ax, const float* __restrict__ Ac,
        const float* __restrict__ Bq, const float* __restrict__ Bkv,
        float* __restrict__ Cq, float* __restrict__ Ckv) {
    extern __shared__ float sm[];
    const int z = blockIdx.z;
    if (z == 0 && blockIdx.x >= 8) return;
    gemm_core(z ? Ac : Ax, z ? Bkv : Bq, nullptr, z ? Ckv : Cq,
              z ? 2 * DIM : DIM, DIM, sm, blockIdx.x, blockIdx.y);
}

__global__ __launch_bounds__(256) void gemm_tf32(
        const float* __restrict__ A, const float* __restrict__ Bt,
        const float* __restrict__ bias, float* __restrict__ C,
        int N, int K) {
    extern __shared__ float sm[];
    gemm_core(A, Bt, bias, C, N, K, sm, blockIdx.x, blockIdx.y);
}

// ---------------- fused LN: q-mode (LN+RoPE) and kv-mode (LN k + V^T) ------
__global__ __launch_bounds__(256) void ln_all_kernel(
        const float* __restrict__ Qbuf, const float* __restrict__ KVbuf,
        const float* __restrict__ qg, const float* __restrict__ qb,
        const float* __restrict__ kg, const float* __restrict__ kb_,
        float* __restrict__ Q, float* __restrict__ K, float* __restrict__ Vt) {
    const int h = blockIdx.y, rb = blockIdx.x * 64;
    const int tid = threadIdx.x, warp = tid >> 5, lane = tid & 31;

    if (blockIdx.z >= 4) {
        const int b = blockIdx.z - 4;
        const float ga0 = qg[lane], ga1 = qg[lane + 32];
        const float be0 = qb[lane], be1 = qb[lane + 32];
        // inv_freq = 10000^(-lane/32) = exp2(-lane/32 * log2(10000))
        const float invf = ex2(-(float)lane * (13.28771237954945f / 32.f));
#pragma unroll
        for (int j = 0; j < 8; j++) {
            const int s = rb + warp * 8 + j;
            const float* in = Qbuf + ((size_t)b * SEQ + s) * DIM + h * HD;
            float v0 = in[lane], v1 = in[lane + 32];
            float sum = v0 + v1;
#pragma unroll
            for (int o = 16; o; o >>= 1) sum += __shfl_xor_sync(0xffffffffu, sum, o);
            float mu = sum * (1.f / 64.f);
            float d0 = v0 - mu, d1 = v1 - mu;
            float vs = d0 * d0 + d1 * d1;
#pragma unroll
            for (int o = 16; o; o >>= 1) vs += __shfl_xor_sync(0xffffffffu, vs, o);
            float rstd = rsqrtf(vs * (1.f / 64.f) + 1e-5f);
            float y0 = d0 * rstd * ga0 + be0;
            float y1 = d1 * rstd * ga1 + be1;
            float sn, cs;
            sincosf((float)s * invf, &sn, &cs);
            float* outp = Q + ((size_t)(b * NHEAD + h) * SEQ + s) * HD;
            outp[lane]      = tf32f(y0 * cs - y1 * sn);
            outp[lane + 32] = tf32f(y0 * sn + y1 * cs);
        }
        return;
    }

    __shared__ float Vs[64 * 65];
    const int b = blockIdx.z;
    const float ga0 = kg[lane], ga1 = kg[lane + 32];
    const float be0 = kb_[lane], be1 = kb_[lane + 32];
#pragma unroll
    for (int j = 0; j < 8; j++) {
        const int kl  = warp * 8 + j;
        const int key = rb + kl;
        const float* kin = KVbuf + ((size_t)b * SEQ + key) * (2 * DIM) + h * HD;
        const float* vin = kin + DIM;
        float v0 = kin[lane], v1 = kin[lane + 32];
        float sum = v0 + v1;
#pragma unroll
        for (int o = 16; o; o >>= 1) sum += __shfl_xor_sync(0xffffffffu, sum, o);
        float mu = sum * (1.f / 64.f);
        float d0 = v0 - mu, d1 = v1 - mu;
        float vs = d0 * d0 + d1 * d1;
#pragma unroll
        for (int o = 16; o; o >>= 1) vs += __shfl_xor_sync(0xffffffffu, vs, o);
        float rstd = rsqrtf(vs * (1.f / 64.f) + 1e-5f);
        size_t ob = ((size_t)(b * NHEAD + h) * SEQ + key) * HD;
        K[ob + lane]      = tf32f(d0 * rstd * ga0 + be0);
        K[ob + lane + 32] = tf32f(d1 * rstd * ga1 + be1);
        Vs[lane * 65 + kl]        = tf32f(vin[lane]);
        Vs[(lane + 32) * 65 + kl] = tf32f(vin[lane + 32]);
    }
    __syncthreads();
    const int d = tid >> 2, c0 = (tid & 3) * 16;
    float* dst = Vt + ((size_t)((b * NHEAD + h) * HD + d)) * SEQ + rb + c0;
#pragma unroll
    for (int e = 0; e < 16; e += 4) {
        const float* s = &Vs[d * 65 + c0 + e];
        *(float4*)(dst + e) = make_float4(s[0], s[1], s[2], s[3]);
    }
}

// --------- flash attention: 128q x 64k, exp2-domain softmax ----------------
#define QIDX(r, col) ((r) * 64 + ((col) ^ (((r) & 7) << 2)))
#define VTIDX(d, key) ((d) * 64 + (((((key) >> 2) ^ ((d) & 7)) << 2) | ((key) & 3)))
#define FKV 8192
#define PWARP 1024
#define FLASH_SMEM ((2*FKV + 8*PWARP)*4)    // 98304 B

#define QSCALE (0.125f * 1.44269504088896340736f)

__global__ __launch_bounds__(256) void flash_tf32(
        const float* __restrict__ Q, const float* __restrict__ K,
        const float* __restrict__ Vt, float* __restrict__ O) {
    extern __shared__ float stage[];

    const int qt = blockIdx.x, h = blockIdx.y, b = blockIdx.z;
    const int tid  = threadIdx.x;
    const int warp = tid >> 5, lane = tid & 31;
    const int g = lane >> 2, c = lane & 3;
    const int wm = warp * 16;

    const int mloc = lane >> 3, rw = lane & 7;
    uint32_t kb_base[4];
#pragma unroll
    for (int gi = 0; gi < 4; gi++) {
        int row = (gi * 2 + (mloc >> 1)) * 8 + rw;
        kb_base[gi] = (uint32_t)(row * 256) + ((((mloc & 1) << 4) ^ (rw << 4)));
    }
    const int Lr = lane & 15, h4 = lane >> 4, mmv = lane & 7;
    uint32_t vrow[4];
#pragma unroll
    for (int gi = 0; gi < 4; gi++) vrow[gi] = (uint32_t)((16 * gi + Lr) * 256);
    const uint32_t vlc = ((uint32_t)h4 << 4) ^ ((uint32_t)mmv << 4);
    float* Pw = stage + 2 * FKV + warp * PWARP;
    const uint32_t pwb = sptr(Pw);
    const uint32_t p_row = (uint32_t)((((lane >> 3) & 1) * 8 + rw) * 256);
    const uint32_t p_hi  = (uint32_t)((lane >> 4) << 4);
    const uint32_t p_rsw = (uint32_t)(rw << 4);

    const float* Qg  = Q  + ((size_t)(b * NHEAD + h) * SEQ + qt * 128) * HD;
    const float* Kg  = K  + (size_t)(b * NHEAD + h) * SEQ * HD;
    const float* Vtg = Vt + (size_t)(b * NHEAD + h) * HD * SEQ;

#pragma unroll
    for (int j = 0; j < 8; j++) {
        int i = tid + j * 256;
        int r = i >> 4, c4 = (i & 15) << 2;
        float* dst = (r < 64) ? &stage[QIDX(r, c4)] : &stage[4096 + QIDX(r - 64, c4)];
        cpa16(sptr(dst), Qg + (size_t)r * 64 + c4);
    }
    cpa_commit();
    asm volatile("cp.async.wait_group 0;");
    __syncthreads();

    unsigned qf[8][4];
    {
        const float* buf = (wm < 64) ? stage : stage + 4096;
        const int rb = wm & 63;
#pragma unroll
        for (int ks = 0; ks < 8; ks++) {
            int kk = ks * 8 + c;
            qf[ks][0] = tf32(QSCALE * buf[QIDX(rb + g, kk)]);
            qf[ks][1] = tf32(QSCALE * buf[QIDX(rb + 8 + g, kk)]);
            qf[ks][2] = tf32(QSCALE * buf[QIDX(rb + g, kk + 4)]);
            qf[ks][3] = tf32(QSCALE * buf[QIDX(rb + 8 + g, kk + 4)]);
        }
    }
    __syncthreads();

    auto issueKV = [&](int t) {
        float* Kb = stage + (t & 1) * FKV;
        float* Vb = Kb + 4096;
#pragma unroll
        for (int j = 0; j < 4; j++) {
            int i = tid + j * 256;
            int r = i >> 4, c4 = (i & 15) << 2;
            cpa16(sptr(&Kb[QIDX(r, c4)]), Kg + (size_t)(t * 64 + r) * 64 + c4);
            cpa16(sptr(&Vb[VTIDX(r, c4)]), Vtg + (size_t)r * SEQ + t * 64 + c4);
        }
    };

    issueKV(0); cpa_commit();
    issueKV(1); cpa_commit();

    float m0 = -1e30f, m1 = -1e30f, l0 = 0.f, l1 = 0.f;
    float o[8][4];
#pragma unroll
    for (int ni = 0; ni < 8; ni++)
#pragma unroll
        for (int t = 0; t < 4; t++) o[ni][t] = 0.f;

    const int nT = SEQ / 64;
    for (int kt = 0; kt < nT; kt++) {
        asm volatile("cp.async.wait_group 1;");
        __syncthreads();

        const uint32_t ksb = sptr(stage + (kt & 1) * FKV);
        const uint32_t vtb = ksb + 4096 * 4;

        float s[8][4];
#pragma unroll
        for (int ni = 0; ni < 8; ni++)
#pragma unroll
            for (int t = 0; t < 4; t++) s[ni][t] = 0.f;
#pragma unroll
        for (int ks = 0; ks < 8; ks++) {
            unsigned kbf[16];
#pragma unroll
            for (int gi = 0; gi < 4; gi++)
                ldsm4(&kbf[gi * 4], ksb + (kb_base[gi] ^ (uint32_t)(ks << 5)));
#pragma unroll
            for (int ni = 0; ni < 8; ni++) mma8(s[ni], qf[ks], &kbf[ni * 2]);
        }

        float rm0 = -1e30f, rm1 = -1e30f;
#pragma unroll
        for (int ni = 0; ni < 8; ni++) {
            rm0 = fmaxf(rm0, fmaxf(s[ni][0], s[ni][1]));
            rm1 = fmaxf(rm1, fmaxf(s[ni][2], s[ni][3]));
        }
        rm0 = fmaxf(rm0, __shfl_xor_sync(0xffffffffu, rm0, 1));
        rm0 = fmaxf(rm0, __shfl_xor_sync(0xffffffffu, rm0, 2));
        rm1 = fmaxf(rm1, __shfl_xor_sync(0xffffffffu, rm1, 1));
        rm1 = fmaxf(rm1, __shfl_xor_sync(0xffffffffu, rm1, 2));
        float mn0 = fmaxf(m0, rm0), mn1 = fmaxf(m1, rm1);

        float ps0 = 0.f, ps1 = 0.f;
#pragma unroll
        for (int ni = 0; ni < 8; ni++) {
            s[ni][0] = ex2(s[ni][0] - mn0); s[ni][1] = ex2(s[ni][1] - mn0);
            s[ni][2] = ex2(s[ni][2] - mn1); s[ni][3] = ex2(s[ni][3] - mn1);
            ps0 += s[ni][0] + s[ni][1];
            ps1 += s[ni][2] + s[ni][3];
        }
        ps0 += __shfl_xor_sync(0xffffffffu, ps0, 1);
        ps0 += __shfl_xor_sync(0xffffffffu, ps0, 2);
        ps1 += __shfl_xor_sync(0xffffffffu, ps1, 1);
        ps1 += __shfl_xor_sync(0xffffffffu, ps1, 2);

        float al0 = ex2(m0 - mn0), al1 = ex2(m1 - mn1);
        m0 = mn0; m1 = mn1;
        l0 = l0 * al0 + ps0;
        l1 = l1 * al1 + ps1;
#pragma unroll
        for (int ni = 0; ni < 8; ni++) {
            o[ni][0] *= al0; o[ni][1] *= al0;
            o[ni][2] *= al1; o[ni][3] *= al1;
        }

        {
            const int sw = g << 2;
#pragma unroll
            for (int ni = 0; ni < 8; ni++) {
                const int colb = ni * 8 + 2 * c;
                *(float2*)&Pw[g * 64 + (colb ^ sw)] =
                    make_float2(tf32f(s[ni][0]), tf32f(s[ni][1]));
                *(float2*)&Pw[(g + 8) * 64 + (colb ^ sw)] =
                    make_float2(tf32f(s[ni][2]), tf32f(s[ni][3]));
            }
        }
        __syncwarp();

#pragma unroll
        for (int ks = 0; ks < 8; ks++) {
            unsigned pa[4];
            ldsm4(pa, pwb + p_row + ((((uint32_t)ks << 5) | p_hi) ^ p_rsw));
            const uint32_t xo = ((uint32_t)ks << 5) ^ vlc;
#pragma unroll
            for (int gi = 0; gi < 4; gi++) {
                unsigned vv[4];
                ldsm4(vv, vtb + vrow[gi] + xo);
                mma8b(o[2 * gi],     pa, vv[0], vv[2]);
                mma8b(o[2 * gi + 1], pa, vv[1], vv[3]);
            }
        }

        __syncthreads();
        if (kt + 2 < nT) issueKV(kt + 2);
        cpa_commit();
    }

    float inv0 = 1.f / l0, inv1 = 1.f / l1;
    int row0 = qt * 128 + wm + g;
#pragma unroll
    for (int ni = 0; ni < 8; ni++) {
        int col = h * HD + ni * 8 + 2 * c;
        float* p0 = O + ((size_t)b * SEQ + row0) * DIM + col;
        float* p1 = O + ((size_t)b * SEQ + row0 + 8) * DIM + col;
        p0[0] = tf32f(o[ni][0] * inv0);
        p0[1] = tf32f(o[ni][1] * inv0);
        p1[0] = tf32f(o[ni][2] * inv1);
        p1[1] = tf32f(o[ni][3] * inv1);
    }
}

// ---------------------------------------------------------------------------
extern "C" void kernel_launch(void* const* d_in, const int* in_sizes, int n_in,
                              void* d_out, int out_size) {
    const float* x        = (const float*)d_in[0];
    const float* context  = (const float*)d_in[1];
    const float* q_w      = (const float*)d_in[2];
    const float* kv_w     = (const float*)d_in[3];
    const float* qn_scale = (const float*)d_in[4];
    const float* qn_bias  = (const float*)d_in[5];
    const float* kn_scale = (const float*)d_in[6];
    const float* kn_bias  = (const float*)d_in[7];
    const float* proj_w   = (const float*)d_in[8];
    const float* proj_b   = (const float*)d_in[9];
    float* out = (float*)d_out;

    float *Qbuf, *KVbuf, *Q, *K, *V, *O, *xc, *cc, *qwt, *kvwt, *pwt;
    cudaGetSymbolAddress((void**)&Qbuf,  g_Qbuf);
    cudaGetSymbolAddress((void**)&KVbuf, g_KVbuf);
    cudaGetSymbolAddress((void**)&Q,     g_Q);
    cudaGetSymbolAddress((void**)&K,     g_K);
    cudaGetSymbolAddress((void**)&V,     g_V);
    cudaGetSymbolAddress((void**)&O,     g_O);
    cudaGetSymbolAddress((void**)&xc,    g_xc);
    cudaGetSymbolAddress((void**)&cc,    g_cc);
    cudaGetSymbolAddress((void**)&qwt,   g_qwt);
    cudaGetSymbolAddress((void**)&kvwt,  g_kvwt);
    cudaGetSymbolAddress((void**)&pwt,   g_pwt);

    cudaFuncSetAttribute(gemm_qkv,
        cudaFuncAttributeMaxDynamicSharedMemorySize, GEMM_SMEM);
    cudaFuncSetAttribute(gemm_tf32,
        cudaFuncAttributeMaxDynamicSharedMemorySize, GEMM_SMEM);
    cudaFuncSetAttribute(flash_tf32,
        cudaFuncAttributeMaxDynamicSharedMemorySize, FLASH_SMEM);

    // L1: prep (round x/context; transpose+round weights)
    prep_kernel<<<dim3(2048, 1, 5), 256>>>(
        (const float4*)x, (const float4*)context, q_w, proj_w, kv_w,
        (float4*)xc, (float4*)cc, qwt, pwt, kvwt);
    // L2: fused q + kv projections
    gemm_qkv<<<dim3(16, 64, 2), 256, GEMM_SMEM>>>(xc, cc, qwt, kvwt, Qbuf, KVbuf);
    // L3: fused LN (q: LN+RoPE, kv: LN k + V^T)
    ln_all_kernel<<<dim3(32, 16, 8), 256>>>(
        Qbuf, KVbuf, qn_scale, qn_bias, kn_scale, kn_bias, Q, K, V);
    // L4: attention (profiled slot)
    flash_tf32<<<dim3(SEQ / 128, NHEAD, BATCH), 256, FLASH_SMEM>>>(Q, K, V, O);
    // L5: out = O @ proj_w + proj_b
    gemm_tf32<<<dim3(8, 64), 256, GEMM_SMEM>>>(O, pwt, proj_b, out, DIM, DIM);
}